// round 1
// baseline (speedup 1.0000x reference)
#include <cuda_runtime.h>
#include <cuda_bf16.h>
#include <math.h>

// Problem constants
#define BATCH 2
#define SEQ 2048
#define DMODEL 1024
#define NHEADS 16
#define DHEAD 64
#define DFF 4096
#define NTOK (BATCH * SEQ)   // 4096

// ---------------------------------------------------------------------------
// Scratch (device globals; allocation is forbidden)
// ---------------------------------------------------------------------------
__device__ float g_h1[NTOK * DMODEL];   // rmsnorm output / reused for h2
__device__ float g_q [NTOK * DMODEL];
__device__ float g_k [NTOK * DMODEL];
__device__ float g_v [NTOK * DMODEL];
__device__ float g_o [NTOK * DMODEL];
__device__ float g_x2[NTOK * DMODEL];
__device__ float g_a [NTOK * DFF];
__device__ float g_c [NTOK * DFF];

// ---------------------------------------------------------------------------
// RMSNorm: one block per token row (1024 elems), 256 threads, float4
// ---------------------------------------------------------------------------
__global__ __launch_bounds__(256) void rmsnorm_kernel(
    const float* __restrict__ x, const float* __restrict__ g,
    float* __restrict__ y)
{
    const int row = blockIdx.x;
    const int tid = threadIdx.x;
    const float* xr = x + (size_t)row * DMODEL;

    float4 v = *(const float4*)(xr + tid * 4);
    float ss = v.x * v.x + v.y * v.y + v.z * v.z + v.w * v.w;

    // warp reduce
    #pragma unroll
    for (int off = 16; off; off >>= 1)
        ss += __shfl_xor_sync(0xffffffffu, ss, off);

    __shared__ float red[8];
    const int lane = tid & 31, warp = tid >> 5;
    if (lane == 0) red[warp] = ss;
    __syncthreads();
    if (warp == 0) {
        float t = (lane < 8) ? red[lane] : 0.0f;
        #pragma unroll
        for (int off = 4; off; off >>= 1)
            t += __shfl_xor_sync(0xffffffffu, t, off);
        if (lane == 0) red[0] = t;
    }
    __syncthreads();

    const float inv = rsqrtf(red[0] * (1.0f / DMODEL) + 1e-5f);
    float4 gv = *(const float4*)(g + tid * 4);
    float4 o;
    o.x = v.x * inv * gv.x;
    o.y = v.y * inv * gv.y;
    o.z = v.z * inv * gv.z;
    o.w = v.w * inv * gv.w;
    *(float4*)(y + (size_t)row * DMODEL + tid * 4) = o;
}

// ---------------------------------------------------------------------------
// SGEMM: C[M,N] = A[M,K] * B[N,K]^T (+ R[M,N] if RES)
// BM=BN=128, BK=16, 256 threads, 8x8 per thread (split 4+4 for float4 smem)
// ---------------------------------------------------------------------------
template <bool RES>
__global__ __launch_bounds__(256) void gemm_kernel(
    const float* __restrict__ A, const float* __restrict__ B,
    const float* __restrict__ R, float* __restrict__ C,
    int M, int N, int K)
{
    __shared__ float As[16][132];
    __shared__ float Bs[16][132];

    const int tid = threadIdx.x;
    const int tx = tid & 15, ty = tid >> 4;
    const int bm = blockIdx.y, bn = blockIdx.x;

    const float* Ab = A + (size_t)bm * 128 * K;
    const float* Bb = B + (size_t)bn * 128 * K;

    float acc[8][8];
    #pragma unroll
    for (int i = 0; i < 8; ++i)
        #pragma unroll
        for (int j = 0; j < 8; ++j) acc[i][j] = 0.0f;

    for (int kt = 0; kt < K; kt += 16) {
        #pragma unroll
        for (int e = 0; e < 2; ++e) {
            int id = e * 256 + tid;          // 0..511 float4 ids
            int row = id >> 2;               // 0..127
            int col = (id & 3) << 2;         // 0,4,8,12
            float4 av = *(const float4*)(Ab + (size_t)row * K + kt + col);
            As[col + 0][row] = av.x;
            As[col + 1][row] = av.y;
            As[col + 2][row] = av.z;
            As[col + 3][row] = av.w;
            float4 bv = *(const float4*)(Bb + (size_t)row * K + kt + col);
            Bs[col + 0][row] = bv.x;
            Bs[col + 1][row] = bv.y;
            Bs[col + 2][row] = bv.z;
            Bs[col + 3][row] = bv.w;
        }
        __syncthreads();

        #pragma unroll
        for (int kk = 0; kk < 16; ++kk) {
            float a[8], b[8];
            *(float4*)(a)     = *(const float4*)&As[kk][ty * 4];
            *(float4*)(a + 4) = *(const float4*)&As[kk][ty * 4 + 64];
            *(float4*)(b)     = *(const float4*)&Bs[kk][tx * 4];
            *(float4*)(b + 4) = *(const float4*)&Bs[kk][tx * 4 + 64];
            #pragma unroll
            for (int i = 0; i < 8; ++i)
                #pragma unroll
                for (int j = 0; j < 8; ++j)
                    acc[i][j] += a[i] * b[j];
        }
        __syncthreads();
    }

    #pragma unroll
    for (int i = 0; i < 8; ++i) {
        int mi = bm * 128 + ((i < 4) ? (ty * 4 + i) : (64 + ty * 4 + i - 4));
        #pragma unroll
        for (int jb = 0; jb < 2; ++jb) {
            int nj = bn * 128 + jb * 64 + tx * 4;
            float4 o;
            o.x = acc[i][jb * 4 + 0];
            o.y = acc[i][jb * 4 + 1];
            o.z = acc[i][jb * 4 + 2];
            o.w = acc[i][jb * 4 + 3];
            if (RES) {
                float4 r = *(const float4*)(R + (size_t)mi * N + nj);
                o.x += r.x; o.y += r.y; o.z += r.z; o.w += r.w;
            }
            *(float4*)(C + (size_t)mi * N + nj) = o;
        }
    }
}

// ---------------------------------------------------------------------------
// Flash attention (fp32, causal). Grid: (S/64, B*H). 256 threads.
// Tiles: 64 queries x 64 keys, dh = 64. Online softmax.
// ---------------------------------------------------------------------------
#define FA_SMEM_FLOATS (4 * 4352 + 128)
#define FA_SMEM_BYTES  (FA_SMEM_FLOATS * 4)

__global__ __launch_bounds__(256) void flash_attn_kernel(
    const float* __restrict__ Q, const float* __restrict__ K,
    const float* __restrict__ V, float* __restrict__ O)
{
    extern __shared__ float sm[];
    float* Qs    = sm;                 // [64 d][68] transposed: Qs[d*68+q]
    float* Ks    = sm + 4352;          // Ks[d*68+k]
    float* Vs    = sm + 2 * 4352;      // Vs[k*68+d]
    float* Ss    = sm + 3 * 4352;      // Ss[q*68+k]
    float* row_f = sm + 4 * 4352;      // [64]
    float* row_l = row_f + 64;         // [64]

    const int tid  = threadIdx.x;
    const int lane = tid & 31, warp = tid >> 5;
    const int ty = tid >> 4, tx = tid & 15;
    const int qb = blockIdx.x;
    const int bh = blockIdx.y;
    const int b = bh >> 4, h = bh & 15;

    const size_t base = ((size_t)b * SEQ) * DMODEL + h * DHEAD;
    const float* Qg = Q + base + (size_t)(qb * 64) * DMODEL;
    const float* Kg = K + base;
    const float* Vg = V + base;

    // load Q tile transposed: Qs[d][q]
    #pragma unroll
    for (int e = 0; e < 4; ++e) {
        int id  = e * 256 + tid;     // 0..1023 float4 ids
        int row = id >> 4;           // 0..63 (query)
        int dc  = (id & 15) << 2;    // 0..60 (dim)
        float4 qv = *(const float4*)(Qg + (size_t)row * DMODEL + dc);
        Qs[(dc + 0) * 68 + row] = qv.x;
        Qs[(dc + 1) * 68 + row] = qv.y;
        Qs[(dc + 2) * 68 + row] = qv.z;
        Qs[(dc + 3) * 68 + row] = qv.w;
    }

    float o_acc[4][4];
    #pragma unroll
    for (int i = 0; i < 4; ++i)
        #pragma unroll
        for (int j = 0; j < 4; ++j) o_acc[i][j] = 0.0f;

    float m_reg[8], l_reg[8];
    #pragma unroll
    for (int r = 0; r < 8; ++r) { m_reg[r] = -INFINITY; l_reg[r] = 0.0f; }

    const int q0 = ty * 4;
    const int k0 = tx * 4;   // also serves as d0 in PV phase

    for (int t = 0; t <= qb; ++t) {
        __syncthreads();  // prior PV done (and Q-load visible at t==0)

        // load K,V tiles
        #pragma unroll
        for (int e = 0; e < 4; ++e) {
            int id  = e * 256 + tid;
            int row = id >> 4;
            int dc  = (id & 15) << 2;
            float4 kv = *(const float4*)(Kg + (size_t)(t * 64 + row) * DMODEL + dc);
            Ks[(dc + 0) * 68 + row] = kv.x;
            Ks[(dc + 1) * 68 + row] = kv.y;
            Ks[(dc + 2) * 68 + row] = kv.z;
            Ks[(dc + 3) * 68 + row] = kv.w;
            float4 vv = *(const float4*)(Vg + (size_t)(t * 64 + row) * DMODEL + dc);
            *(float4*)(Vs + row * 68 + dc) = vv;
        }
        __syncthreads();

        // S = (Q K^T) * scale, with causal mask on the diagonal tile
        float s_acc[4][4];
        #pragma unroll
        for (int i = 0; i < 4; ++i)
            #pragma unroll
            for (int j = 0; j < 4; ++j) s_acc[i][j] = 0.0f;

        #pragma unroll 8
        for (int kk = 0; kk < 64; ++kk) {
            float a[4], bb[4];
            *(float4*)a  = *(const float4*)(Qs + kk * 68 + q0);
            *(float4*)bb = *(const float4*)(Ks + kk * 68 + k0);
            #pragma unroll
            for (int i = 0; i < 4; ++i)
                #pragma unroll
                for (int j = 0; j < 4; ++j)
                    s_acc[i][j] += a[i] * bb[j];
        }

        const bool diag = (t == qb);
        #pragma unroll
        for (int i = 0; i < 4; ++i)
            #pragma unroll
            for (int j = 0; j < 4; ++j) {
                float s = s_acc[i][j] * 0.125f;
                if (diag && (k0 + j > q0 + i)) s = -INFINITY;
                Ss[(q0 + i) * 68 + (k0 + j)] = s;
            }
        __syncthreads();

        // online softmax: warp w handles rows w*8 .. w*8+7
        #pragma unroll
        for (int r = 0; r < 8; ++r) {
            int qr = warp * 8 + r;
            float v0 = Ss[qr * 68 + lane];
            float v1 = Ss[qr * 68 + 32 + lane];
            float mt = fmaxf(v0, v1);
            #pragma unroll
            for (int off = 16; off; off >>= 1)
                mt = fmaxf(mt, __shfl_xor_sync(0xffffffffu, mt, off));
            float mnew = fmaxf(m_reg[r], mt);
            float f  = __expf(m_reg[r] - mnew);
            float p0 = __expf(v0 - mnew);
            float p1 = __expf(v1 - mnew);
            Ss[qr * 68 + lane]      = p0;
            Ss[qr * 68 + 32 + lane] = p1;
            float su = p0 + p1;
            #pragma unroll
            for (int off = 16; off; off >>= 1)
                su += __shfl_xor_sync(0xffffffffu, su, off);
            l_reg[r] = l_reg[r] * f + su;
            m_reg[r] = mnew;
            if (lane == 0) row_f[qr] = f;
        }
        __syncthreads();

        // O = O*f + P @ V
        #pragma unroll
        for (int i = 0; i < 4; ++i) {
            float f = row_f[q0 + i];
            #pragma unroll
            for (int j = 0; j < 4; ++j) o_acc[i][j] *= f;
        }
        #pragma unroll 8
        for (int kk = 0; kk < 64; ++kk) {
            float vv[4];
            *(float4*)vv = *(const float4*)(Vs + kk * 68 + k0);
            #pragma unroll
            for (int i = 0; i < 4; ++i) {
                float p = Ss[(q0 + i) * 68 + kk];
                #pragma unroll
                for (int j = 0; j < 4; ++j)
                    o_acc[i][j] += p * vv[j];
            }
        }
    }

    // finalize: divide by l, write O[b, q, h*64+d]
    if (lane == 0) {
        #pragma unroll
        for (int r = 0; r < 8; ++r) row_l[warp * 8 + r] = l_reg[r];
    }
    __syncthreads();

    float* Og = O + base + (size_t)(qb * 64) * DMODEL;
    #pragma unroll
    for (int i = 0; i < 4; ++i) {
        float inv = 1.0f / row_l[q0 + i];
        float4 o4;
        o4.x = o_acc[i][0] * inv;
        o4.y = o_acc[i][1] * inv;
        o4.z = o_acc[i][2] * inv;
        o4.w = o_acc[i][3] * inv;
        *(float4*)(Og + (size_t)(q0 + i) * DMODEL + k0) = o4;
    }
}

// ---------------------------------------------------------------------------
// SwiGLU combine: a = silu(a) * c   (in place on a)
// ---------------------------------------------------------------------------
__global__ __launch_bounds__(256) void swiglu_kernel(
    float* __restrict__ a, const float* __restrict__ c, int n4)
{
    int idx = blockIdx.x * blockDim.x + threadIdx.x;
    if (idx >= n4) return;
    float4 av = *(const float4*)(a + (size_t)idx * 4);
    float4 cv = *(const float4*)(c + (size_t)idx * 4);
    float4 o;
    o.x = av.x * (1.0f / (1.0f + __expf(-av.x))) * cv.x;
    o.y = av.y * (1.0f / (1.0f + __expf(-av.y))) * cv.y;
    o.z = av.z * (1.0f / (1.0f + __expf(-av.z))) * cv.z;
    o.w = av.w * (1.0f / (1.0f + __expf(-av.w))) * cv.w;
    *(float4*)(a + (size_t)idx * 4) = o;
}

// ---------------------------------------------------------------------------
// Launch
// ---------------------------------------------------------------------------
extern "C" void kernel_launch(void* const* d_in, const int* in_sizes, int n_in,
                              void* d_out, int out_size)
{
    const float* x  = (const float*)d_in[0];
    const float* Wq = (const float*)d_in[1];
    const float* Wk = (const float*)d_in[2];
    const float* Wv = (const float*)d_in[3];
    const float* Wo = (const float*)d_in[4];
    const float* W1 = (const float*)d_in[5];
    const float* W2 = (const float*)d_in[6];
    const float* W3 = (const float*)d_in[7];
    const float* g1 = (const float*)d_in[8];
    const float* g2 = (const float*)d_in[9];
    float* out = (float*)d_out;

    float *h1, *q, *k, *v, *o, *x2, *a, *c;
    cudaGetSymbolAddress((void**)&h1, g_h1);
    cudaGetSymbolAddress((void**)&q,  g_q);
    cudaGetSymbolAddress((void**)&k,  g_k);
    cudaGetSymbolAddress((void**)&v,  g_v);
    cudaGetSymbolAddress((void**)&o,  g_o);
    cudaGetSymbolAddress((void**)&x2, g_x2);
    cudaGetSymbolAddress((void**)&a,  g_a);
    cudaGetSymbolAddress((void**)&c,  g_c);

    cudaFuncSetAttribute(flash_attn_kernel,
                         cudaFuncAttributeMaxDynamicSharedMemorySize,
                         FA_SMEM_BYTES);

    const dim3 gemm_d_d(DMODEL / 128, NTOK / 128);   // N=1024
    const dim3 gemm_ff_d(DFF / 128,   NTOK / 128);   // N=4096

    // 1) h1 = rmsnorm(x, g1)
    rmsnorm_kernel<<<NTOK, 256>>>(x, g1, h1);

    // 2-4) q,k,v = h1 @ W{q,k,v}^T
    gemm_kernel<false><<<gemm_d_d, 256>>>(h1, Wq, nullptr, q, NTOK, DMODEL, DMODEL);
    gemm_kernel<false><<<gemm_d_d, 256>>>(h1, Wk, nullptr, k, NTOK, DMODEL, DMODEL);
    gemm_kernel<false><<<gemm_d_d, 256>>>(h1, Wv, nullptr, v, NTOK, DMODEL, DMODEL);

    // 5) o = causal_attention(q, k, v)
    dim3 fa_grid(SEQ / 64, BATCH * NHEADS);
    flash_attn_kernel<<<fa_grid, 256, FA_SMEM_BYTES>>>(q, k, v, o);

    // 6) x2 = x + o @ Wo^T
    gemm_kernel<true><<<gemm_d_d, 256>>>(o, Wo, x, x2, NTOK, DMODEL, DMODEL);

    // 7) h2 = rmsnorm(x2, g2)   (reuse h1)
    rmsnorm_kernel<<<NTOK, 256>>>(x2, g2, h1);

    // 8-9) a = h2 @ W1^T, c = h2 @ W3^T
    gemm_kernel<false><<<gemm_ff_d, 256>>>(h1, W1, nullptr, a, NTOK, DFF, DMODEL);
    gemm_kernel<false><<<gemm_ff_d, 256>>>(h1, W3, nullptr, c, NTOK, DFF, DMODEL);

    // 10) a = silu(a) * c
    int n4 = NTOK * DFF / 4;
    swiglu_kernel<<<n4 / 256, 256>>>(a, c, n4);

    // 11) out = x2 + a @ W2^T
    gemm_kernel<true><<<gemm_d_d, 256>>>(a, W2, x2, out, NTOK, DMODEL, DFF);
}

// round 3
// speedup vs baseline: 2.0350x; 2.0350x over previous
#include <cuda_runtime.h>
#include <cuda_bf16.h>
#include <stdint.h>
#include <math.h>

// Problem constants
#define BATCH 2
#define SEQ 2048
#define DMODEL 1024
#define NHEADS 16
#define DHEAD 64
#define DFF 4096
#define NTOK (BATCH * SEQ)   // 4096

// ---------------------------------------------------------------------------
// Scratch (device globals; allocation is forbidden)
// ---------------------------------------------------------------------------
__device__ float g_h1[NTOK * DMODEL];
__device__ float g_q [NTOK * DMODEL];
__device__ float g_k [NTOK * DMODEL];
__device__ float g_v [NTOK * DMODEL];
__device__ float g_o [NTOK * DMODEL];
__device__ float g_x2[NTOK * DMODEL];
__device__ float g_a [NTOK * DFF];
__device__ float g_c [NTOK * DFF];

// ---------------------------------------------------------------------------
// Helpers
// ---------------------------------------------------------------------------
__device__ __forceinline__ unsigned int f2tf32(float f) {
    unsigned int r;
    asm("cvt.rna.tf32.f32 %0, %1;" : "=r"(r) : "f"(f));
    return r;
}

__device__ __forceinline__ void mma_tf32(float* c, const unsigned int* a, const unsigned int* b) {
    asm volatile(
        "mma.sync.aligned.m16n8k8.row.col.f32.tf32.tf32.f32 "
        "{%0,%1,%2,%3}, {%4,%5,%6,%7}, {%8,%9}, {%0,%1,%2,%3};"
        : "+f"(c[0]), "+f"(c[1]), "+f"(c[2]), "+f"(c[3])
        : "r"(a[0]), "r"(a[1]), "r"(a[2]), "r"(a[3]), "r"(b[0]), "r"(b[1]));
}

// ---------------------------------------------------------------------------
// RMSNorm: one block per token row (1024 elems), 256 threads, float4
// ---------------------------------------------------------------------------
__global__ __launch_bounds__(256) void rmsnorm_kernel(
    const float* __restrict__ x, const float* __restrict__ g,
    float* __restrict__ y)
{
    const int row = blockIdx.x;
    const int tid = threadIdx.x;
    const float* xr = x + (size_t)row * DMODEL;

    float4 v = *(const float4*)(xr + tid * 4);
    float ss = v.x * v.x + v.y * v.y + v.z * v.z + v.w * v.w;

    #pragma unroll
    for (int off = 16; off; off >>= 1)
        ss += __shfl_xor_sync(0xffffffffu, ss, off);

    __shared__ float red[8];
    const int lane = tid & 31, warp = tid >> 5;
    if (lane == 0) red[warp] = ss;
    __syncthreads();
    if (warp == 0) {
        float t = (lane < 8) ? red[lane] : 0.0f;
        #pragma unroll
        for (int off = 4; off; off >>= 1)
            t += __shfl_xor_sync(0xffffffffu, t, off);
        if (lane == 0) red[0] = t;
    }
    __syncthreads();

    const float inv = rsqrtf(red[0] * (1.0f / DMODEL) + 1e-5f);
    float4 gv = *(const float4*)(g + tid * 4);
    float4 o;
    o.x = v.x * inv * gv.x;
    o.y = v.y * inv * gv.y;
    o.z = v.z * inv * gv.z;
    o.w = v.w * inv * gv.w;
    *(float4*)(y + (size_t)row * DMODEL + tid * 4) = o;
}

// ---------------------------------------------------------------------------
// TF32 tensor-core GEMM: C[M,N] = A[M,K] * B[N,K]^T (+ R[M,N] if RES)
// BM=BN=128, BK=32, 256 threads (8 warps as 2x4), warp tile 64x32,
// mma.sync m16n8k8 tf32, cp.async double-buffered smem (pad-4 rows).
// ---------------------------------------------------------------------------
#define GT_LDS 36                    // padded row stride (floats)
#define GT_BUF (128 * GT_LDS)        // floats per tile buffer
#define GT_SMEM_BYTES (4 * GT_BUF * 4)  // As[2] + Bs[2]

template <bool RES>
__global__ __launch_bounds__(256) void gemm_tf32(
    const float* __restrict__ A, const float* __restrict__ B,
    const float* __restrict__ R, float* __restrict__ C,
    int M, int N, int K)
{
    extern __shared__ float sm[];
    float* As = sm;                 // [2][128][36]
    float* Bs = sm + 2 * GT_BUF;    // [2][128][36]

    const int tid  = threadIdx.x;
    const int lane = tid & 31, warp = tid >> 5;
    const int g = lane >> 2, t4 = lane & 3;
    const int wm = warp >> 2, wn = warp & 3;
    const int bm = blockIdx.y, bn = blockIdx.x;

    const float* Ab = A + (size_t)bm * 128 * K;
    const float* Bb = B + (size_t)bn * 128 * K;

    float acc[4][4][4];
    #pragma unroll
    for (int i = 0; i < 4; ++i)
        #pragma unroll
        for (int j = 0; j < 4; ++j)
            #pragma unroll
            for (int r = 0; r < 4; ++r) acc[i][j][r] = 0.0f;

    const int T = K >> 5;   // number of BK=32 tiles

    // issue cp.async loads for tile kt into buffer buf
    auto load_tile = [&](int kt, int buf) {
        #pragma unroll
        for (int i = 0; i < 4; ++i) {
            int id  = i * 256 + tid;     // 0..1023
            int row = id >> 3;           // 0..127
            int col = (id & 7) << 2;     // 0,4,...,28
            const float* ga = Ab + (size_t)row * K + kt * 32 + col;
            unsigned int sa = (unsigned int)__cvta_generic_to_shared(
                As + buf * GT_BUF + row * GT_LDS + col);
            asm volatile("cp.async.cg.shared.global [%0], [%1], 16;\n"
                         :: "r"(sa), "l"(ga));
            const float* gb = Bb + (size_t)row * K + kt * 32 + col;
            unsigned int sb = (unsigned int)__cvta_generic_to_shared(
                Bs + buf * GT_BUF + row * GT_LDS + col);
            asm volatile("cp.async.cg.shared.global [%0], [%1], 16;\n"
                         :: "r"(sb), "l"(gb));
        }
        asm volatile("cp.async.commit_group;\n");
    };

    load_tile(0, 0);

    for (int kt = 0; kt < T; ++kt) {
        const int buf = kt & 1;
        if (kt + 1 < T) {
            load_tile(kt + 1, buf ^ 1);
            asm volatile("cp.async.wait_group 1;\n");
        } else {
            asm volatile("cp.async.wait_group 0;\n");
        }
        __syncthreads();

        const float* Asb = As + buf * GT_BUF;
        const float* Bsb = Bs + buf * GT_BUF;

        #pragma unroll
        for (int ks = 0; ks < 4; ++ks) {
            const int k0 = ks * 8;
            unsigned int af[4][4], bf[4][2];
            #pragma unroll
            for (int i = 0; i < 4; ++i) {
                int r = wm * 64 + i * 16 + g;
                af[i][0] = f2tf32(Asb[r * GT_LDS + k0 + t4]);
                af[i][1] = f2tf32(Asb[(r + 8) * GT_LDS + k0 + t4]);
                af[i][2] = f2tf32(Asb[r * GT_LDS + k0 + t4 + 4]);
                af[i][3] = f2tf32(Asb[(r + 8) * GT_LDS + k0 + t4 + 4]);
            }
            #pragma unroll
            for (int j = 0; j < 4; ++j) {
                int n = wn * 32 + j * 8 + g;
                bf[j][0] = f2tf32(Bsb[n * GT_LDS + k0 + t4]);
                bf[j][1] = f2tf32(Bsb[n * GT_LDS + k0 + t4 + 4]);
            }
            #pragma unroll
            for (int i = 0; i < 4; ++i)
                #pragma unroll
                for (int j = 0; j < 4; ++j)
                    mma_tf32(acc[i][j], af[i], bf[j]);
        }
        __syncthreads();
    }

    // epilogue: each mma frag -> rows (r0, r0+8), cols (c0, c0+1)
    #pragma unroll
    for (int i = 0; i < 4; ++i) {
        const int r0 = bm * 128 + wm * 64 + i * 16 + g;
        #pragma unroll
        for (int j = 0; j < 4; ++j) {
            const int c0 = bn * 128 + wn * 32 + j * 8 + 2 * t4;
            float2 v0 = make_float2(acc[i][j][0], acc[i][j][1]);
            float2 v1 = make_float2(acc[i][j][2], acc[i][j][3]);
            if (RES) {
                float2 rr0 = *(const float2*)(R + (size_t)r0 * N + c0);
                float2 rr1 = *(const float2*)(R + (size_t)(r0 + 8) * N + c0);
                v0.x += rr0.x; v0.y += rr0.y;
                v1.x += rr1.x; v1.y += rr1.y;
            }
            *(float2*)(C + (size_t)r0 * N + c0)       = v0;
            *(float2*)(C + (size_t)(r0 + 8) * N + c0) = v1;
        }
    }
}

// ---------------------------------------------------------------------------
// Flash attention (fp32, causal). Grid: (S/64, B*H). 256 threads.
// ---------------------------------------------------------------------------
#define FA_SMEM_FLOATS (4 * 4352 + 128)
#define FA_SMEM_BYTES  (FA_SMEM_FLOATS * 4)

__global__ __launch_bounds__(256) void flash_attn_kernel(
    const float* __restrict__ Q, const float* __restrict__ K,
    const float* __restrict__ V, float* __restrict__ O)
{
    extern __shared__ float sm[];
    float* Qs    = sm;                 // Qs[d*68+q]
    float* Ks    = sm + 4352;          // Ks[d*68+k]
    float* Vs    = sm + 2 * 4352;      // Vs[k*68+d]
    float* Ss    = sm + 3 * 4352;      // Ss[q*68+k]
    float* row_f = sm + 4 * 4352;
    float* row_l = row_f + 64;

    const int tid  = threadIdx.x;
    const int lane = tid & 31, warp = tid >> 5;
    const int ty = tid >> 4, tx = tid & 15;
    const int qb = blockIdx.x;
    const int bh = blockIdx.y;
    const int b = bh >> 4, h = bh & 15;

    const size_t base = ((size_t)b * SEQ) * DMODEL + h * DHEAD;
    const float* Qg = Q + base + (size_t)(qb * 64) * DMODEL;
    const float* Kg = K + base;
    const float* Vg = V + base;

    #pragma unroll
    for (int e = 0; e < 4; ++e) {
        int id  = e * 256 + tid;
        int row = id >> 4;
        int dc  = (id & 15) << 2;
        float4 qv = *(const float4*)(Qg + (size_t)row * DMODEL + dc);
        Qs[(dc + 0) * 68 + row] = qv.x;
        Qs[(dc + 1) * 68 + row] = qv.y;
        Qs[(dc + 2) * 68 + row] = qv.z;
        Qs[(dc + 3) * 68 + row] = qv.w;
    }

    float o_acc[4][4];
    #pragma unroll
    for (int i = 0; i < 4; ++i)
        #pragma unroll
        for (int j = 0; j < 4; ++j) o_acc[i][j] = 0.0f;

    float m_reg[8], l_reg[8];
    #pragma unroll
    for (int r = 0; r < 8; ++r) { m_reg[r] = -INFINITY; l_reg[r] = 0.0f; }

    const int q0 = ty * 4;
    const int k0 = tx * 4;

    for (int t = 0; t <= qb; ++t) {
        __syncthreads();

        #pragma unroll
        for (int e = 0; e < 4; ++e) {
            int id  = e * 256 + tid;
            int row = id >> 4;
            int dc  = (id & 15) << 2;
            float4 kv = *(const float4*)(Kg + (size_t)(t * 64 + row) * DMODEL + dc);
            Ks[(dc + 0) * 68 + row] = kv.x;
            Ks[(dc + 1) * 68 + row] = kv.y;
            Ks[(dc + 2) * 68 + row] = kv.z;
            Ks[(dc + 3) * 68 + row] = kv.w;
            float4 vv = *(const float4*)(Vg + (size_t)(t * 64 + row) * DMODEL + dc);
            *(float4*)(Vs + row * 68 + dc) = vv;
        }
        __syncthreads();

        float s_acc[4][4];
        #pragma unroll
        for (int i = 0; i < 4; ++i)
            #pragma unroll
            for (int j = 0; j < 4; ++j) s_acc[i][j] = 0.0f;

        #pragma unroll 8
        for (int kk = 0; kk < 64; ++kk) {
            float a[4], bb[4];
            *(float4*)a  = *(const float4*)(Qs + kk * 68 + q0);
            *(float4*)bb = *(const float4*)(Ks + kk * 68 + k0);
            #pragma unroll
            for (int i = 0; i < 4; ++i)
                #pragma unroll
                for (int j = 0; j < 4; ++j)
                    s_acc[i][j] += a[i] * bb[j];
        }

        const bool diag = (t == qb);
        #pragma unroll
        for (int i = 0; i < 4; ++i)
            #pragma unroll
            for (int j = 0; j < 4; ++j) {
                float s = s_acc[i][j] * 0.125f;
                if (diag && (k0 + j > q0 + i)) s = -INFINITY;
                Ss[(q0 + i) * 68 + (k0 + j)] = s;
            }
        __syncthreads();

        #pragma unroll
        for (int r = 0; r < 8; ++r) {
            int qr = warp * 8 + r;
            float v0 = Ss[qr * 68 + lane];
            float v1 = Ss[qr * 68 + 32 + lane];
            float mt = fmaxf(v0, v1);
            #pragma unroll
            for (int off = 16; off; off >>= 1)
                mt = fmaxf(mt, __shfl_xor_sync(0xffffffffu, mt, off));
            float mnew = fmaxf(m_reg[r], mt);
            float f  = __expf(m_reg[r] - mnew);
            float p0 = __expf(v0 - mnew);
            float p1 = __expf(v1 - mnew);
            Ss[qr * 68 + lane]      = p0;
            Ss[qr * 68 + 32 + lane] = p1;
            float su = p0 + p1;
            #pragma unroll
            for (int off = 16; off; off >>= 1)
                su += __shfl_xor_sync(0xffffffffu, su, off);
            l_reg[r] = l_reg[r] * f + su;
            m_reg[r] = mnew;
            if (lane == 0) row_f[qr] = f;
        }
        __syncthreads();

        #pragma unroll
        for (int i = 0; i < 4; ++i) {
            float f = row_f[q0 + i];
            #pragma unroll
            for (int j = 0; j < 4; ++j) o_acc[i][j] *= f;
        }
        #pragma unroll 8
        for (int kk = 0; kk < 64; ++kk) {
            float vv[4];
            *(float4*)vv = *(const float4*)(Vs + kk * 68 + k0);
            #pragma unroll
            for (int i = 0; i < 4; ++i) {
                float p = Ss[(q0 + i) * 68 + kk];
                #pragma unroll
                for (int j = 0; j < 4; ++j)
                    o_acc[i][j] += p * vv[j];
            }
        }
    }

    if (lane == 0) {
        #pragma unroll
        for (int r = 0; r < 8; ++r) row_l[warp * 8 + r] = l_reg[r];
    }
    __syncthreads();

    float* Og = O + base + (size_t)(qb * 64) * DMODEL;
    #pragma unroll
    for (int i = 0; i < 4; ++i) {
        float inv = 1.0f / row_l[q0 + i];
        float4 o4;
        o4.x = o_acc[i][0] * inv;
        o4.y = o_acc[i][1] * inv;
        o4.z = o_acc[i][2] * inv;
        o4.w = o_acc[i][3] * inv;
        *(float4*)(Og + (size_t)(q0 + i) * DMODEL + k0) = o4;
    }
}

// ---------------------------------------------------------------------------
// SwiGLU combine: a = silu(a) * c
// ---------------------------------------------------------------------------
__global__ __launch_bounds__(256) void swiglu_kernel(
    float* __restrict__ a, const float* __restrict__ c, int n4)
{
    int idx = blockIdx.x * blockDim.x + threadIdx.x;
    if (idx >= n4) return;
    float4 av = *(const float4*)(a + (size_t)idx * 4);
    float4 cv = *(const float4*)(c + (size_t)idx * 4);
    float4 o;
    o.x = av.x * (1.0f / (1.0f + __expf(-av.x))) * cv.x;
    o.y = av.y * (1.0f / (1.0f + __expf(-av.y))) * cv.y;
    o.z = av.z * (1.0f / (1.0f + __expf(-av.z))) * cv.z;
    o.w = av.w * (1.0f / (1.0f + __expf(-av.w))) * cv.w;
    *(float4*)(a + (size_t)idx * 4) = o;
}

// ---------------------------------------------------------------------------
// Launch
// ---------------------------------------------------------------------------
extern "C" void kernel_launch(void* const* d_in, const int* in_sizes, int n_in,
                              void* d_out, int out_size)
{
    const float* x  = (const float*)d_in[0];
    const float* Wq = (const float*)d_in[1];
    const float* Wk = (const float*)d_in[2];
    const float* Wv = (const float*)d_in[3];
    const float* Wo = (const float*)d_in[4];
    const float* W1 = (const float*)d_in[5];
    const float* W2 = (const float*)d_in[6];
    const float* W3 = (const float*)d_in[7];
    const float* g1 = (const float*)d_in[8];
    const float* g2 = (const float*)d_in[9];
    float* out = (float*)d_out;

    float *h1, *q, *k, *v, *o, *x2, *a, *c;
    cudaGetSymbolAddress((void**)&h1, g_h1);
    cudaGetSymbolAddress((void**)&q,  g_q);
    cudaGetSymbolAddress((void**)&k,  g_k);
    cudaGetSymbolAddress((void**)&v,  g_v);
    cudaGetSymbolAddress((void**)&o,  g_o);
    cudaGetSymbolAddress((void**)&x2, g_x2);
    cudaGetSymbolAddress((void**)&a,  g_a);
    cudaGetSymbolAddress((void**)&c,  g_c);

    cudaFuncSetAttribute(flash_attn_kernel,
                         cudaFuncAttributeMaxDynamicSharedMemorySize,
                         FA_SMEM_BYTES);
    cudaFuncSetAttribute(gemm_tf32<false>,
                         cudaFuncAttributeMaxDynamicSharedMemorySize,
                         GT_SMEM_BYTES);
    cudaFuncSetAttribute(gemm_tf32<true>,
                         cudaFuncAttributeMaxDynamicSharedMemorySize,
                         GT_SMEM_BYTES);

    const dim3 gemm_d_d(DMODEL / 128, NTOK / 128);   // N=1024
    const dim3 gemm_ff_d(DFF / 128,   NTOK / 128);   // N=4096

    // 1) h1 = rmsnorm(x, g1)
    rmsnorm_kernel<<<NTOK, 256>>>(x, g1, h1);

    // 2-4) q,k,v = h1 @ W{q,k,v}^T
    gemm_tf32<false><<<gemm_d_d, 256, GT_SMEM_BYTES>>>(h1, Wq, nullptr, q, NTOK, DMODEL, DMODEL);
    gemm_tf32<false><<<gemm_d_d, 256, GT_SMEM_BYTES>>>(h1, Wk, nullptr, k, NTOK, DMODEL, DMODEL);
    gemm_tf32<false><<<gemm_d_d, 256, GT_SMEM_BYTES>>>(h1, Wv, nullptr, v, NTOK, DMODEL, DMODEL);

    // 5) o = causal_attention(q, k, v)
    dim3 fa_grid(SEQ / 64, BATCH * NHEADS);
    flash_attn_kernel<<<fa_grid, 256, FA_SMEM_BYTES>>>(q, k, v, o);

    // 6) x2 = x + o @ Wo^T
    gemm_tf32<true><<<gemm_d_d, 256, GT_SMEM_BYTES>>>(o, Wo, x, x2, NTOK, DMODEL, DMODEL);

    // 7) h2 = rmsnorm(x2, g2)
    rmsnorm_kernel<<<NTOK, 256>>>(x2, g2, h1);

    // 8-9) a = h2 @ W1^T, c = h2 @ W3^T
    gemm_tf32<false><<<gemm_ff_d, 256, GT_SMEM_BYTES>>>(h1, W1, nullptr, a, NTOK, DFF, DMODEL);
    gemm_tf32<false><<<gemm_ff_d, 256, GT_SMEM_BYTES>>>(h1, W3, nullptr, c, NTOK, DFF, DMODEL);

    // 10) a = silu(a) * c
    int n4 = NTOK * DFF / 4;
    swiglu_kernel<<<n4 / 256, 256>>>(a, c, n4);

    // 11) out = x2 + a @ W2^T
    gemm_tf32<true><<<gemm_d_d, 256, GT_SMEM_BYTES>>>(a, W2, x2, out, NTOK, DMODEL, DFF);
}

// round 4
// speedup vs baseline: 2.9474x; 1.4484x over previous
#include <cuda_runtime.h>
#include <cuda_bf16.h>
#include <stdint.h>
#include <math.h>

// Problem constants
#define BATCH 2
#define SEQ 2048
#define DMODEL 1024
#define NHEADS 16
#define DHEAD 64
#define DFF 4096
#define NTOK (BATCH * SEQ)   // 4096

// ---------------------------------------------------------------------------
// Scratch (device globals; allocation is forbidden)
// ---------------------------------------------------------------------------
__device__ float g_h1[NTOK * DMODEL];
__device__ float g_q [NTOK * DMODEL];
__device__ float g_k [NTOK * DMODEL];
__device__ float g_v [NTOK * DMODEL];
__device__ float g_o [NTOK * DMODEL];
__device__ float g_x2[NTOK * DMODEL];
__device__ float g_a [NTOK * DFF];
__device__ float g_c [NTOK * DFF];
// tf32-rounded weights
__device__ float g_wq[DMODEL * DMODEL];
__device__ float g_wk[DMODEL * DMODEL];
__device__ float g_wv[DMODEL * DMODEL];
__device__ float g_wo[DMODEL * DMODEL];
__device__ float g_w1[DFF * DMODEL];
__device__ float g_w2[DMODEL * DFF];
__device__ float g_w3[DFF * DMODEL];

// ---------------------------------------------------------------------------
// Helpers
// ---------------------------------------------------------------------------
__device__ __forceinline__ float rndtf(float f) {   // round-to-nearest tf32, as float
    unsigned int r;
    asm("cvt.rna.tf32.f32 %0, %1;" : "=r"(r) : "f"(f));
    return __uint_as_float(r);
}

__device__ __forceinline__ void mma_tf32(float* c, const unsigned int* a, const unsigned int* b) {
    asm volatile(
        "mma.sync.aligned.m16n8k8.row.col.f32.tf32.tf32.f32 "
        "{%0,%1,%2,%3}, {%4,%5,%6,%7}, {%8,%9}, {%0,%1,%2,%3};"
        : "+f"(c[0]), "+f"(c[1]), "+f"(c[2]), "+f"(c[3])
        : "r"(a[0]), "r"(a[1]), "r"(a[2]), "r"(a[3]), "r"(b[0]), "r"(b[1]));
}

__device__ __forceinline__ void ldsm4(unsigned int* r, const float* p) {
    unsigned int addr = (unsigned int)__cvta_generic_to_shared(p);
    asm volatile("ldmatrix.sync.aligned.m8n8.x4.shared.b16 {%0,%1,%2,%3}, [%4];"
                 : "=r"(r[0]), "=r"(r[1]), "=r"(r[2]), "=r"(r[3]) : "r"(addr));
}
__device__ __forceinline__ void ldsm2(unsigned int* r, const float* p) {
    unsigned int addr = (unsigned int)__cvta_generic_to_shared(p);
    asm volatile("ldmatrix.sync.aligned.m8n8.x2.shared.b16 {%0,%1}, [%2];"
                 : "=r"(r[0]), "=r"(r[1]) : "r"(addr));
}

// ---------------------------------------------------------------------------
// Weight rounding: out[i] = tf32_rna(in[i])
// ---------------------------------------------------------------------------
__global__ __launch_bounds__(256) void round_kernel(
    const float* __restrict__ in, float* __restrict__ out, int n4)
{
    int idx = blockIdx.x * blockDim.x + threadIdx.x;
    if (idx >= n4) return;
    float4 v = *(const float4*)(in + (size_t)idx * 4);
    v.x = rndtf(v.x); v.y = rndtf(v.y); v.z = rndtf(v.z); v.w = rndtf(v.w);
    *(float4*)(out + (size_t)idx * 4) = v;
}

// ---------------------------------------------------------------------------
// RMSNorm (output rounded to tf32 — it only feeds GEMM A operands)
// ---------------------------------------------------------------------------
__global__ __launch_bounds__(256) void rmsnorm_kernel(
    const float* __restrict__ x, const float* __restrict__ g,
    float* __restrict__ y)
{
    const int row = blockIdx.x;
    const int tid = threadIdx.x;
    const float* xr = x + (size_t)row * DMODEL;

    float4 v = *(const float4*)(xr + tid * 4);
    float ss = v.x * v.x + v.y * v.y + v.z * v.z + v.w * v.w;

    #pragma unroll
    for (int off = 16; off; off >>= 1)
        ss += __shfl_xor_sync(0xffffffffu, ss, off);

    __shared__ float red[8];
    const int lane = tid & 31, warp = tid >> 5;
    if (lane == 0) red[warp] = ss;
    __syncthreads();
    if (warp == 0) {
        float t = (lane < 8) ? red[lane] : 0.0f;
        #pragma unroll
        for (int off = 4; off; off >>= 1)
            t += __shfl_xor_sync(0xffffffffu, t, off);
        if (lane == 0) red[0] = t;
    }
    __syncthreads();

    const float inv = rsqrtf(red[0] * (1.0f / DMODEL) + 1e-5f);
    float4 gv = *(const float4*)(g + tid * 4);
    float4 o;
    o.x = rndtf(v.x * inv * gv.x);
    o.y = rndtf(v.y * inv * gv.y);
    o.z = rndtf(v.z * inv * gv.z);
    o.w = rndtf(v.w * inv * gv.w);
    *(float4*)(y + (size_t)row * DMODEL + tid * 4) = o;
}

// ---------------------------------------------------------------------------
// TF32 tensor-core GEMM: C[M,N] = A[M,K] * B[N,K]^T (+ R[M,N] if RES)
// BM=BN=128, BK=32, 256 threads (8 warps 2x4), warp tile 64x32,
// ldmatrix fragment loads, cp.async double-buffered. blockIdx.z picks (B,C).
// ---------------------------------------------------------------------------
#define GT_LDS 36
#define GT_BUF (128 * GT_LDS)
#define GT_SMEM_BYTES (4 * GT_BUF * 4)

template <bool RES, bool ROUND>
__global__ __launch_bounds__(256) void gemm_tf32(
    const float* __restrict__ A,
    const float* __restrict__ B0, const float* __restrict__ B1, const float* __restrict__ B2,
    const float* __restrict__ R,
    float* __restrict__ C0, float* __restrict__ C1, float* __restrict__ C2,
    int M, int N, int K)
{
    extern __shared__ float sm[];
    float* As = sm;
    float* Bs = sm + 2 * GT_BUF;

    const int z = blockIdx.z;
    const float* B = (z == 0) ? B0 : (z == 1) ? B1 : B2;
    float*       C = (z == 0) ? C0 : (z == 1) ? C1 : C2;

    const int tid  = threadIdx.x;
    const int lane = tid & 31, warp = tid >> 5;
    const int g = lane >> 2, t4 = lane & 3;
    const int wm = warp >> 2, wn = warp & 3;
    const int bm = blockIdx.y, bn = blockIdx.x;

    const int lr = lane & 15;            // A ldsm row
    const int lc = (lane >> 4) << 2;     // A ldsm col offset (0/4)
    const int br = lane & 7;             // B ldsm row
    const int bc = ((lane >> 3) & 1) << 2;

    const float* Ab = A + (size_t)bm * 128 * K;
    const float* Bb = B + (size_t)bn * 128 * K;

    float acc[4][4][4];
    #pragma unroll
    for (int i = 0; i < 4; ++i)
        #pragma unroll
        for (int j = 0; j < 4; ++j)
            #pragma unroll
            for (int r = 0; r < 4; ++r) acc[i][j][r] = 0.0f;

    const int T = K >> 5;

    auto load_tile = [&](int kt, int buf) {
        #pragma unroll
        for (int i = 0; i < 4; ++i) {
            int id  = i * 256 + tid;
            int row = id >> 3;
            int col = (id & 7) << 2;
            const float* ga = Ab + (size_t)row * K + kt * 32 + col;
            unsigned int sa = (unsigned int)__cvta_generic_to_shared(
                As + buf * GT_BUF + row * GT_LDS + col);
            asm volatile("cp.async.cg.shared.global [%0], [%1], 16;\n"
                         :: "r"(sa), "l"(ga));
            const float* gb = Bb + (size_t)row * K + kt * 32 + col;
            unsigned int sb = (unsigned int)__cvta_generic_to_shared(
                Bs + buf * GT_BUF + row * GT_LDS + col);
            asm volatile("cp.async.cg.shared.global [%0], [%1], 16;\n"
                         :: "r"(sb), "l"(gb));
        }
        asm volatile("cp.async.commit_group;\n");
    };

    load_tile(0, 0);

    for (int kt = 0; kt < T; ++kt) {
        const int buf = kt & 1;
        if (kt + 1 < T) {
            load_tile(kt + 1, buf ^ 1);
            asm volatile("cp.async.wait_group 1;\n");
        } else {
            asm volatile("cp.async.wait_group 0;\n");
        }
        __syncthreads();

        const float* Asb = As + buf * GT_BUF;
        const float* Bsb = Bs + buf * GT_BUF;

        #pragma unroll
        for (int ks = 0; ks < 4; ++ks) {
            const int k0 = ks * 8;
            unsigned int af[4][4], bf[4][2];
            const float* abase = Asb + (wm * 64 + lr) * GT_LDS + k0 + lc;
            #pragma unroll
            for (int i = 0; i < 4; ++i)
                ldsm4(af[i], abase + i * 16 * GT_LDS);
            const float* bbase = Bsb + (wn * 32 + br) * GT_LDS + k0 + bc;
            #pragma unroll
            for (int j = 0; j < 4; ++j)
                ldsm2(bf[j], bbase + j * 8 * GT_LDS);
            #pragma unroll
            for (int i = 0; i < 4; ++i)
                #pragma unroll
                for (int j = 0; j < 4; ++j)
                    mma_tf32(acc[i][j], af[i], bf[j]);
        }
        __syncthreads();
    }

    #pragma unroll
    for (int i = 0; i < 4; ++i) {
        const int r0 = bm * 128 + wm * 64 + i * 16 + g;
        #pragma unroll
        for (int j = 0; j < 4; ++j) {
            const int c0 = bn * 128 + wn * 32 + j * 8 + 2 * t4;
            float2 v0 = make_float2(acc[i][j][0], acc[i][j][1]);
            float2 v1 = make_float2(acc[i][j][2], acc[i][j][3]);
            if (RES) {
                float2 rr0 = *(const float2*)(R + (size_t)r0 * N + c0);
                float2 rr1 = *(const float2*)(R + (size_t)(r0 + 8) * N + c0);
                v0.x += rr0.x; v0.y += rr0.y;
                v1.x += rr1.x; v1.y += rr1.y;
            }
            if (ROUND) {
                v0.x = rndtf(v0.x); v0.y = rndtf(v0.y);
                v1.x = rndtf(v1.x); v1.y = rndtf(v1.y);
            }
            *(float2*)(C + (size_t)r0 * N + c0)       = v0;
            *(float2*)(C + (size_t)(r0 + 8) * N + c0) = v1;
        }
    }
}

// ---------------------------------------------------------------------------
// Flash attention (tf32 mma, causal). Grid: (S/64, B*H). 256 threads (8 warps).
// Tile 64q x 64k, dh=64. Qs[q][d], Ks[k][d], Vs[d][k], Ss[q][k], stride 68.
// ---------------------------------------------------------------------------
#define FA_STRIDE 68
#define FA_SMEM_FLOATS (4 * 4352 + 128)
#define FA_SMEM_BYTES  (FA_SMEM_FLOATS * 4)

__global__ __launch_bounds__(256) void flash_attn_kernel(
    const float* __restrict__ Q, const float* __restrict__ K,
    const float* __restrict__ V, float* __restrict__ O)
{
    extern __shared__ float sm[];
    float* Qs    = sm;
    float* Ks    = sm + 4352;
    float* Vs    = sm + 2 * 4352;
    float* Ss    = sm + 3 * 4352;
    float* row_f = sm + 4 * 4352;
    float* row_l = row_f + 64;

    const int tid  = threadIdx.x;
    const int lane = tid & 31, warp = tid >> 5;
    const int g = lane >> 2, t4 = lane & 3;
    const int wm = warp >> 2, wn = warp & 3;   // 2 x 4 warps; warp tile 32q x 16n
    const int lr = lane & 15;
    const int lc = (lane >> 4) << 2;
    const int br = lane & 7;
    const int bc = ((lane >> 3) & 1) << 2;

    const int qb = blockIdx.x;
    const int bh = blockIdx.y;
    const int b = bh >> 4, h = bh & 15;

    const size_t base = ((size_t)b * SEQ) * DMODEL + h * DHEAD;
    const float* Qg = Q + base + (size_t)(qb * 64) * DMODEL;
    const float* Kg = K + base;
    const float* Vg = V + base;

    // load Q tile [q][d] (direct, vectorized)
    #pragma unroll
    for (int e = 0; e < 4; ++e) {
        int id  = e * 256 + tid;
        int row = id >> 4;
        int dc  = (id & 15) << 2;
        float4 qv = *(const float4*)(Qg + (size_t)row * DMODEL + dc);
        *(float4*)(Qs + row * FA_STRIDE + dc) = qv;
    }

    float o_acc[2][2][4];
    #pragma unroll
    for (int i = 0; i < 2; ++i)
        #pragma unroll
        for (int j = 0; j < 2; ++j)
            #pragma unroll
            for (int r = 0; r < 4; ++r) o_acc[i][j][r] = 0.0f;

    float m_reg[8], l_reg[8];
    #pragma unroll
    for (int r = 0; r < 8; ++r) { m_reg[r] = -INFINITY; l_reg[r] = 0.0f; }

    for (int t = 0; t <= qb; ++t) {
        __syncthreads();

        // load K [k][d] direct, V transposed [d][k]
        #pragma unroll
        for (int e = 0; e < 4; ++e) {
            int id  = e * 256 + tid;
            int row = id >> 4;
            int dc  = (id & 15) << 2;
            float4 kv = *(const float4*)(Kg + (size_t)(t * 64 + row) * DMODEL + dc);
            *(float4*)(Ks + row * FA_STRIDE + dc) = kv;
            float4 vv = *(const float4*)(Vg + (size_t)(t * 64 + row) * DMODEL + dc);
            Vs[(dc + 0) * FA_STRIDE + row] = vv.x;
            Vs[(dc + 1) * FA_STRIDE + row] = vv.y;
            Vs[(dc + 2) * FA_STRIDE + row] = vv.z;
            Vs[(dc + 3) * FA_STRIDE + row] = vv.w;
        }
        __syncthreads();

        // S = Q K^T via mma
        float sfrag[2][2][4];
        #pragma unroll
        for (int i = 0; i < 2; ++i)
            #pragma unroll
            for (int j = 0; j < 2; ++j)
                #pragma unroll
                for (int r = 0; r < 4; ++r) sfrag[i][j][r] = 0.0f;

        #pragma unroll
        for (int d0 = 0; d0 < 64; d0 += 8) {
            unsigned int aq[2][4], bk[2][2];
            const float* ab = Qs + (wm * 32 + lr) * FA_STRIDE + d0 + lc;
            ldsm4(aq[0], ab);
            ldsm4(aq[1], ab + 16 * FA_STRIDE);
            const float* bb = Ks + (wn * 16 + br) * FA_STRIDE + d0 + bc;
            ldsm2(bk[0], bb);
            ldsm2(bk[1], bb + 8 * FA_STRIDE);
            #pragma unroll
            for (int i = 0; i < 2; ++i)
                #pragma unroll
                for (int j = 0; j < 2; ++j)
                    mma_tf32(sfrag[i][j], aq[i], bk[j]);
        }

        // scale + causal mask, write to Ss
        const bool diag = (t == qb);
        #pragma unroll
        for (int i = 0; i < 2; ++i) {
            const int q = wm * 32 + i * 16 + g;
            #pragma unroll
            for (int j = 0; j < 2; ++j) {
                const int kk = wn * 16 + j * 8 + 2 * t4;
                float s0 = sfrag[i][j][0] * 0.125f;
                float s1 = sfrag[i][j][1] * 0.125f;
                float s2 = sfrag[i][j][2] * 0.125f;
                float s3 = sfrag[i][j][3] * 0.125f;
                if (diag) {
                    if (kk     > q)     s0 = -INFINITY;
                    if (kk + 1 > q)     s1 = -INFINITY;
                    if (kk     > q + 8) s2 = -INFINITY;
                    if (kk + 1 > q + 8) s3 = -INFINITY;
                }
                *(float2*)(Ss + q * FA_STRIDE + kk)       = make_float2(s0, s1);
                *(float2*)(Ss + (q + 8) * FA_STRIDE + kk) = make_float2(s2, s3);
            }
        }
        __syncthreads();

        // online softmax: warp w handles rows w*8 .. w*8+7; p rounded to tf32
        #pragma unroll
        for (int r = 0; r < 8; ++r) {
            int qr = warp * 8 + r;
            float v0 = Ss[qr * FA_STRIDE + lane];
            float v1 = Ss[qr * FA_STRIDE + 32 + lane];
            float mt = fmaxf(v0, v1);
            #pragma unroll
            for (int off = 16; off; off >>= 1)
                mt = fmaxf(mt, __shfl_xor_sync(0xffffffffu, mt, off));
            float mnew = fmaxf(m_reg[r], mt);
            float f  = __expf(m_reg[r] - mnew);
            float p0 = __expf(v0 - mnew);
            float p1 = __expf(v1 - mnew);
            Ss[qr * FA_STRIDE + lane]      = rndtf(p0);
            Ss[qr * FA_STRIDE + 32 + lane] = rndtf(p1);
            float su = p0 + p1;
            #pragma unroll
            for (int off = 16; off; off >>= 1)
                su += __shfl_xor_sync(0xffffffffu, su, off);
            l_reg[r] = l_reg[r] * f + su;
            m_reg[r] = mnew;
            if (lane == 0) row_f[qr] = f;
        }
        __syncthreads();

        // O = O*f + P @ V via mma
        #pragma unroll
        for (int i = 0; i < 2; ++i) {
            const int q = wm * 32 + i * 16 + g;
            float f0 = row_f[q];
            float f1 = row_f[q + 8];
            #pragma unroll
            for (int j = 0; j < 2; ++j) {
                o_acc[i][j][0] *= f0; o_acc[i][j][1] *= f0;
                o_acc[i][j][2] *= f1; o_acc[i][j][3] *= f1;
            }
        }
        #pragma unroll
        for (int k0 = 0; k0 < 64; k0 += 8) {
            unsigned int ap[2][4], bv[2][2];
            const float* ab = Ss + (wm * 32 + lr) * FA_STRIDE + k0 + lc;
            ldsm4(ap[0], ab);
            ldsm4(ap[1], ab + 16 * FA_STRIDE);
            const float* bb = Vs + (wn * 16 + br) * FA_STRIDE + k0 + bc;
            ldsm2(bv[0], bb);
            ldsm2(bv[1], bb + 8 * FA_STRIDE);
            #pragma unroll
            for (int i = 0; i < 2; ++i)
                #pragma unroll
                for (int j = 0; j < 2; ++j)
                    mma_tf32(o_acc[i][j], ap[i], bv[j]);
        }
    }

    if (lane == 0) {
        #pragma unroll
        for (int r = 0; r < 8; ++r) row_l[warp * 8 + r] = l_reg[r];
    }
    __syncthreads();

    // finalize + store (rounded; feeds Wo GEMM)
    float* Og = O + base + (size_t)(qb * 64) * DMODEL;
    #pragma unroll
    for (int i = 0; i < 2; ++i) {
        const int q = wm * 32 + i * 16 + g;
        float inv0 = 1.0f / row_l[q];
        float inv1 = 1.0f / row_l[q + 8];
        #pragma unroll
        for (int j = 0; j < 2; ++j) {
            const int d = wn * 16 + j * 8 + 2 * t4;
            float2 w0 = make_float2(rndtf(o_acc[i][j][0] * inv0),
                                    rndtf(o_acc[i][j][1] * inv0));
            float2 w1 = make_float2(rndtf(o_acc[i][j][2] * inv1),
                                    rndtf(o_acc[i][j][3] * inv1));
            *(float2*)(Og + (size_t)q * DMODEL + d)       = w0;
            *(float2*)(Og + (size_t)(q + 8) * DMODEL + d) = w1;
        }
    }
}

// ---------------------------------------------------------------------------
// SwiGLU combine: a = tf32(silu(a) * c)
// ---------------------------------------------------------------------------
__global__ __launch_bounds__(256) void swiglu_kernel(
    float* __restrict__ a, const float* __restrict__ c, int n4)
{
    int idx = blockIdx.x * blockDim.x + threadIdx.x;
    if (idx >= n4) return;
    float4 av = *(const float4*)(a + (size_t)idx * 4);
    float4 cv = *(const float4*)(c + (size_t)idx * 4);
    float4 o;
    o.x = rndtf(av.x * (1.0f / (1.0f + __expf(-av.x))) * cv.x);
    o.y = rndtf(av.y * (1.0f / (1.0f + __expf(-av.y))) * cv.y);
    o.z = rndtf(av.z * (1.0f / (1.0f + __expf(-av.z))) * cv.z);
    o.w = rndtf(av.w * (1.0f / (1.0f + __expf(-av.w))) * cv.w);
    *(float4*)(a + (size_t)idx * 4) = o;
}

// ---------------------------------------------------------------------------
// Launch
// ---------------------------------------------------------------------------
extern "C" void kernel_launch(void* const* d_in, const int* in_sizes, int n_in,
                              void* d_out, int out_size)
{
    const float* x  = (const float*)d_in[0];
    const float* Wq = (const float*)d_in[1];
    const float* Wk = (const float*)d_in[2];
    const float* Wv = (const float*)d_in[3];
    const float* Wo = (const float*)d_in[4];
    const float* W1 = (const float*)d_in[5];
    const float* W2 = (const float*)d_in[6];
    const float* W3 = (const float*)d_in[7];
    const float* g1 = (const float*)d_in[8];
    const float* g2 = (const float*)d_in[9];
    float* out = (float*)d_out;

    float *h1, *q, *k, *v, *o, *x2, *a, *c;
    float *wq, *wk, *wv, *wo, *w1, *w2, *w3;
    cudaGetSymbolAddress((void**)&h1, g_h1);
    cudaGetSymbolAddress((void**)&q,  g_q);
    cudaGetSymbolAddress((void**)&k,  g_k);
    cudaGetSymbolAddress((void**)&v,  g_v);
    cudaGetSymbolAddress((void**)&o,  g_o);
    cudaGetSymbolAddress((void**)&x2, g_x2);
    cudaGetSymbolAddress((void**)&a,  g_a);
    cudaGetSymbolAddress((void**)&c,  g_c);
    cudaGetSymbolAddress((void**)&wq, g_wq);
    cudaGetSymbolAddress((void**)&wk, g_wk);
    cudaGetSymbolAddress((void**)&wv, g_wv);
    cudaGetSymbolAddress((void**)&wo, g_wo);
    cudaGetSymbolAddress((void**)&w1, g_w1);
    cudaGetSymbolAddress((void**)&w2, g_w2);
    cudaGetSymbolAddress((void**)&w3, g_w3);

    cudaFuncSetAttribute(flash_attn_kernel,
                         cudaFuncAttributeMaxDynamicSharedMemorySize, FA_SMEM_BYTES);
    cudaFuncSetAttribute(gemm_tf32<false, true>,
                         cudaFuncAttributeMaxDynamicSharedMemorySize, GT_SMEM_BYTES);
    cudaFuncSetAttribute(gemm_tf32<false, false>,
                         cudaFuncAttributeMaxDynamicSharedMemorySize, GT_SMEM_BYTES);
    cudaFuncSetAttribute(gemm_tf32<true, false>,
                         cudaFuncAttributeMaxDynamicSharedMemorySize, GT_SMEM_BYTES);

    // 0) round weights to tf32 once per call
    const int n4_dd = DMODEL * DMODEL / 4;   // 262144
    const int n4_ff = DFF * DMODEL / 4;      // 1048576
    round_kernel<<<n4_dd / 256, 256>>>(Wq, wq, n4_dd);
    round_kernel<<<n4_dd / 256, 256>>>(Wk, wk, n4_dd);
    round_kernel<<<n4_dd / 256, 256>>>(Wv, wv, n4_dd);
    round_kernel<<<n4_dd / 256, 256>>>(Wo, wo, n4_dd);
    round_kernel<<<n4_ff / 256, 256>>>(W1, w1, n4_ff);
    round_kernel<<<n4_ff / 256, 256>>>(W2, w2, n4_ff);
    round_kernel<<<n4_ff / 256, 256>>>(W3, w3, n4_ff);

    const dim3 gemm_qkv(DMODEL / 128, NTOK / 128, 3);
    const dim3 gemm_d_d(DMODEL / 128, NTOK / 128, 1);
    const dim3 gemm_w13(DFF / 128,    NTOK / 128, 2);

    // 1) h1 = rmsnorm(x, g1)  [tf32-rounded]
    rmsnorm_kernel<<<NTOK, 256>>>(x, g1, h1);

    // 2) q,k,v = h1 @ W{q,k,v}^T  (fused over z; outputs rounded)
    gemm_tf32<false, true><<<gemm_qkv, 256, GT_SMEM_BYTES>>>(
        h1, wq, wk, wv, nullptr, q, k, v, NTOK, DMODEL, DMODEL);

    // 3) o = causal_attention(q, k, v)  [rounded]
    dim3 fa_grid(SEQ / 64, BATCH * NHEADS);
    flash_attn_kernel<<<fa_grid, 256, FA_SMEM_BYTES>>>(q, k, v, o);

    // 4) x2 = x + o @ Wo^T  (full fp32)
    gemm_tf32<true, false><<<gemm_d_d, 256, GT_SMEM_BYTES>>>(
        o, wo, wo, wo, x, x2, x2, x2, NTOK, DMODEL, DMODEL);

    // 5) h2 = rmsnorm(x2, g2)  [rounded]
    rmsnorm_kernel<<<NTOK, 256>>>(x2, g2, h1);

    // 6) a = h2 @ W1^T, c = h2 @ W3^T  (fused over z)
    gemm_tf32<false, false><<<gemm_w13, 256, GT_SMEM_BYTES>>>(
        h1, w1, w3, w3, nullptr, a, c, c, NTOK, DFF, DMODEL);

    // 7) a = tf32(silu(a) * c)
    int n4 = NTOK * DFF / 4;
    swiglu_kernel<<<n4 / 256, 256>>>(a, c, n4);

    // 8) out = x2 + a @ W2^T  (full fp32)
    gemm_tf32<true, false><<<gemm_d_d, 256, GT_SMEM_BYTES>>>(
        a, w2, w2, w2, x2, out, out, out, NTOK, DMODEL, DFF);
}

// round 5
// speedup vs baseline: 4.3458x; 1.4744x over previous
#include <cuda_runtime.h>
#include <cuda_fp16.h>
#include <stdint.h>
#include <math.h>

// Problem constants
#define BATCH 2
#define SEQ 2048
#define DMODEL 1024
#define NHEADS 16
#define DHEAD 64
#define DFF 4096
#define NTOK (BATCH * SEQ)   // 4096

// ---------------------------------------------------------------------------
// Scratch (device globals; allocation is forbidden)
// ---------------------------------------------------------------------------
__device__ __half g_h1[NTOK * DMODEL];
__device__ __half g_q [NTOK * DMODEL];
__device__ __half g_k [NTOK * DMODEL];
__device__ __half g_v [NTOK * DMODEL];
__device__ __half g_o [NTOK * DMODEL];
__device__ float  g_x2[NTOK * DMODEL];
__device__ __half g_a [NTOK * DFF];
__device__ __half g_c [NTOK * DFF];
// fp16 weights
__device__ __half g_wq[DMODEL * DMODEL];
__device__ __half g_wk[DMODEL * DMODEL];
__device__ __half g_wv[DMODEL * DMODEL];
__device__ __half g_wo[DMODEL * DMODEL];
__device__ __half g_w1[DFF * DMODEL];
__device__ __half g_w2[DMODEL * DFF];
__device__ __half g_w3[DFF * DMODEL];

// ---------------------------------------------------------------------------
// Helpers
// ---------------------------------------------------------------------------
__device__ __forceinline__ void mma_f16(float* c, const unsigned int* a, const unsigned int* b) {
    asm volatile(
        "mma.sync.aligned.m16n8k16.row.col.f32.f16.f16.f32 "
        "{%0,%1,%2,%3}, {%4,%5,%6,%7}, {%8,%9}, {%0,%1,%2,%3};"
        : "+f"(c[0]), "+f"(c[1]), "+f"(c[2]), "+f"(c[3])
        : "r"(a[0]), "r"(a[1]), "r"(a[2]), "r"(a[3]), "r"(b[0]), "r"(b[1]));
}

__device__ __forceinline__ void ldsm4h(unsigned int* r, const __half* p) {
    unsigned int addr = (unsigned int)__cvta_generic_to_shared(p);
    asm volatile("ldmatrix.sync.aligned.m8n8.x4.shared.b16 {%0,%1,%2,%3}, [%4];"
                 : "=r"(r[0]), "=r"(r[1]), "=r"(r[2]), "=r"(r[3]) : "r"(addr));
}
__device__ __forceinline__ void ldsm2h(unsigned int* r, const __half* p) {
    unsigned int addr = (unsigned int)__cvta_generic_to_shared(p);
    asm volatile("ldmatrix.sync.aligned.m8n8.x2.shared.b16 {%0,%1}, [%2];"
                 : "=r"(r[0]), "=r"(r[1]) : "r"(addr));
}

// ---------------------------------------------------------------------------
// Weight convert: fp32 -> fp16 (rn). 8 elems/thread.
// ---------------------------------------------------------------------------
__global__ __launch_bounds__(256) void convert_kernel(
    const float* __restrict__ in, __half* __restrict__ out, int n8)
{
    int idx = blockIdx.x * blockDim.x + threadIdx.x;
    if (idx >= n8) return;
    float4 v0 = *(const float4*)(in + (size_t)idx * 8);
    float4 v1 = *(const float4*)(in + (size_t)idx * 8 + 4);
    __half2 h[4];
    h[0] = __floats2half2_rn(v0.x, v0.y);
    h[1] = __floats2half2_rn(v0.z, v0.w);
    h[2] = __floats2half2_rn(v1.x, v1.y);
    h[3] = __floats2half2_rn(v1.z, v1.w);
    *(uint4*)(out + (size_t)idx * 8) = *(uint4*)h;
}

// ---------------------------------------------------------------------------
// RMSNorm: fp32 in -> fp16 out. One block per token row.
// ---------------------------------------------------------------------------
__global__ __launch_bounds__(256) void rmsnorm_kernel(
    const float* __restrict__ x, const float* __restrict__ g,
    __half* __restrict__ y)
{
    const int row = blockIdx.x;
    const int tid = threadIdx.x;
    const float* xr = x + (size_t)row * DMODEL;

    float4 v = *(const float4*)(xr + tid * 4);
    float ss = v.x * v.x + v.y * v.y + v.z * v.z + v.w * v.w;

    #pragma unroll
    for (int off = 16; off; off >>= 1)
        ss += __shfl_xor_sync(0xffffffffu, ss, off);

    __shared__ float red[8];
    const int lane = tid & 31, warp = tid >> 5;
    if (lane == 0) red[warp] = ss;
    __syncthreads();
    if (warp == 0) {
        float t = (lane < 8) ? red[lane] : 0.0f;
        #pragma unroll
        for (int off = 4; off; off >>= 1)
            t += __shfl_xor_sync(0xffffffffu, t, off);
        if (lane == 0) red[0] = t;
    }
    __syncthreads();

    const float inv = rsqrtf(red[0] * (1.0f / DMODEL) + 1e-5f);
    float4 gv = *(const float4*)(g + tid * 4);
    __half2 h0 = __floats2half2_rn(v.x * inv * gv.x, v.y * inv * gv.y);
    __half2 h1 = __floats2half2_rn(v.z * inv * gv.z, v.w * inv * gv.w);
    __half* yp = y + (size_t)row * DMODEL + tid * 4;
    *(__half2*)(yp)     = h0;
    *(__half2*)(yp + 2) = h1;
}

// ---------------------------------------------------------------------------
// FP16 tensor-core GEMM: C[M,N] = A[M,K] * B[N,K]^T (+ R if MODE==1)
// BM=BN=128, BK=32, 256 threads (8 warps 2x4), warp tile 64x32,
// mma m16n8k16 f16 with f32 accum, ldmatrix, cp.async double-buffered.
// MODE 0: half C, no residual.  MODE 1: float C, + float residual R.
// blockIdx.z selects (B,C) pair.
// ---------------------------------------------------------------------------
#define GH_LDS 40                    // padded row stride (halfs)
#define GH_BUF (128 * GH_LDS)

template <int MODE>
__global__ __launch_bounds__(256) void gemm_f16(
    const __half* __restrict__ A,
    const __half* __restrict__ B0, const __half* __restrict__ B1, const __half* __restrict__ B2,
    const float* __restrict__ R,
    void* __restrict__ C0v, void* __restrict__ C1v, void* __restrict__ C2v,
    int M, int N, int K)
{
    __shared__ __half As[2 * GH_BUF];
    __shared__ __half Bs[2 * GH_BUF];

    const int z = blockIdx.z;
    const __half* B = (z == 0) ? B0 : (z == 1) ? B1 : B2;
    void*         Cv = (z == 0) ? C0v : (z == 1) ? C1v : C2v;

    const int tid  = threadIdx.x;
    const int lane = tid & 31, warp = tid >> 5;
    const int g = lane >> 2, t4 = lane & 3;
    const int wm = warp >> 2, wn = warp & 3;
    const int bm = blockIdx.y, bn = blockIdx.x;

    const int lr = lane & 15;             // A ldsm row
    const int lc = (lane >> 4) << 3;      // A ldsm k-offset (0/8 halfs)
    const int br = lane & 7;              // B ldsm row
    const int bc = ((lane >> 3) & 1) << 3;

    const __half* Ab = A + (size_t)bm * 128 * K;
    const __half* Bb = B + (size_t)bn * 128 * K;

    float acc[4][4][4];
    #pragma unroll
    for (int i = 0; i < 4; ++i)
        #pragma unroll
        for (int j = 0; j < 4; ++j)
            #pragma unroll
            for (int r = 0; r < 4; ++r) acc[i][j][r] = 0.0f;

    const int T = K >> 5;

    auto load_tile = [&](int kt, int buf) {
        #pragma unroll
        for (int e = 0; e < 2; ++e) {
            int id   = e * 256 + tid;      // 0..511 16B-chunk ids
            int row  = id >> 2;            // 0..127
            int col8 = (id & 3) << 3;      // 0,8,16,24 halfs
            const __half* ga = Ab + (size_t)row * K + kt * 32 + col8;
            unsigned int sa = (unsigned int)__cvta_generic_to_shared(
                As + buf * GH_BUF + row * GH_LDS + col8);
            asm volatile("cp.async.cg.shared.global [%0], [%1], 16;\n"
                         :: "r"(sa), "l"(ga));
            const __half* gb = Bb + (size_t)row * K + kt * 32 + col8;
            unsigned int sb = (unsigned int)__cvta_generic_to_shared(
                Bs + buf * GH_BUF + row * GH_LDS + col8);
            asm volatile("cp.async.cg.shared.global [%0], [%1], 16;\n"
                         :: "r"(sb), "l"(gb));
        }
        asm volatile("cp.async.commit_group;\n");
    };

    load_tile(0, 0);

    for (int kt = 0; kt < T; ++kt) {
        const int buf = kt & 1;
        if (kt + 1 < T) {
            load_tile(kt + 1, buf ^ 1);
            asm volatile("cp.async.wait_group 1;\n");
        } else {
            asm volatile("cp.async.wait_group 0;\n");
        }
        __syncthreads();

        const __half* Asb = As + buf * GH_BUF;
        const __half* Bsb = Bs + buf * GH_BUF;

        #pragma unroll
        for (int ks = 0; ks < 2; ++ks) {
            const int k0 = ks * 16;
            unsigned int af[4][4], bf[4][2];
            const __half* abase = Asb + (wm * 64 + lr) * GH_LDS + k0 + lc;
            #pragma unroll
            for (int i = 0; i < 4; ++i)
                ldsm4h(af[i], abase + i * 16 * GH_LDS);
            const __half* bbase = Bsb + (wn * 32 + br) * GH_LDS + k0 + bc;
            #pragma unroll
            for (int j = 0; j < 4; ++j)
                ldsm2h(bf[j], bbase + j * 8 * GH_LDS);
            #pragma unroll
            for (int i = 0; i < 4; ++i)
                #pragma unroll
                for (int j = 0; j < 4; ++j)
                    mma_f16(acc[i][j], af[i], bf[j]);
        }
        __syncthreads();
    }

    #pragma unroll
    for (int i = 0; i < 4; ++i) {
        const int r0 = bm * 128 + wm * 64 + i * 16 + g;
        #pragma unroll
        for (int j = 0; j < 4; ++j) {
            const int c0 = bn * 128 + wn * 32 + j * 8 + 2 * t4;
            if (MODE == 1) {
                float* C = (float*)Cv;
                float2 rr0 = *(const float2*)(R + (size_t)r0 * N + c0);
                float2 rr1 = *(const float2*)(R + (size_t)(r0 + 8) * N + c0);
                *(float2*)(C + (size_t)r0 * N + c0) =
                    make_float2(acc[i][j][0] + rr0.x, acc[i][j][1] + rr0.y);
                *(float2*)(C + (size_t)(r0 + 8) * N + c0) =
                    make_float2(acc[i][j][2] + rr1.x, acc[i][j][3] + rr1.y);
            } else {
                __half* C = (__half*)Cv;
                *(__half2*)(C + (size_t)r0 * N + c0) =
                    __floats2half2_rn(acc[i][j][0], acc[i][j][1]);
                *(__half2*)(C + (size_t)(r0 + 8) * N + c0) =
                    __floats2half2_rn(acc[i][j][2], acc[i][j][3]);
            }
        }
    }
}

// ---------------------------------------------------------------------------
// Flash attention (fp16 mma, fp32 softmax, causal). Grid: (S/64, B*H).
// 256 threads, 8 warps (2 x 4), warp tile 32q x 16n. Tile 64q x 64k, dh=64.
// ---------------------------------------------------------------------------
#define FA_HS 72   // half-array row stride
#define FA_FS 68   // float S row stride
// byte offsets
#define FA_QS 0
#define FA_KS 9216
#define FA_VS 18432
#define FA_PS 27648
#define FA_SS 36864
#define FA_RF 54272
#define FA_RL 54528
#define FA_SMEM_BYTES 54784

__global__ __launch_bounds__(256) void flash_attn_kernel(
    const __half* __restrict__ Q, const __half* __restrict__ K,
    const __half* __restrict__ V, __half* __restrict__ O)
{
    extern __shared__ char smraw[];
    __half* Qs = (__half*)(smraw + FA_QS);   // [64][72] q x d
    __half* Ks = (__half*)(smraw + FA_KS);   // [64][72] k x d
    __half* Vs = (__half*)(smraw + FA_VS);   // [64][72] d x k (transposed)
    __half* Ps = (__half*)(smraw + FA_PS);   // [64][72] q x k
    float*  Ss = (float*)(smraw + FA_SS);    // [64][68] q x k
    float*  row_f = (float*)(smraw + FA_RF);
    float*  row_l = (float*)(smraw + FA_RL);

    const int tid  = threadIdx.x;
    const int lane = tid & 31, warp = tid >> 5;
    const int g = lane >> 2, t4 = lane & 3;
    const int wm = warp >> 2, wn = warp & 3;
    const int lr = lane & 15;
    const int lc = (lane >> 4) << 3;
    const int br = lane & 7;
    const int bc = ((lane >> 3) & 1) << 3;

    const int qb = blockIdx.x;
    const int bh = blockIdx.y;
    const int b = bh >> 4, h = bh & 15;

    const size_t base = ((size_t)b * SEQ) * DMODEL + h * DHEAD;
    const __half* Qg = Q + base + (size_t)(qb * 64) * DMODEL;
    const __half* Kg = K + base;
    const __half* Vg = V + base;

    // load Q tile [q][d]
    #pragma unroll
    for (int e = 0; e < 2; ++e) {
        int id  = e * 256 + tid;      // 0..511
        int row = id >> 3;            // 0..63
        int dc  = (id & 7) << 3;      // 0..56
        *(uint4*)(Qs + row * FA_HS + dc) =
            *(const uint4*)(Qg + (size_t)row * DMODEL + dc);
    }

    float o_acc[2][2][4];
    #pragma unroll
    for (int i = 0; i < 2; ++i)
        #pragma unroll
        for (int j = 0; j < 2; ++j)
            #pragma unroll
            for (int r = 0; r < 4; ++r) o_acc[i][j][r] = 0.0f;

    float m_reg[8], l_reg[8];
    #pragma unroll
    for (int r = 0; r < 8; ++r) { m_reg[r] = -INFINITY; l_reg[r] = 0.0f; }

    for (int t = 0; t <= qb; ++t) {
        __syncthreads();

        // load K [k][d], V transposed [d][k]
        #pragma unroll
        for (int e = 0; e < 2; ++e) {
            int id  = e * 256 + tid;
            int row = id >> 3;
            int dc  = (id & 7) << 3;
            *(uint4*)(Ks + row * FA_HS + dc) =
                *(const uint4*)(Kg + (size_t)(t * 64 + row) * DMODEL + dc);
            uint4 vv = *(const uint4*)(Vg + (size_t)(t * 64 + row) * DMODEL + dc);
            const __half* vh = (const __half*)&vv;
            #pragma unroll
            for (int u = 0; u < 8; ++u)
                Vs[(dc + u) * FA_HS + row] = vh[u];
        }
        __syncthreads();

        // S = Q K^T via mma (fp32 accum)
        float sfrag[2][2][4];
        #pragma unroll
        for (int i = 0; i < 2; ++i)
            #pragma unroll
            for (int j = 0; j < 2; ++j)
                #pragma unroll
                for (int r = 0; r < 4; ++r) sfrag[i][j][r] = 0.0f;

        #pragma unroll
        for (int d0 = 0; d0 < 64; d0 += 16) {
            unsigned int aq[2][4], bk[2][2];
            const __half* ab = Qs + (wm * 32 + lr) * FA_HS + d0 + lc;
            ldsm4h(aq[0], ab);
            ldsm4h(aq[1], ab + 16 * FA_HS);
            const __half* bb = Ks + (wn * 16 + br) * FA_HS + d0 + bc;
            ldsm2h(bk[0], bb);
            ldsm2h(bk[1], bb + 8 * FA_HS);
            #pragma unroll
            for (int i = 0; i < 2; ++i)
                #pragma unroll
                for (int j = 0; j < 2; ++j)
                    mma_f16(sfrag[i][j], aq[i], bk[j]);
        }

        // scale + causal mask, write to Ss (fp32)
        const bool diag = (t == qb);
        #pragma unroll
        for (int i = 0; i < 2; ++i) {
            const int q = wm * 32 + i * 16 + g;
            #pragma unroll
            for (int j = 0; j < 2; ++j) {
                const int kk = wn * 16 + j * 8 + 2 * t4;
                float s0 = sfrag[i][j][0] * 0.125f;
                float s1 = sfrag[i][j][1] * 0.125f;
                float s2 = sfrag[i][j][2] * 0.125f;
                float s3 = sfrag[i][j][3] * 0.125f;
                if (diag) {
                    if (kk     > q)     s0 = -INFINITY;
                    if (kk + 1 > q)     s1 = -INFINITY;
                    if (kk     > q + 8) s2 = -INFINITY;
                    if (kk + 1 > q + 8) s3 = -INFINITY;
                }
                *(float2*)(Ss + q * FA_FS + kk)       = make_float2(s0, s1);
                *(float2*)(Ss + (q + 8) * FA_FS + kk) = make_float2(s2, s3);
            }
        }
        __syncthreads();

        // online softmax (fp32); P written as fp16
        #pragma unroll
        for (int r = 0; r < 8; ++r) {
            int qr = warp * 8 + r;
            float v0 = Ss[qr * FA_FS + lane];
            float v1 = Ss[qr * FA_FS + 32 + lane];
            float mt = fmaxf(v0, v1);
            #pragma unroll
            for (int off = 16; off; off >>= 1)
                mt = fmaxf(mt, __shfl_xor_sync(0xffffffffu, mt, off));
            float mnew = fmaxf(m_reg[r], mt);
            float f  = __expf(m_reg[r] - mnew);
            float p0 = __expf(v0 - mnew);
            float p1 = __expf(v1 - mnew);
            Ps[qr * FA_HS + lane]      = __float2half_rn(p0);
            Ps[qr * FA_HS + 32 + lane] = __float2half_rn(p1);
            float su = p0 + p1;
            #pragma unroll
            for (int off = 16; off; off >>= 1)
                su += __shfl_xor_sync(0xffffffffu, su, off);
            l_reg[r] = l_reg[r] * f + su;
            m_reg[r] = mnew;
            if (lane == 0) row_f[qr] = f;
        }
        __syncthreads();

        // O = O*f + P @ V via mma
        #pragma unroll
        for (int i = 0; i < 2; ++i) {
            const int q = wm * 32 + i * 16 + g;
            float f0 = row_f[q];
            float f1 = row_f[q + 8];
            #pragma unroll
            for (int j = 0; j < 2; ++j) {
                o_acc[i][j][0] *= f0; o_acc[i][j][1] *= f0;
                o_acc[i][j][2] *= f1; o_acc[i][j][3] *= f1;
            }
        }
        #pragma unroll
        for (int k0 = 0; k0 < 64; k0 += 16) {
            unsigned int ap[2][4], bv[2][2];
            const __half* ab = Ps + (wm * 32 + lr) * FA_HS + k0 + lc;
            ldsm4h(ap[0], ab);
            ldsm4h(ap[1], ab + 16 * FA_HS);
            const __half* bb = Vs + (wn * 16 + br) * FA_HS + k0 + bc;
            ldsm2h(bv[0], bb);
            ldsm2h(bv[1], bb + 8 * FA_HS);
            #pragma unroll
            for (int i = 0; i < 2; ++i)
                #pragma unroll
                for (int j = 0; j < 2; ++j)
                    mma_f16(o_acc[i][j], ap[i], bv[j]);
        }
    }

    if (lane == 0) {
        #pragma unroll
        for (int r = 0; r < 8; ++r) row_l[warp * 8 + r] = l_reg[r];
    }
    __syncthreads();

    // finalize + store fp16
    __half* Og = O + base + (size_t)(qb * 64) * DMODEL;
    #pragma unroll
    for (int i = 0; i < 2; ++i) {
        const int q = wm * 32 + i * 16 + g;
        float inv0 = 1.0f / row_l[q];
        float inv1 = 1.0f / row_l[q + 8];
        #pragma unroll
        for (int j = 0; j < 2; ++j) {
            const int d = wn * 16 + j * 8 + 2 * t4;
            *(__half2*)(Og + (size_t)q * DMODEL + d) =
                __floats2half2_rn(o_acc[i][j][0] * inv0, o_acc[i][j][1] * inv0);
            *(__half2*)(Og + (size_t)(q + 8) * DMODEL + d) =
                __floats2half2_rn(o_acc[i][j][2] * inv1, o_acc[i][j][3] * inv1);
        }
    }
}

// ---------------------------------------------------------------------------
// SwiGLU combine: a = h16(silu(a) * c), 8 halfs per thread
// ---------------------------------------------------------------------------
__global__ __launch_bounds__(256) void swiglu_kernel(
    __half* __restrict__ a, const __half* __restrict__ c, int n8)
{
    int idx = blockIdx.x * blockDim.x + threadIdx.x;
    if (idx >= n8) return;
    uint4 au = *(const uint4*)(a + (size_t)idx * 8);
    uint4 cu = *(const uint4*)(c + (size_t)idx * 8);
    const __half2* ah = (const __half2*)&au;
    const __half2* ch = (const __half2*)&cu;
    __half2 oh[4];
    #pragma unroll
    for (int i = 0; i < 4; ++i) {
        float2 af = __half22float2(ah[i]);
        float2 cf = __half22float2(ch[i]);
        float ox = af.x * (1.0f / (1.0f + __expf(-af.x))) * cf.x;
        float oy = af.y * (1.0f / (1.0f + __expf(-af.y))) * cf.y;
        oh[i] = __floats2half2_rn(ox, oy);
    }
    *(uint4*)(a + (size_t)idx * 8) = *(uint4*)oh;
}

// ---------------------------------------------------------------------------
// Launch
// ---------------------------------------------------------------------------
extern "C" void kernel_launch(void* const* d_in, const int* in_sizes, int n_in,
                              void* d_out, int out_size)
{
    const float* x  = (const float*)d_in[0];
    const float* Wq = (const float*)d_in[1];
    const float* Wk = (const float*)d_in[2];
    const float* Wv = (const float*)d_in[3];
    const float* Wo = (const float*)d_in[4];
    const float* W1 = (const float*)d_in[5];
    const float* W2 = (const float*)d_in[6];
    const float* W3 = (const float*)d_in[7];
    const float* g1 = (const float*)d_in[8];
    const float* g2 = (const float*)d_in[9];
    float* out = (float*)d_out;

    __half *h1, *q, *k, *v, *o, *a, *c;
    __half *wq, *wk, *wv, *wo, *w1, *w2, *w3;
    float *x2;
    cudaGetSymbolAddress((void**)&h1, g_h1);
    cudaGetSymbolAddress((void**)&q,  g_q);
    cudaGetSymbolAddress((void**)&k,  g_k);
    cudaGetSymbolAddress((void**)&v,  g_v);
    cudaGetSymbolAddress((void**)&o,  g_o);
    cudaGetSymbolAddress((void**)&x2, g_x2);
    cudaGetSymbolAddress((void**)&a,  g_a);
    cudaGetSymbolAddress((void**)&c,  g_c);
    cudaGetSymbolAddress((void**)&wq, g_wq);
    cudaGetSymbolAddress((void**)&wk, g_wk);
    cudaGetSymbolAddress((void**)&wv, g_wv);
    cudaGetSymbolAddress((void**)&wo, g_wo);
    cudaGetSymbolAddress((void**)&w1, g_w1);
    cudaGetSymbolAddress((void**)&w2, g_w2);
    cudaGetSymbolAddress((void**)&w3, g_w3);

    cudaFuncSetAttribute(flash_attn_kernel,
                         cudaFuncAttributeMaxDynamicSharedMemorySize, FA_SMEM_BYTES);

    // 0) convert weights to fp16
    const int n8_dd = DMODEL * DMODEL / 8;   // 131072
    const int n8_ff = DFF * DMODEL / 8;      // 524288
    convert_kernel<<<n8_dd / 256, 256>>>(Wq, wq, n8_dd);
    convert_kernel<<<n8_dd / 256, 256>>>(Wk, wk, n8_dd);
    convert_kernel<<<n8_dd / 256, 256>>>(Wv, wv, n8_dd);
    convert_kernel<<<n8_dd / 256, 256>>>(Wo, wo, n8_dd);
    convert_kernel<<<n8_ff / 256, 256>>>(W1, w1, n8_ff);
    convert_kernel<<<n8_ff / 256, 256>>>(W2, w2, n8_ff);
    convert_kernel<<<n8_ff / 256, 256>>>(W3, w3, n8_ff);

    const dim3 gemm_qkv(DMODEL / 128, NTOK / 128, 3);
    const dim3 gemm_d_d(DMODEL / 128, NTOK / 128, 1);
    const dim3 gemm_w13(DFF / 128,    NTOK / 128, 2);

    // 1) h1 = rmsnorm(x, g1) -> fp16
    rmsnorm_kernel<<<NTOK, 256>>>(x, g1, h1);

    // 2) q,k,v = h1 @ W{q,k,v}^T (fused over z)
    gemm_f16<0><<<gemm_qkv, 256>>>(h1, wq, wk, wv, nullptr,
                                   q, k, v, NTOK, DMODEL, DMODEL);

    // 3) o = causal_attention(q, k, v)
    dim3 fa_grid(SEQ / 64, BATCH * NHEADS);
    flash_attn_kernel<<<fa_grid, 256, FA_SMEM_BYTES>>>(q, k, v, o);

    // 4) x2 = x + o @ Wo^T (fp32 out)
    gemm_f16<1><<<gemm_d_d, 256>>>(o, wo, wo, wo, x,
                                   x2, x2, x2, NTOK, DMODEL, DMODEL);

    // 5) h2 = rmsnorm(x2, g2) -> fp16
    rmsnorm_kernel<<<NTOK, 256>>>(x2, g2, h1);

    // 6) a = h2 @ W1^T, c = h2 @ W3^T (fused over z)
    gemm_f16<0><<<gemm_w13, 256>>>(h1, w1, w3, w3, nullptr,
                                   a, c, c, NTOK, DFF, DMODEL);

    // 7) a = silu(a) * c
    int n8 = NTOK * DFF / 8;
    swiglu_kernel<<<n8 / 256, 256>>>(a, c, n8);

    // 8) out = x2 + a @ W2^T (fp32 out)
    gemm_f16<1><<<gemm_d_d, 256>>>(a, w2, w2, w2, x2,
                                   out, out, out, NTOK, DMODEL, DFF);
}

// round 7
// speedup vs baseline: 4.9628x; 1.1420x over previous
#include <cuda_runtime.h>
#include <cuda_fp16.h>
#include <stdint.h>
#include <math.h>

// Problem constants
#define BATCH 2
#define SEQ 2048
#define DMODEL 1024
#define NHEADS 16
#define DHEAD 64
#define DFF 4096
#define NTOK (BATCH * SEQ)   // 4096

// ---------------------------------------------------------------------------
// Scratch (device globals; allocation is forbidden)
// ---------------------------------------------------------------------------
__device__ __half g_h1[NTOK * DMODEL];
__device__ __half g_q [NTOK * DMODEL];
__device__ __half g_k [NTOK * DMODEL];
__device__ __half g_v [NTOK * DMODEL];
__device__ __half g_o [NTOK * DMODEL];
__device__ float  g_x2[NTOK * DMODEL];
__device__ __half g_a [NTOK * DFF];
__device__ __half g_c [NTOK * DFF];
// fp16 weights
__device__ __half g_wq[DMODEL * DMODEL];
__device__ __half g_wk[DMODEL * DMODEL];
__device__ __half g_wv[DMODEL * DMODEL];
__device__ __half g_wo[DMODEL * DMODEL];
__device__ __half g_w1[DFF * DMODEL];
__device__ __half g_w2[DMODEL * DFF];
__device__ __half g_w3[DFF * DMODEL];

// ---------------------------------------------------------------------------
// mma.sync helpers
// ---------------------------------------------------------------------------
__device__ __forceinline__ void mma_f16(float* c, const unsigned int* a, const unsigned int* b) {
    asm volatile(
        "mma.sync.aligned.m16n8k16.row.col.f32.f16.f16.f32 "
        "{%0,%1,%2,%3}, {%4,%5,%6,%7}, {%8,%9}, {%0,%1,%2,%3};"
        : "+f"(c[0]), "+f"(c[1]), "+f"(c[2]), "+f"(c[3])
        : "r"(a[0]), "r"(a[1]), "r"(a[2]), "r"(a[3]), "r"(b[0]), "r"(b[1]));
}
__device__ __forceinline__ void ldsm4h(unsigned int* r, const __half* p) {
    unsigned int addr = (unsigned int)__cvta_generic_to_shared(p);
    asm volatile("ldmatrix.sync.aligned.m8n8.x4.shared.b16 {%0,%1,%2,%3}, [%4];"
                 : "=r"(r[0]), "=r"(r[1]), "=r"(r[2]), "=r"(r[3]) : "r"(addr));
}
__device__ __forceinline__ void ldsm2h(unsigned int* r, const __half* p) {
    unsigned int addr = (unsigned int)__cvta_generic_to_shared(p);
    asm volatile("ldmatrix.sync.aligned.m8n8.x2.shared.b16 {%0,%1}, [%2];"
                 : "=r"(r[0]), "=r"(r[1]) : "r"(addr));
}

// SW128 swizzled pointer within a [128 rows x 128 bytes] tile.
// halfcol must be a multiple of 8.
__device__ __forceinline__ const __half* swp(const __half* base, int row, int halfcol) {
    unsigned int off = (unsigned int)(row * 128) + (((unsigned int)(halfcol * 2)) ^ (((unsigned int)row & 7u) * 16u));
    return (const __half*)((const char*)base + off);
}

// ---------------------------------------------------------------------------
// Fused weight convert: all 7 weight matrices fp32 -> fp16 in one launch.
// Unit = 8 floats. Segments: 4 x NDD8 (Wq,Wk,Wv,Wo), 3 x NFF8 (W1,W2,W3).
// ---------------------------------------------------------------------------
#define NDD8 (DMODEL * DMODEL / 8)   // 131072
#define NFF8 (DFF * DMODEL / 8)      // 524288
#define NTOT8 (4 * NDD8 + 3 * NFF8)  // 2097152

__global__ __launch_bounds__(256) void convert_all_kernel(
    const float* __restrict__ s0, const float* __restrict__ s1,
    const float* __restrict__ s2, const float* __restrict__ s3,
    const float* __restrict__ s4, const float* __restrict__ s5,
    const float* __restrict__ s6,
    __half* __restrict__ d0, __half* __restrict__ d1,
    __half* __restrict__ d2, __half* __restrict__ d3,
    __half* __restrict__ d4, __half* __restrict__ d5,
    __half* __restrict__ d6)
{
    int idx = blockIdx.x * 256 + threadIdx.x;
    if (idx >= NTOT8) return;

    const float* src;
    __half* dst;
    int off;
    if (idx < 4 * NDD8) {
        int seg = idx / NDD8;
        off = idx - seg * NDD8;
        src = (seg == 0) ? s0 : (seg == 1) ? s1 : (seg == 2) ? s2 : s3;
        dst = (seg == 0) ? d0 : (seg == 1) ? d1 : (seg == 2) ? d2 : d3;
    } else {
        int r = idx - 4 * NDD8;
        int seg = r / NFF8;
        off = r - seg * NFF8;
        src = (seg == 0) ? s4 : (seg == 1) ? s5 : s6;
        dst = (seg == 0) ? d4 : (seg == 1) ? d5 : d6;
    }

    float4 v0 = *(const float4*)(src + (size_t)off * 8);
    float4 v1 = *(const float4*)(src + (size_t)off * 8 + 4);
    __half2 h[4];
    h[0] = __floats2half2_rn(v0.x, v0.y);
    h[1] = __floats2half2_rn(v0.z, v0.w);
    h[2] = __floats2half2_rn(v1.x, v1.y);
    h[3] = __floats2half2_rn(v1.z, v1.w);
    *(uint4*)(dst + (size_t)off * 8) = *(uint4*)h;
}

// ---------------------------------------------------------------------------
// RMSNorm: fp32 in -> fp16 out.
// ---------------------------------------------------------------------------
__global__ __launch_bounds__(256) void rmsnorm_kernel(
    const float* __restrict__ x, const float* __restrict__ g,
    __half* __restrict__ y)
{
    const int row = blockIdx.x;
    const int tid = threadIdx.x;
    const float* xr = x + (size_t)row * DMODEL;

    float4 v = *(const float4*)(xr + tid * 4);
    float ss = v.x * v.x + v.y * v.y + v.z * v.z + v.w * v.w;

    #pragma unroll
    for (int off = 16; off; off >>= 1)
        ss += __shfl_xor_sync(0xffffffffu, ss, off);

    __shared__ float red[8];
    const int lane = tid & 31, warp = tid >> 5;
    if (lane == 0) red[warp] = ss;
    __syncthreads();
    if (warp == 0) {
        float t = (lane < 8) ? red[lane] : 0.0f;
        #pragma unroll
        for (int off = 4; off; off >>= 1)
            t += __shfl_xor_sync(0xffffffffu, t, off);
        if (lane == 0) red[0] = t;
    }
    __syncthreads();

    const float inv = rsqrtf(red[0] * (1.0f / DMODEL) + 1e-5f);
    float4 gv = *(const float4*)(g + tid * 4);
    __half2 h0 = __floats2half2_rn(v.x * inv * gv.x, v.y * inv * gv.y);
    __half2 h1 = __floats2half2_rn(v.z * inv * gv.z, v.w * inv * gv.w);
    __half* yp = y + (size_t)row * DMODEL + tid * 4;
    *(__half2*)(yp)     = h0;
    *(__half2*)(yp + 2) = h1;
}

// ---------------------------------------------------------------------------
// FP16 tensor-core GEMM: C[M,N] = A[M,K] * B[N,K]^T (+ float R if MODE==1)
// BM=BN=128, BK=64 halfs (128B rows, SW128 XOR swizzle, no padding),
// 256 threads (8 warps 2x4), warp tile 64x32, 3-stage cp.async pipeline.
// MODE 0: half C.  MODE 1: float C = acc + R.  blockIdx.z selects (B,C).
// ---------------------------------------------------------------------------
#define GF_STAGE_H (128 * 64)                 // halfs per matrix per stage
#define GF_SMEM (6 * GF_STAGE_H * 2)          // 3 stages x (A+B) = 98304 bytes

template <int MODE>
__global__ __launch_bounds__(256) void gemm_f16(
    const __half* __restrict__ A,
    const __half* __restrict__ B0, const __half* __restrict__ B1, const __half* __restrict__ B2,
    const float* __restrict__ R,
    void* __restrict__ C0v, void* __restrict__ C1v, void* __restrict__ C2v,
    int M, int N, int K)
{
    extern __shared__ __half smh[];
    __half* As = smh;                       // 3 stages
    __half* Bs = smh + 3 * GF_STAGE_H;      // 3 stages

    const int z = blockIdx.z;
    const __half* B = (z == 0) ? B0 : (z == 1) ? B1 : B2;
    void*         Cv = (z == 0) ? C0v : (z == 1) ? C1v : C2v;

    const int tid  = threadIdx.x;
    const int lane = tid & 31, warp = tid >> 5;
    const int g = lane >> 2, t4 = lane & 3;
    const int wm = warp >> 2, wn = warp & 3;
    const int bm = blockIdx.y, bn = blockIdx.x;

    const int lr = lane & 15;             // A ldsm row
    const int lc = (lane >> 4) << 3;      // A ldsm k-offset (0/8 halfs)
    const int br = lane & 7;              // B ldsm row
    const int bc = ((lane >> 3) & 1) << 3;

    const __half* Ab = A + (size_t)bm * 128 * K;
    const __half* Bb = B + (size_t)bn * 128 * K;

    float acc[4][4][4];
    #pragma unroll
    for (int i = 0; i < 4; ++i)
        #pragma unroll
        for (int j = 0; j < 4; ++j)
            #pragma unroll
            for (int r = 0; r < 4; ++r) acc[i][j][r] = 0.0f;

    const int T = K >> 6;   // 64-half k-tiles (T >= 16 here)

    auto load_tile = [&](int kt, int st) {
        const __half* Asrc = Ab + kt * 64;
        const __half* Bsrc = Bb + kt * 64;
        __half* Adst = As + st * GF_STAGE_H;
        __half* Bdst = Bs + st * GF_STAGE_H;
        #pragma unroll
        for (int e = 0; e < 4; ++e) {
            int id  = e * 256 + tid;     // 0..1023 chunk ids
            int row = id >> 3;           // 0..127
            int c16 = id & 7;            // 16B chunk in 128B row
            unsigned int sw = (unsigned int)(row * 128) + (((unsigned int)c16 ^ ((unsigned int)row & 7u)) * 16u);
            unsigned int sa = (unsigned int)__cvta_generic_to_shared((const char*)Adst + sw);
            asm volatile("cp.async.cg.shared.global [%0], [%1], 16;\n"
                         :: "r"(sa), "l"(Asrc + (size_t)row * K + c16 * 8));
            unsigned int sb = (unsigned int)__cvta_generic_to_shared((const char*)Bdst + sw);
            asm volatile("cp.async.cg.shared.global [%0], [%1], 16;\n"
                         :: "r"(sb), "l"(Bsrc + (size_t)row * K + c16 * 8));
        }
        asm volatile("cp.async.commit_group;\n");
    };

    load_tile(0, 0);
    load_tile(1, 1);

    for (int kt = 0; kt < T; ++kt) {
        if (kt + 2 < T) {
            load_tile(kt + 2, (kt + 2) % 3);
            asm volatile("cp.async.wait_group 2;\n");
        } else if (kt + 1 < T) {
            asm volatile("cp.async.wait_group 1;\n");
        } else {
            asm volatile("cp.async.wait_group 0;\n");
        }
        __syncthreads();

        const __half* Asb = As + (kt % 3) * GF_STAGE_H;
        const __half* Bsb = Bs + (kt % 3) * GF_STAGE_H;

        #pragma unroll
        for (int ks = 0; ks < 4; ++ks) {
            const int k0 = ks * 16;
            unsigned int af[4][4], bf[4][2];
            #pragma unroll
            for (int i = 0; i < 4; ++i)
                ldsm4h(af[i], swp(Asb, wm * 64 + i * 16 + lr, k0 + lc));
            #pragma unroll
            for (int j = 0; j < 4; ++j)
                ldsm2h(bf[j], swp(Bsb, wn * 32 + j * 8 + br, k0 + bc));
            #pragma unroll
            for (int i = 0; i < 4; ++i)
                #pragma unroll
                for (int j = 0; j < 4; ++j)
                    mma_f16(acc[i][j], af[i], bf[j]);
        }
        __syncthreads();
    }

    #pragma unroll
    for (int i = 0; i < 4; ++i) {
        const int r0 = bm * 128 + wm * 64 + i * 16 + g;
        #pragma unroll
        for (int j = 0; j < 4; ++j) {
            const int c0 = bn * 128 + wn * 32 + j * 8 + 2 * t4;
            if (MODE == 1) {
                float* C = (float*)Cv;
                float2 rr0 = *(const float2*)(R + (size_t)r0 * N + c0);
                float2 rr1 = *(const float2*)(R + (size_t)(r0 + 8) * N + c0);
                *(float2*)(C + (size_t)r0 * N + c0) =
                    make_float2(acc[i][j][0] + rr0.x, acc[i][j][1] + rr0.y);
                *(float2*)(C + (size_t)(r0 + 8) * N + c0) =
                    make_float2(acc[i][j][2] + rr1.x, acc[i][j][3] + rr1.y);
            } else {
                __half* C = (__half*)Cv;
                *(__half2*)(C + (size_t)r0 * N + c0) =
                    __floats2half2_rn(acc[i][j][0], acc[i][j][1]);
                *(__half2*)(C + (size_t)(r0 + 8) * N + c0) =
                    __floats2half2_rn(acc[i][j][2], acc[i][j][3]);
            }
        }
    }
}

// ---------------------------------------------------------------------------
// Flash attention (fp16 mma.sync, fp32 softmax, causal). Grid: (S/64, B*H).
// ---------------------------------------------------------------------------
#define FA_HS 72
#define FA_FS 68
#define FA_QS 0
#define FA_KS 9216
#define FA_VS 18432
#define FA_PS 27648
#define FA_SS 36864
#define FA_RF 54272
#define FA_RL 54528
#define FA_SMEM_BYTES 54784

__global__ __launch_bounds__(256) void flash_attn_kernel(
    const __half* __restrict__ Q, const __half* __restrict__ K,
    const __half* __restrict__ V, __half* __restrict__ O)
{
    extern __shared__ char smraw[];
    __half* Qs = (__half*)(smraw + FA_QS);
    __half* Ks = (__half*)(smraw + FA_KS);
    __half* Vs = (__half*)(smraw + FA_VS);
    __half* Ps = (__half*)(smraw + FA_PS);
    float*  Ss = (float*)(smraw + FA_SS);
    float*  row_f = (float*)(smraw + FA_RF);
    float*  row_l = (float*)(smraw + FA_RL);

    const int tid  = threadIdx.x;
    const int lane = tid & 31, warp = tid >> 5;
    const int g = lane >> 2, t4 = lane & 3;
    const int wm = warp >> 2, wn = warp & 3;
    const int lr = lane & 15;
    const int lc = (lane >> 4) << 3;
    const int br = lane & 7;
    const int bc = ((lane >> 3) & 1) << 3;

    const int qb = blockIdx.x;
    const int bh = blockIdx.y;
    const int b = bh >> 4, h = bh & 15;

    const size_t base = ((size_t)b * SEQ) * DMODEL + h * DHEAD;
    const __half* Qg = Q + base + (size_t)(qb * 64) * DMODEL;
    const __half* Kg = K + base;
    const __half* Vg = V + base;

    #pragma unroll
    for (int e = 0; e < 2; ++e) {
        int id  = e * 256 + tid;
        int row = id >> 3;
        int dc  = (id & 7) << 3;
        *(uint4*)(Qs + row * FA_HS + dc) =
            *(const uint4*)(Qg + (size_t)row * DMODEL + dc);
    }

    float o_acc[2][2][4];
    #pragma unroll
    for (int i = 0; i < 2; ++i)
        #pragma unroll
        for (int j = 0; j < 2; ++j)
            #pragma unroll
            for (int r = 0; r < 4; ++r) o_acc[i][j][r] = 0.0f;

    float m_reg[8], l_reg[8];
    #pragma unroll
    for (int r = 0; r < 8; ++r) { m_reg[r] = -INFINITY; l_reg[r] = 0.0f; }

    for (int t = 0; t <= qb; ++t) {
        __syncthreads();

        #pragma unroll
        for (int e = 0; e < 2; ++e) {
            int id  = e * 256 + tid;
            int row = id >> 3;
            int dc  = (id & 7) << 3;
            *(uint4*)(Ks + row * FA_HS + dc) =
                *(const uint4*)(Kg + (size_t)(t * 64 + row) * DMODEL + dc);
            uint4 vv = *(const uint4*)(Vg + (size_t)(t * 64 + row) * DMODEL + dc);
            const __half* vh = (const __half*)&vv;
            #pragma unroll
            for (int u = 0; u < 8; ++u)
                Vs[(dc + u) * FA_HS + row] = vh[u];
        }
        __syncthreads();

        float sfrag[2][2][4];
        #pragma unroll
        for (int i = 0; i < 2; ++i)
            #pragma unroll
            for (int j = 0; j < 2; ++j)
                #pragma unroll
                for (int r = 0; r < 4; ++r) sfrag[i][j][r] = 0.0f;

        #pragma unroll
        for (int d0 = 0; d0 < 64; d0 += 16) {
            unsigned int aq[2][4], bk[2][2];
            const __half* ab = Qs + (wm * 32 + lr) * FA_HS + d0 + lc;
            ldsm4h(aq[0], ab);
            ldsm4h(aq[1], ab + 16 * FA_HS);
            const __half* bb = Ks + (wn * 16 + br) * FA_HS + d0 + bc;
            ldsm2h(bk[0], bb);
            ldsm2h(bk[1], bb + 8 * FA_HS);
            #pragma unroll
            for (int i = 0; i < 2; ++i)
                #pragma unroll
                for (int j = 0; j < 2; ++j)
                    mma_f16(sfrag[i][j], aq[i], bk[j]);
        }

        const bool diag = (t == qb);
        #pragma unroll
        for (int i = 0; i < 2; ++i) {
            const int q = wm * 32 + i * 16 + g;
            #pragma unroll
            for (int j = 0; j < 2; ++j) {
                const int kk = wn * 16 + j * 8 + 2 * t4;
                float s0 = sfrag[i][j][0] * 0.125f;
                float s1 = sfrag[i][j][1] * 0.125f;
                float s2 = sfrag[i][j][2] * 0.125f;
                float s3 = sfrag[i][j][3] * 0.125f;
                if (diag) {
                    if (kk     > q)     s0 = -INFINITY;
                    if (kk + 1 > q)     s1 = -INFINITY;
                    if (kk     > q + 8) s2 = -INFINITY;
                    if (kk + 1 > q + 8) s3 = -INFINITY;
                }
                *(float2*)(Ss + q * FA_FS + kk)       = make_float2(s0, s1);
                *(float2*)(Ss + (q + 8) * FA_FS + kk) = make_float2(s2, s3);
            }
        }
        __syncthreads();

        #pragma unroll
        for (int r = 0; r < 8; ++r) {
            int qr = warp * 8 + r;
            float v0 = Ss[qr * FA_FS + lane];
            float v1 = Ss[qr * FA_FS + 32 + lane];
            float mt = fmaxf(v0, v1);
            #pragma unroll
            for (int off = 16; off; off >>= 1)
                mt = fmaxf(mt, __shfl_xor_sync(0xffffffffu, mt, off));
            float mnew = fmaxf(m_reg[r], mt);
            float f  = __expf(m_reg[r] - mnew);
            float p0 = __expf(v0 - mnew);
            float p1 = __expf(v1 - mnew);
            Ps[qr * FA_HS + lane]      = __float2half_rn(p0);
            Ps[qr * FA_HS + 32 + lane] = __float2half_rn(p1);
            float su = p0 + p1;
            #pragma unroll
            for (int off = 16; off; off >>= 1)
                su += __shfl_xor_sync(0xffffffffu, su, off);
            l_reg[r] = l_reg[r] * f + su;
            m_reg[r] = mnew;
            if (lane == 0) row_f[qr] = f;
        }
        __syncthreads();

        #pragma unroll
        for (int i = 0; i < 2; ++i) {
            const int q = wm * 32 + i * 16 + g;
            float f0 = row_f[q];
            float f1 = row_f[q + 8];
            #pragma unroll
            for (int j = 0; j < 2; ++j) {
                o_acc[i][j][0] *= f0; o_acc[i][j][1] *= f0;
                o_acc[i][j][2] *= f1; o_acc[i][j][3] *= f1;
            }
        }
        #pragma unroll
        for (int k0 = 0; k0 < 64; k0 += 16) {
            unsigned int ap[2][4], bv[2][2];
            const __half* ab = Ps + (wm * 32 + lr) * FA_HS + k0 + lc;
            ldsm4h(ap[0], ab);
            ldsm4h(ap[1], ab + 16 * FA_HS);
            const __half* bb = Vs + (wn * 16 + br) * FA_HS + k0 + bc;
            ldsm2h(bv[0], bb);
            ldsm2h(bv[1], bb + 8 * FA_HS);
            #pragma unroll
            for (int i = 0; i < 2; ++i)
                #pragma unroll
                for (int j = 0; j < 2; ++j)
                    mma_f16(o_acc[i][j], ap[i], bv[j]);
        }
    }

    if (lane == 0) {
        #pragma unroll
        for (int r = 0; r < 8; ++r) row_l[warp * 8 + r] = l_reg[r];
    }
    __syncthreads();

    __half* Og = O + base + (size_t)(qb * 64) * DMODEL;
    #pragma unroll
    for (int i = 0; i < 2; ++i) {
        const int q = wm * 32 + i * 16 + g;
        float inv0 = 1.0f / row_l[q];
        float inv1 = 1.0f / row_l[q + 8];
        #pragma unroll
        for (int j = 0; j < 2; ++j) {
            const int d = wn * 16 + j * 8 + 2 * t4;
            *(__half2*)(Og + (size_t)q * DMODEL + d) =
                __floats2half2_rn(o_acc[i][j][0] * inv0, o_acc[i][j][1] * inv0);
            *(__half2*)(Og + (size_t)(q + 8) * DMODEL + d) =
                __floats2half2_rn(o_acc[i][j][2] * inv1, o_acc[i][j][3] * inv1);
        }
    }
}

// ---------------------------------------------------------------------------
// SwiGLU combine: a = h16(silu(a) * c)
// ---------------------------------------------------------------------------
__global__ __launch_bounds__(256) void swiglu_kernel(
    __half* __restrict__ a, const __half* __restrict__ c, int n8)
{
    int idx = blockIdx.x * blockDim.x + threadIdx.x;
    if (idx >= n8) return;
    uint4 au = *(const uint4*)(a + (size_t)idx * 8);
    uint4 cu = *(const uint4*)(c + (size_t)idx * 8);
    const __half2* ah = (const __half2*)&au;
    const __half2* ch = (const __half2*)&cu;
    __half2 oh[4];
    #pragma unroll
    for (int i = 0; i < 4; ++i) {
        float2 af = __half22float2(ah[i]);
        float2 cf = __half22float2(ch[i]);
        float ox = af.x * (1.0f / (1.0f + __expf(-af.x))) * cf.x;
        float oy = af.y * (1.0f / (1.0f + __expf(-af.y))) * cf.y;
        oh[i] = __floats2half2_rn(ox, oy);
    }
    *(uint4*)(a + (size_t)idx * 8) = *(uint4*)oh;
}

// ---------------------------------------------------------------------------
// Launch
// ---------------------------------------------------------------------------
extern "C" void kernel_launch(void* const* d_in, const int* in_sizes, int n_in,
                              void* d_out, int out_size)
{
    const float* x  = (const float*)d_in[0];
    const float* Wq = (const float*)d_in[1];
    const float* Wk = (const float*)d_in[2];
    const float* Wv = (const float*)d_in[3];
    const float* Wo = (const float*)d_in[4];
    const float* W1 = (const float*)d_in[5];
    const float* W2 = (const float*)d_in[6];
    const float* W3 = (const float*)d_in[7];
    const float* g1 = (const float*)d_in[8];
    const float* g2 = (const float*)d_in[9];
    float* out = (float*)d_out;

    __half *h1, *q, *k, *v, *o, *a, *c;
    __half *wq, *wk, *wv, *wo, *w1, *w2, *w3;
    float *x2;
    cudaGetSymbolAddress((void**)&h1, g_h1);
    cudaGetSymbolAddress((void**)&q,  g_q);
    cudaGetSymbolAddress((void**)&k,  g_k);
    cudaGetSymbolAddress((void**)&v,  g_v);
    cudaGetSymbolAddress((void**)&o,  g_o);
    cudaGetSymbolAddress((void**)&x2, g_x2);
    cudaGetSymbolAddress((void**)&a,  g_a);
    cudaGetSymbolAddress((void**)&c,  g_c);
    cudaGetSymbolAddress((void**)&wq, g_wq);
    cudaGetSymbolAddress((void**)&wk, g_wk);
    cudaGetSymbolAddress((void**)&wv, g_wv);
    cudaGetSymbolAddress((void**)&wo, g_wo);
    cudaGetSymbolAddress((void**)&w1, g_w1);
    cudaGetSymbolAddress((void**)&w2, g_w2);
    cudaGetSymbolAddress((void**)&w3, g_w3);

    cudaFuncSetAttribute(flash_attn_kernel,
                         cudaFuncAttributeMaxDynamicSharedMemorySize, FA_SMEM_BYTES);
    cudaFuncSetAttribute(gemm_f16<0>,
                         cudaFuncAttributeMaxDynamicSharedMemorySize, GF_SMEM);
    cudaFuncSetAttribute(gemm_f16<1>,
                         cudaFuncAttributeMaxDynamicSharedMemorySize, GF_SMEM);

    // 0) convert all weights to fp16 in one launch
    convert_all_kernel<<<NTOT8 / 256, 256>>>(Wq, Wk, Wv, Wo, W1, W2, W3,
                                             wq, wk, wv, wo, w1, w2, w3);

    const dim3 gemm_qkv(DMODEL / 128, NTOK / 128, 3);   // (8, 32, 3)
    const dim3 gemm_d_d(DMODEL / 128, NTOK / 128, 1);   // (8, 32)
    const dim3 gemm_w13(DFF / 128,    NTOK / 128, 2);   // (32, 32, 2)

    // 1) h1 = rmsnorm(x, g1) -> fp16
    rmsnorm_kernel<<<NTOK, 256>>>(x, g1, h1);

    // 2) q,k,v = h1 @ W{q,k,v}^T
    gemm_f16<0><<<gemm_qkv, 256, GF_SMEM>>>(h1, wq, wk, wv, nullptr,
                                            q, k, v, NTOK, DMODEL, DMODEL);

    // 3) o = causal_attention(q, k, v)
    dim3 fa_grid(SEQ / 64, BATCH * NHEADS);
    flash_attn_kernel<<<fa_grid, 256, FA_SMEM_BYTES>>>(q, k, v, o);

    // 4) x2 = x + o @ Wo^T (fp32 out)
    gemm_f16<1><<<gemm_d_d, 256, GF_SMEM>>>(o, wo, wo, wo, x,
                                            x2, x2, x2, NTOK, DMODEL, DMODEL);

    // 5) h2 = rmsnorm(x2, g2) -> fp16
    rmsnorm_kernel<<<NTOK, 256>>>(x2, g2, h1);

    // 6) a = h2 @ W1^T, c = h2 @ W3^T
    gemm_f16<0><<<gemm_w13, 256, GF_SMEM>>>(h1, w1, w3, w3, nullptr,
                                            a, c, c, NTOK, DFF, DMODEL);

    // 7) a = silu(a) * c
    int n8 = NTOK * DFF / 8;
    swiglu_kernel<<<n8 / 256, 256>>>(a, c, n8);

    // 8) out = x2 + a @ W2^T (fp32 out)
    gemm_f16<1><<<gemm_d_d, 256, GF_SMEM>>>(a, w2, w2, w2, x2,
                                            out, out, out, NTOK, DMODEL, DFF);
}

// round 8
// speedup vs baseline: 6.6926x; 1.3485x over previous
#include <cuda_runtime.h>
#include <cuda_fp16.h>
#include <stdint.h>
#include <math.h>

// Problem constants
#define BATCH 2
#define SEQ 2048
#define DMODEL 1024
#define NHEADS 16
#define DHEAD 64
#define DFF 4096
#define NTOK (BATCH * SEQ)   // 4096

// ---------------------------------------------------------------------------
// Scratch (device globals; allocation is forbidden)
// ---------------------------------------------------------------------------
__device__ __half g_h1[NTOK * DMODEL];
__device__ __half g_q [NTOK * DMODEL];
__device__ __half g_k [NTOK * DMODEL];
__device__ __half g_v [NTOK * DMODEL];
__device__ __half g_o [NTOK * DMODEL];
__device__ float  g_x2[NTOK * DMODEL];
__device__ __half g_a [NTOK * DFF];
__device__ __half g_c [NTOK * DFF];
// fp16 weights
__device__ __half g_wq[DMODEL * DMODEL];
__device__ __half g_wk[DMODEL * DMODEL];
__device__ __half g_wv[DMODEL * DMODEL];
__device__ __half g_wo[DMODEL * DMODEL];
__device__ __half g_w1[DFF * DMODEL];
__device__ __half g_w2[DMODEL * DFF];
__device__ __half g_w3[DFF * DMODEL];

// ---------------------------------------------------------------------------
// mma.sync helpers
// ---------------------------------------------------------------------------
__device__ __forceinline__ void mma_f16(float* c, const unsigned int* a, const unsigned int* b) {
    asm volatile(
        "mma.sync.aligned.m16n8k16.row.col.f32.f16.f16.f32 "
        "{%0,%1,%2,%3}, {%4,%5,%6,%7}, {%8,%9}, {%0,%1,%2,%3};"
        : "+f"(c[0]), "+f"(c[1]), "+f"(c[2]), "+f"(c[3])
        : "r"(a[0]), "r"(a[1]), "r"(a[2]), "r"(a[3]), "r"(b[0]), "r"(b[1]));
}
__device__ __forceinline__ void ldsm4h(unsigned int* r, const __half* p) {
    unsigned int addr = (unsigned int)__cvta_generic_to_shared(p);
    asm volatile("ldmatrix.sync.aligned.m8n8.x4.shared.b16 {%0,%1,%2,%3}, [%4];"
                 : "=r"(r[0]), "=r"(r[1]), "=r"(r[2]), "=r"(r[3]) : "r"(addr));
}
__device__ __forceinline__ void ldsm4ht(unsigned int* r, const __half* p) {
    unsigned int addr = (unsigned int)__cvta_generic_to_shared(p);
    asm volatile("ldmatrix.sync.aligned.m8n8.x4.trans.shared.b16 {%0,%1,%2,%3}, [%4];"
                 : "=r"(r[0]), "=r"(r[1]), "=r"(r[2]), "=r"(r[3]) : "r"(addr));
}
__device__ __forceinline__ void ldsm2h(unsigned int* r, const __half* p) {
    unsigned int addr = (unsigned int)__cvta_generic_to_shared(p);
    asm volatile("ldmatrix.sync.aligned.m8n8.x2.shared.b16 {%0,%1}, [%2];"
                 : "=r"(r[0]), "=r"(r[1]) : "r"(addr));
}

// SW128 swizzled pointer within a [rows x 128 bytes] tile. halfcol multiple of 8.
__device__ __forceinline__ const __half* swp(const __half* base, int row, int halfcol) {
    unsigned int off = (unsigned int)(row * 128) +
        (((unsigned int)(halfcol * 2)) ^ (((unsigned int)row & 7u) * 16u));
    return (const __half*)((const char*)base + off);
}

// ---------------------------------------------------------------------------
// Fused weight convert: all 7 weight matrices fp32 -> fp16 in one launch.
// ---------------------------------------------------------------------------
#define NDD8 (DMODEL * DMODEL / 8)
#define NFF8 (DFF * DMODEL / 8)
#define NTOT8 (4 * NDD8 + 3 * NFF8)

__global__ __launch_bounds__(256) void convert_all_kernel(
    const float* __restrict__ s0, const float* __restrict__ s1,
    const float* __restrict__ s2, const float* __restrict__ s3,
    const float* __restrict__ s4, const float* __restrict__ s5,
    const float* __restrict__ s6,
    __half* __restrict__ d0, __half* __restrict__ d1,
    __half* __restrict__ d2, __half* __restrict__ d3,
    __half* __restrict__ d4, __half* __restrict__ d5,
    __half* __restrict__ d6)
{
    int idx = blockIdx.x * 256 + threadIdx.x;
    if (idx >= NTOT8) return;

    const float* src;
    __half* dst;
    int off;
    if (idx < 4 * NDD8) {
        int seg = idx / NDD8;
        off = idx - seg * NDD8;
        src = (seg == 0) ? s0 : (seg == 1) ? s1 : (seg == 2) ? s2 : s3;
        dst = (seg == 0) ? d0 : (seg == 1) ? d1 : (seg == 2) ? d2 : d3;
    } else {
        int r = idx - 4 * NDD8;
        int seg = r / NFF8;
        off = r - seg * NFF8;
        src = (seg == 0) ? s4 : (seg == 1) ? s5 : s6;
        dst = (seg == 0) ? d4 : (seg == 1) ? d5 : d6;
    }

    float4 v0 = *(const float4*)(src + (size_t)off * 8);
    float4 v1 = *(const float4*)(src + (size_t)off * 8 + 4);
    __half2 h[4];
    h[0] = __floats2half2_rn(v0.x, v0.y);
    h[1] = __floats2half2_rn(v0.z, v0.w);
    h[2] = __floats2half2_rn(v1.x, v1.y);
    h[3] = __floats2half2_rn(v1.z, v1.w);
    *(uint4*)(dst + (size_t)off * 8) = *(uint4*)h;
}

// ---------------------------------------------------------------------------
// RMSNorm: fp32 in -> fp16 out.
// ---------------------------------------------------------------------------
__global__ __launch_bounds__(256) void rmsnorm_kernel(
    const float* __restrict__ x, const float* __restrict__ g,
    __half* __restrict__ y)
{
    const int row = blockIdx.x;
    const int tid = threadIdx.x;
    const float* xr = x + (size_t)row * DMODEL;

    float4 v = *(const float4*)(xr + tid * 4);
    float ss = v.x * v.x + v.y * v.y + v.z * v.z + v.w * v.w;

    #pragma unroll
    for (int off = 16; off; off >>= 1)
        ss += __shfl_xor_sync(0xffffffffu, ss, off);

    __shared__ float red[8];
    const int lane = tid & 31, warp = tid >> 5;
    if (lane == 0) red[warp] = ss;
    __syncthreads();
    if (warp == 0) {
        float t = (lane < 8) ? red[lane] : 0.0f;
        #pragma unroll
        for (int off = 4; off; off >>= 1)
            t += __shfl_xor_sync(0xffffffffu, t, off);
        if (lane == 0) red[0] = t;
    }
    __syncthreads();

    const float inv = rsqrtf(red[0] * (1.0f / DMODEL) + 1e-5f);
    float4 gv = *(const float4*)(g + tid * 4);
    __half2 h0 = __floats2half2_rn(v.x * inv * gv.x, v.y * inv * gv.y);
    __half2 h1 = __floats2half2_rn(v.z * inv * gv.z, v.w * inv * gv.w);
    __half* yp = y + (size_t)row * DMODEL + tid * 4;
    *(__half2*)(yp)     = h0;
    *(__half2*)(yp + 2) = h1;
}

// ---------------------------------------------------------------------------
// FP16 tensor-core GEMM (unchanged from R7)
// ---------------------------------------------------------------------------
#define GF_STAGE_H (128 * 64)
#define GF_SMEM (6 * GF_STAGE_H * 2)

template <int MODE>
__global__ __launch_bounds__(256) void gemm_f16(
    const __half* __restrict__ A,
    const __half* __restrict__ B0, const __half* __restrict__ B1, const __half* __restrict__ B2,
    const float* __restrict__ R,
    void* __restrict__ C0v, void* __restrict__ C1v, void* __restrict__ C2v,
    int M, int N, int K)
{
    extern __shared__ __half smh[];
    __half* As = smh;
    __half* Bs = smh + 3 * GF_STAGE_H;

    const int z = blockIdx.z;
    const __half* B = (z == 0) ? B0 : (z == 1) ? B1 : B2;
    void*         Cv = (z == 0) ? C0v : (z == 1) ? C1v : C2v;

    const int tid  = threadIdx.x;
    const int lane = tid & 31, warp = tid >> 5;
    const int g = lane >> 2, t4 = lane & 3;
    const int wm = warp >> 2, wn = warp & 3;
    const int bm = blockIdx.y, bn = blockIdx.x;

    const int lr = lane & 15;
    const int lc = (lane >> 4) << 3;
    const int br = lane & 7;
    const int bc = ((lane >> 3) & 1) << 3;

    const __half* Ab = A + (size_t)bm * 128 * K;
    const __half* Bb = B + (size_t)bn * 128 * K;

    float acc[4][4][4];
    #pragma unroll
    for (int i = 0; i < 4; ++i)
        #pragma unroll
        for (int j = 0; j < 4; ++j)
            #pragma unroll
            for (int r = 0; r < 4; ++r) acc[i][j][r] = 0.0f;

    const int T = K >> 6;

    auto load_tile = [&](int kt, int st) {
        const __half* Asrc = Ab + kt * 64;
        const __half* Bsrc = Bb + kt * 64;
        __half* Adst = As + st * GF_STAGE_H;
        __half* Bdst = Bs + st * GF_STAGE_H;
        #pragma unroll
        for (int e = 0; e < 4; ++e) {
            int id  = e * 256 + tid;
            int row = id >> 3;
            int c16 = id & 7;
            unsigned int sw = (unsigned int)(row * 128) + (((unsigned int)c16 ^ ((unsigned int)row & 7u)) * 16u);
            unsigned int sa = (unsigned int)__cvta_generic_to_shared((const char*)Adst + sw);
            asm volatile("cp.async.cg.shared.global [%0], [%1], 16;\n"
                         :: "r"(sa), "l"(Asrc + (size_t)row * K + c16 * 8));
            unsigned int sb = (unsigned int)__cvta_generic_to_shared((const char*)Bdst + sw);
            asm volatile("cp.async.cg.shared.global [%0], [%1], 16;\n"
                         :: "r"(sb), "l"(Bsrc + (size_t)row * K + c16 * 8));
        }
        asm volatile("cp.async.commit_group;\n");
    };

    load_tile(0, 0);
    load_tile(1, 1);

    for (int kt = 0; kt < T; ++kt) {
        if (kt + 2 < T) {
            load_tile(kt + 2, (kt + 2) % 3);
            asm volatile("cp.async.wait_group 2;\n");
        } else if (kt + 1 < T) {
            asm volatile("cp.async.wait_group 1;\n");
        } else {
            asm volatile("cp.async.wait_group 0;\n");
        }
        __syncthreads();

        const __half* Asb = As + (kt % 3) * GF_STAGE_H;
        const __half* Bsb = Bs + (kt % 3) * GF_STAGE_H;

        #pragma unroll
        for (int ks = 0; ks < 4; ++ks) {
            const int k0 = ks * 16;
            unsigned int af[4][4], bf[4][2];
            #pragma unroll
            for (int i = 0; i < 4; ++i)
                ldsm4h(af[i], swp(Asb, wm * 64 + i * 16 + lr, k0 + lc));
            #pragma unroll
            for (int j = 0; j < 4; ++j)
                ldsm2h(bf[j], swp(Bsb, wn * 32 + j * 8 + br, k0 + bc));
            #pragma unroll
            for (int i = 0; i < 4; ++i)
                #pragma unroll
                for (int j = 0; j < 4; ++j)
                    mma_f16(acc[i][j], af[i], bf[j]);
        }
        __syncthreads();
    }

    #pragma unroll
    for (int i = 0; i < 4; ++i) {
        const int r0 = bm * 128 + wm * 64 + i * 16 + g;
        #pragma unroll
        for (int j = 0; j < 4; ++j) {
            const int c0 = bn * 128 + wn * 32 + j * 8 + 2 * t4;
            if (MODE == 1) {
                float* C = (float*)Cv;
                float2 rr0 = *(const float2*)(R + (size_t)r0 * N + c0);
                float2 rr1 = *(const float2*)(R + (size_t)(r0 + 8) * N + c0);
                *(float2*)(C + (size_t)r0 * N + c0) =
                    make_float2(acc[i][j][0] + rr0.x, acc[i][j][1] + rr0.y);
                *(float2*)(C + (size_t)(r0 + 8) * N + c0) =
                    make_float2(acc[i][j][2] + rr1.x, acc[i][j][3] + rr1.y);
            } else {
                __half* C = (__half*)Cv;
                *(__half2*)(C + (size_t)r0 * N + c0) =
                    __floats2half2_rn(acc[i][j][0], acc[i][j][1]);
                *(__half2*)(C + (size_t)(r0 + 8) * N + c0) =
                    __floats2half2_rn(acc[i][j][2], acc[i][j][3]);
            }
        }
    }
}

// ---------------------------------------------------------------------------
// Flash attention v2: 128q block, 8 warps, warp tile 16q x 64k.
// S/P register-resident; softmax via quad shuffles; V loaded row-major with
// ldmatrix.trans; K/V double-buffered cp.async. Grid: (S/128, B*H).
// ---------------------------------------------------------------------------
#define FA_Q_BYTES (128 * 128)           // Q tile: 128 rows x 128B (swizzled)
#define FA_KV_BYTES (64 * 128)           // one K or V buffer
#define FA_SMEM_BYTES (FA_Q_BYTES + 4 * FA_KV_BYTES)   // 49152

__global__ __launch_bounds__(256) void flash_attn_kernel(
    const __half* __restrict__ Q, const __half* __restrict__ K,
    const __half* __restrict__ V, __half* __restrict__ O)
{
    extern __shared__ char smraw[];
    __half* Qs = (__half*)smraw;
    // K buffers at +16384, +24576; V buffers at +32768, +40960

    const int tid  = threadIdx.x;
    const int lane = tid & 31, w = tid >> 5;
    const int g = lane >> 2, t4 = lane & 3;
    const int lr = lane & 15;
    const int lc = (lane >> 4) << 3;

    const int qb = (int)gridDim.x - 1 - (int)blockIdx.x;   // big tiles first
    const int bh = blockIdx.y;
    const int b = bh >> 4, h = bh & 15;

    const size_t base = ((size_t)b * SEQ) * DMODEL + h * DHEAD;
    const __half* Qg = Q + base + (size_t)(qb * 128) * DMODEL;
    const __half* Kg = K + base;
    const __half* Vg = V + base;

    // ---- load Q tile (128 rows x 64 halfs, swizzled) ----
    #pragma unroll
    for (int e = 0; e < 4; ++e) {
        int id  = e * 256 + tid;      // 0..1023
        int row = id >> 3;            // 0..127
        int c16 = id & 7;
        unsigned int sw = (unsigned int)(row * 128) + (((unsigned int)c16 ^ ((unsigned int)row & 7u)) * 16u);
        unsigned int sa = (unsigned int)__cvta_generic_to_shared(smraw + sw);
        asm volatile("cp.async.cg.shared.global [%0], [%1], 16;\n"
                     :: "r"(sa), "l"(Qg + (size_t)row * DMODEL + c16 * 8));
    }
    asm volatile("cp.async.commit_group;\n");

    auto load_kv = [&](int t, int buf) {
        const __half* Ksrc = Kg + (size_t)(t * 64) * DMODEL;
        const __half* Vsrc = Vg + (size_t)(t * 64) * DMODEL;
        char* Kdst = smraw + FA_Q_BYTES + buf * FA_KV_BYTES;
        char* Vdst = smraw + FA_Q_BYTES + 2 * FA_KV_BYTES + buf * FA_KV_BYTES;
        #pragma unroll
        for (int e = 0; e < 2; ++e) {
            int id  = e * 256 + tid;   // 0..511
            int row = id >> 3;         // 0..63
            int c16 = id & 7;
            unsigned int sw = (unsigned int)(row * 128) + (((unsigned int)c16 ^ ((unsigned int)row & 7u)) * 16u);
            unsigned int sk = (unsigned int)__cvta_generic_to_shared(Kdst + sw);
            asm volatile("cp.async.cg.shared.global [%0], [%1], 16;\n"
                         :: "r"(sk), "l"(Ksrc + (size_t)row * DMODEL + c16 * 8));
            unsigned int sv = (unsigned int)__cvta_generic_to_shared(Vdst + sw);
            asm volatile("cp.async.cg.shared.global [%0], [%1], 16;\n"
                         :: "r"(sv), "l"(Vsrc + (size_t)row * DMODEL + c16 * 8));
        }
        asm volatile("cp.async.commit_group;\n");
    };

    load_kv(0, 0);

    // wait for Q, then load Q fragments (held in registers)
    asm volatile("cp.async.wait_group 1;\n");
    __syncthreads();

    unsigned int aq[4][4];
    #pragma unroll
    for (int dt = 0; dt < 4; ++dt)
        ldsm4h(aq[dt], swp(Qs, 16 * w + lr, dt * 16 + lc));

    float o_acc[8][4];
    #pragma unroll
    for (int j = 0; j < 8; ++j)
        #pragma unroll
        for (int r = 0; r < 4; ++r) o_acc[j][r] = 0.0f;

    float m0 = -INFINITY, m1 = -INFINITY, l0 = 0.0f, l1 = 0.0f;

    const int T = 2 * qb + 2;

    for (int t = 0; t < T; ++t) {
        if (t + 1 < T) {
            load_kv(t + 1, (t + 1) & 1);
            asm volatile("cp.async.wait_group 1;\n");
        } else {
            asm volatile("cp.async.wait_group 0;\n");
        }
        __syncthreads();

        // warp-level skip: all q rows of this warp < all keys of this tile
        const bool skip = (16 * w + 15) < (64 * t - 128 * qb);
        if (!skip) {
            const __half* Ksb = (const __half*)(smraw + FA_Q_BYTES + (t & 1) * FA_KV_BYTES);
            const __half* Vsb = (const __half*)(smraw + FA_Q_BYTES + 2 * FA_KV_BYTES + (t & 1) * FA_KV_BYTES);

            // ---- S = Q K^T ----
            float s[8][4];
            #pragma unroll
            for (int j = 0; j < 8; ++j)
                #pragma unroll
                for (int r = 0; r < 4; ++r) s[j][r] = 0.0f;

            const int sft = lane >> 3;   // 0..3
            #pragma unroll
            for (int dt = 0; dt < 4; ++dt) {
                #pragma unroll
                for (int jp = 0; jp < 4; ++jp) {
                    unsigned int bk[4];
                    ldsm4h(bk, swp(Ksb, 8 * (2 * jp + (sft >> 1)) + (lane & 7),
                                   dt * 16 + ((sft & 1) << 3)));
                    mma_f16(s[2 * jp],     aq[dt], bk);
                    mma_f16(s[2 * jp + 1], aq[dt], bk + 2);
                }
            }

            // scale
            #pragma unroll
            for (int j = 0; j < 8; ++j)
                #pragma unroll
                for (int r = 0; r < 4; ++r) s[j][r] *= 0.125f;

            // causal mask (only last two tiles can intersect the diagonal)
            if (t >= 2 * qb) {
                const int q0r = 128 * qb + 16 * w + g;
                #pragma unroll
                for (int j = 0; j < 8; ++j) {
                    const int kk = 64 * t + 8 * j + 2 * t4;
                    if (kk     > q0r)     s[j][0] = -INFINITY;
                    if (kk + 1 > q0r)     s[j][1] = -INFINITY;
                    if (kk     > q0r + 8) s[j][2] = -INFINITY;
                    if (kk + 1 > q0r + 8) s[j][3] = -INFINITY;
                }
            }

            // ---- online softmax (registers + quad shuffles) ----
            float mt0 = -INFINITY, mt1 = -INFINITY;
            #pragma unroll
            for (int j = 0; j < 8; ++j) {
                mt0 = fmaxf(mt0, fmaxf(s[j][0], s[j][1]));
                mt1 = fmaxf(mt1, fmaxf(s[j][2], s[j][3]));
            }
            mt0 = fmaxf(mt0, __shfl_xor_sync(0xffffffffu, mt0, 1));
            mt0 = fmaxf(mt0, __shfl_xor_sync(0xffffffffu, mt0, 2));
            mt1 = fmaxf(mt1, __shfl_xor_sync(0xffffffffu, mt1, 1));
            mt1 = fmaxf(mt1, __shfl_xor_sync(0xffffffffu, mt1, 2));

            const float mn0 = fmaxf(m0, mt0);
            const float mn1 = fmaxf(m1, mt1);
            const float sc0 = __expf(m0 - mn0);
            const float sc1 = __expf(m1 - mn1);

            float sum0 = 0.0f, sum1 = 0.0f;
            unsigned int ap[4][4];
            #pragma unroll
            for (int j = 0; j < 8; ++j) {
                float p0 = __expf(s[j][0] - mn0);
                float p1 = __expf(s[j][1] - mn0);
                float p2 = __expf(s[j][2] - mn1);
                float p3 = __expf(s[j][3] - mn1);
                sum0 += p0 + p1;
                sum1 += p2 + p3;
                __half2 h01 = __floats2half2_rn(p0, p1);
                __half2 h23 = __floats2half2_rn(p2, p3);
                const int kt = j >> 1;
                if ((j & 1) == 0) {
                    ap[kt][0] = *(unsigned int*)&h01;
                    ap[kt][1] = *(unsigned int*)&h23;
                } else {
                    ap[kt][2] = *(unsigned int*)&h01;
                    ap[kt][3] = *(unsigned int*)&h23;
                }
            }
            sum0 += __shfl_xor_sync(0xffffffffu, sum0, 1);
            sum0 += __shfl_xor_sync(0xffffffffu, sum0, 2);
            sum1 += __shfl_xor_sync(0xffffffffu, sum1, 1);
            sum1 += __shfl_xor_sync(0xffffffffu, sum1, 2);

            l0 = l0 * sc0 + sum0;
            l1 = l1 * sc1 + sum1;
            m0 = mn0;
            m1 = mn1;

            #pragma unroll
            for (int j = 0; j < 8; ++j) {
                o_acc[j][0] *= sc0; o_acc[j][1] *= sc0;
                o_acc[j][2] *= sc1; o_acc[j][3] *= sc1;
            }

            // ---- O += P V (V row-major, trans ldmatrix) ----
            #pragma unroll
            for (int kt = 0; kt < 4; ++kt) {
                #pragma unroll
                for (int jp = 0; jp < 4; ++jp) {
                    unsigned int bv[4];
                    ldsm4ht(bv, swp(Vsb, 16 * kt + ((sft & 1) << 3) + (lane & 7),
                                    16 * jp + ((sft >> 1) << 3)));
                    mma_f16(o_acc[2 * jp],     ap[kt], bv);
                    mma_f16(o_acc[2 * jp + 1], ap[kt], bv + 2);
                }
            }
        }
        __syncthreads();
    }

    // ---- finalize + store ----
    const float inv0 = 1.0f / l0;
    const float inv1 = 1.0f / l1;
    __half* Og = O + base + (size_t)(qb * 128 + 16 * w) * DMODEL;
    #pragma unroll
    for (int j = 0; j < 8; ++j) {
        const int d = 8 * j + 2 * t4;
        *(__half2*)(Og + (size_t)g * DMODEL + d) =
            __floats2half2_rn(o_acc[j][0] * inv0, o_acc[j][1] * inv0);
        *(__half2*)(Og + (size_t)(g + 8) * DMODEL + d) =
            __floats2half2_rn(o_acc[j][2] * inv1, o_acc[j][3] * inv1);
    }
}

// ---------------------------------------------------------------------------
// SwiGLU combine: a = h16(silu(a) * c)
// ---------------------------------------------------------------------------
__global__ __launch_bounds__(256) void swiglu_kernel(
    __half* __restrict__ a, const __half* __restrict__ c, int n8)
{
    int idx = blockIdx.x * blockDim.x + threadIdx.x;
    if (idx >= n8) return;
    uint4 au = *(const uint4*)(a + (size_t)idx * 8);
    uint4 cu = *(const uint4*)(c + (size_t)idx * 8);
    const __half2* ah = (const __half2*)&au;
    const __half2* ch = (const __half2*)&cu;
    __half2 oh[4];
    #pragma unroll
    for (int i = 0; i < 4; ++i) {
        float2 af = __half22float2(ah[i]);
        float2 cf = __half22float2(ch[i]);
        float ox = af.x * (1.0f / (1.0f + __expf(-af.x))) * cf.x;
        float oy = af.y * (1.0f / (1.0f + __expf(-af.y))) * cf.y;
        oh[i] = __floats2half2_rn(ox, oy);
    }
    *(uint4*)(a + (size_t)idx * 8) = *(uint4*)oh;
}

// ---------------------------------------------------------------------------
// Launch
// ---------------------------------------------------------------------------
extern "C" void kernel_launch(void* const* d_in, const int* in_sizes, int n_in,
                              void* d_out, int out_size)
{
    const float* x  = (const float*)d_in[0];
    const float* Wq = (const float*)d_in[1];
    const float* Wk = (const float*)d_in[2];
    const float* Wv = (const float*)d_in[3];
    const float* Wo = (const float*)d_in[4];
    const float* W1 = (const float*)d_in[5];
    const float* W2 = (const float*)d_in[6];
    const float* W3 = (const float*)d_in[7];
    const float* g1 = (const float*)d_in[8];
    const float* g2 = (const float*)d_in[9];
    float* out = (float*)d_out;

    __half *h1, *q, *k, *v, *o, *a, *c;
    __half *wq, *wk, *wv, *wo, *w1, *w2, *w3;
    float *x2;
    cudaGetSymbolAddress((void**)&h1, g_h1);
    cudaGetSymbolAddress((void**)&q,  g_q);
    cudaGetSymbolAddress((void**)&k,  g_k);
    cudaGetSymbolAddress((void**)&v,  g_v);
    cudaGetSymbolAddress((void**)&o,  g_o);
    cudaGetSymbolAddress((void**)&x2, g_x2);
    cudaGetSymbolAddress((void**)&a,  g_a);
    cudaGetSymbolAddress((void**)&c,  g_c);
    cudaGetSymbolAddress((void**)&wq, g_wq);
    cudaGetSymbolAddress((void**)&wk, g_wk);
    cudaGetSymbolAddress((void**)&wv, g_wv);
    cudaGetSymbolAddress((void**)&wo, g_wo);
    cudaGetSymbolAddress((void**)&w1, g_w1);
    cudaGetSymbolAddress((void**)&w2, g_w2);
    cudaGetSymbolAddress((void**)&w3, g_w3);

    cudaFuncSetAttribute(flash_attn_kernel,
                         cudaFuncAttributeMaxDynamicSharedMemorySize, FA_SMEM_BYTES);
    cudaFuncSetAttribute(gemm_f16<0>,
                         cudaFuncAttributeMaxDynamicSharedMemorySize, GF_SMEM);
    cudaFuncSetAttribute(gemm_f16<1>,
                         cudaFuncAttributeMaxDynamicSharedMemorySize, GF_SMEM);

    // 0) convert all weights to fp16 in one launch
    convert_all_kernel<<<NTOT8 / 256, 256>>>(Wq, Wk, Wv, Wo, W1, W2, W3,
                                             wq, wk, wv, wo, w1, w2, w3);

    const dim3 gemm_qkv(DMODEL / 128, NTOK / 128, 3);
    const dim3 gemm_d_d(DMODEL / 128, NTOK / 128, 1);
    const dim3 gemm_w13(DFF / 128,    NTOK / 128, 2);

    // 1) h1 = rmsnorm(x, g1) -> fp16
    rmsnorm_kernel<<<NTOK, 256>>>(x, g1, h1);

    // 2) q,k,v = h1 @ W{q,k,v}^T
    gemm_f16<0><<<gemm_qkv, 256, GF_SMEM>>>(h1, wq, wk, wv, nullptr,
                                            q, k, v, NTOK, DMODEL, DMODEL);

    // 3) o = causal_attention(q, k, v)
    dim3 fa_grid(SEQ / 128, BATCH * NHEADS);
    flash_attn_kernel<<<fa_grid, 256, FA_SMEM_BYTES>>>(q, k, v, o);

    // 4) x2 = x + o @ Wo^T (fp32 out)
    gemm_f16<1><<<gemm_d_d, 256, GF_SMEM>>>(o, wo, wo, wo, x,
                                            x2, x2, x2, NTOK, DMODEL, DMODEL);

    // 5) h2 = rmsnorm(x2, g2) -> fp16
    rmsnorm_kernel<<<NTOK, 256>>>(x2, g2, h1);

    // 6) a = h2 @ W1^T, c = h2 @ W3^T
    gemm_f16<0><<<gemm_w13, 256, GF_SMEM>>>(h1, w1, w3, w3, nullptr,
                                            a, c, c, NTOK, DFF, DMODEL);

    // 7) a = silu(a) * c
    int n8 = NTOK * DFF / 8;
    swiglu_kernel<<<n8 / 256, 256>>>(a, c, n8);

    // 8) out = x2 + a @ W2^T (fp32 out)
    gemm_f16<1><<<gemm_d_d, 256, GF_SMEM>>>(a, w2, w2, w2, x2,
                                            out, out, out, NTOK, DMODEL, DFF);
}

// round 9
// speedup vs baseline: 7.8036x; 1.1660x over previous
#include <cuda_runtime.h>
#include <cuda_fp16.h>
#include <stdint.h>
#include <math.h>

// Problem constants
#define BATCH 2
#define SEQ 2048
#define DMODEL 1024
#define NHEADS 16
#define DHEAD 64
#define DFF 4096
#define NTOK (BATCH * SEQ)   // 4096

// ---------------------------------------------------------------------------
// Scratch (device globals; allocation is forbidden)
// ---------------------------------------------------------------------------
__device__ __half g_h1[NTOK * DMODEL];
__device__ __half g_q [NTOK * DMODEL];
__device__ __half g_k [NTOK * DMODEL];
__device__ __half g_v [NTOK * DMODEL];
__device__ __half g_o [NTOK * DMODEL];
__device__ float  g_x2[NTOK * DMODEL];
__device__ __half g_a [NTOK * DFF];
// fp16 weights
__device__ __half g_wq[DMODEL * DMODEL];
__device__ __half g_wk[DMODEL * DMODEL];
__device__ __half g_wv[DMODEL * DMODEL];
__device__ __half g_wo[DMODEL * DMODEL];
__device__ __half g_w1[DFF * DMODEL];
__device__ __half g_w2[DMODEL * DFF];
__device__ __half g_w3[DFF * DMODEL];

// ---------------------------------------------------------------------------
// mma.sync helpers
// ---------------------------------------------------------------------------
__device__ __forceinline__ void mma_f16(float* c, const unsigned int* a, const unsigned int* b) {
    asm volatile(
        "mma.sync.aligned.m16n8k16.row.col.f32.f16.f16.f32 "
        "{%0,%1,%2,%3}, {%4,%5,%6,%7}, {%8,%9}, {%0,%1,%2,%3};"
        : "+f"(c[0]), "+f"(c[1]), "+f"(c[2]), "+f"(c[3])
        : "r"(a[0]), "r"(a[1]), "r"(a[2]), "r"(a[3]), "r"(b[0]), "r"(b[1]));
}
__device__ __forceinline__ void ldsm4h(unsigned int* r, const __half* p) {
    unsigned int addr = (unsigned int)__cvta_generic_to_shared(p);
    asm volatile("ldmatrix.sync.aligned.m8n8.x4.shared.b16 {%0,%1,%2,%3}, [%4];"
                 : "=r"(r[0]), "=r"(r[1]), "=r"(r[2]), "=r"(r[3]) : "r"(addr));
}
__device__ __forceinline__ void ldsm4ht(unsigned int* r, const __half* p) {
    unsigned int addr = (unsigned int)__cvta_generic_to_shared(p);
    asm volatile("ldmatrix.sync.aligned.m8n8.x4.trans.shared.b16 {%0,%1,%2,%3}, [%4];"
                 : "=r"(r[0]), "=r"(r[1]), "=r"(r[2]), "=r"(r[3]) : "r"(addr));
}

// SW128 swizzled pointer within a [rows x 128 bytes] tile. halfcol multiple of 8.
__device__ __forceinline__ const __half* swp(const __half* base, int row, int halfcol) {
    unsigned int off = (unsigned int)(row * 128) +
        (((unsigned int)(halfcol * 2)) ^ (((unsigned int)row & 7u) * 16u));
    return (const __half*)((const char*)base + off);
}

// ---------------------------------------------------------------------------
// Fused weight convert: all 7 weight matrices fp32 -> fp16 in one launch.
// ---------------------------------------------------------------------------
#define NDD8 (DMODEL * DMODEL / 8)
#define NFF8 (DFF * DMODEL / 8)
#define NTOT8 (4 * NDD8 + 3 * NFF8)

__global__ __launch_bounds__(256) void convert_all_kernel(
    const float* __restrict__ s0, const float* __restrict__ s1,
    const float* __restrict__ s2, const float* __restrict__ s3,
    const float* __restrict__ s4, const float* __restrict__ s5,
    const float* __restrict__ s6,
    __half* __restrict__ d0, __half* __restrict__ d1,
    __half* __restrict__ d2, __half* __restrict__ d3,
    __half* __restrict__ d4, __half* __restrict__ d5,
    __half* __restrict__ d6)
{
    int idx = blockIdx.x * 256 + threadIdx.x;
    if (idx >= NTOT8) return;

    const float* src;
    __half* dst;
    int off;
    if (idx < 4 * NDD8) {
        int seg = idx / NDD8;
        off = idx - seg * NDD8;
        src = (seg == 0) ? s0 : (seg == 1) ? s1 : (seg == 2) ? s2 : s3;
        dst = (seg == 0) ? d0 : (seg == 1) ? d1 : (seg == 2) ? d2 : d3;
    } else {
        int r = idx - 4 * NDD8;
        int seg = r / NFF8;
        off = r - seg * NFF8;
        src = (seg == 0) ? s4 : (seg == 1) ? s5 : s6;
        dst = (seg == 0) ? d4 : (seg == 1) ? d5 : d6;
    }

    float4 v0 = *(const float4*)(src + (size_t)off * 8);
    float4 v1 = *(const float4*)(src + (size_t)off * 8 + 4);
    __half2 h[4];
    h[0] = __floats2half2_rn(v0.x, v0.y);
    h[1] = __floats2half2_rn(v0.z, v0.w);
    h[2] = __floats2half2_rn(v1.x, v1.y);
    h[3] = __floats2half2_rn(v1.z, v1.w);
    *(uint4*)(dst + (size_t)off * 8) = *(uint4*)h;
}

// ---------------------------------------------------------------------------
// RMSNorm: fp32 in -> fp16 out.
// ---------------------------------------------------------------------------
__global__ __launch_bounds__(256) void rmsnorm_kernel(
    const float* __restrict__ x, const float* __restrict__ g,
    __half* __restrict__ y)
{
    const int row = blockIdx.x;
    const int tid = threadIdx.x;
    const float* xr = x + (size_t)row * DMODEL;

    float4 v = *(const float4*)(xr + tid * 4);
    float ss = v.x * v.x + v.y * v.y + v.z * v.z + v.w * v.w;

    #pragma unroll
    for (int off = 16; off; off >>= 1)
        ss += __shfl_xor_sync(0xffffffffu, ss, off);

    __shared__ float red[8];
    const int lane = tid & 31, warp = tid >> 5;
    if (lane == 0) red[warp] = ss;
    __syncthreads();
    if (warp == 0) {
        float t = (lane < 8) ? red[lane] : 0.0f;
        #pragma unroll
        for (int off = 4; off; off >>= 1)
            t += __shfl_xor_sync(0xffffffffu, t, off);
        if (lane == 0) red[0] = t;
    }
    __syncthreads();

    const float inv = rsqrtf(red[0] * (1.0f / DMODEL) + 1e-5f);
    float4 gv = *(const float4*)(g + tid * 4);
    __half2 h0 = __floats2half2_rn(v.x * inv * gv.x, v.y * inv * gv.y);
    __half2 h1 = __floats2half2_rn(v.z * inv * gv.z, v.w * inv * gv.w);
    __half* yp = y + (size_t)row * DMODEL + tid * 4;
    *(__half2*)(yp)     = h0;
    *(__half2*)(yp + 2) = h1;
}

// ---------------------------------------------------------------------------
// FP16 tensor-core GEMM: C[M,N] = A[M,K] * B[N,K]^T (+ float R if MODE==1)
// BM=BN=128, BK=64 (128B rows, SW128), 8 warps 2x4, warp tile 64x32,
// B fragments via ldsm4 (16 rows/op), 3-stage cp.async pipeline.
// ---------------------------------------------------------------------------
#define GF_STAGE_H (128 * 64)
#define GF_SMEM (6 * GF_STAGE_H * 2)

template <int MODE>
__global__ __launch_bounds__(256) void gemm_f16(
    const __half* __restrict__ A,
    const __half* __restrict__ B0, const __half* __restrict__ B1, const __half* __restrict__ B2,
    const float* __restrict__ R,
    void* __restrict__ C0v, void* __restrict__ C1v, void* __restrict__ C2v,
    int M, int N, int K)
{
    extern __shared__ __half smh[];
    __half* As = smh;
    __half* Bs = smh + 3 * GF_STAGE_H;

    const int z = blockIdx.z;
    const __half* B = (z == 0) ? B0 : (z == 1) ? B1 : B2;
    void*         Cv = (z == 0) ? C0v : (z == 1) ? C1v : C2v;

    const int tid  = threadIdx.x;
    const int lane = tid & 31, warp = tid >> 5;
    const int g = lane >> 2, t4 = lane & 3;
    const int wm = warp >> 2, wn = warp & 3;
    const int bm = blockIdx.y, bn = blockIdx.x;

    const int lr = lane & 15;
    const int lc = (lane >> 4) << 3;
    const int sft = lane >> 3;          // 0..3 quadrant for B ldsm4

    const __half* Ab = A + (size_t)bm * 128 * K;
    const __half* Bb = B + (size_t)bn * 128 * K;

    float acc[4][4][4];
    #pragma unroll
    for (int i = 0; i < 4; ++i)
        #pragma unroll
        for (int j = 0; j < 4; ++j)
            #pragma unroll
            for (int r = 0; r < 4; ++r) acc[i][j][r] = 0.0f;

    const int T = K >> 6;

    auto load_tile = [&](int kt, int st) {
        const __half* Asrc = Ab + kt * 64;
        const __half* Bsrc = Bb + kt * 64;
        __half* Adst = As + st * GF_STAGE_H;
        __half* Bdst = Bs + st * GF_STAGE_H;
        #pragma unroll
        for (int e = 0; e < 4; ++e) {
            int id  = e * 256 + tid;
            int row = id >> 3;
            int c16 = id & 7;
            unsigned int sw = (unsigned int)(row * 128) + (((unsigned int)c16 ^ ((unsigned int)row & 7u)) * 16u);
            unsigned int sa = (unsigned int)__cvta_generic_to_shared((const char*)Adst + sw);
            asm volatile("cp.async.cg.shared.global [%0], [%1], 16;\n"
                         :: "r"(sa), "l"(Asrc + (size_t)row * K + c16 * 8));
            unsigned int sb = (unsigned int)__cvta_generic_to_shared((const char*)Bdst + sw);
            asm volatile("cp.async.cg.shared.global [%0], [%1], 16;\n"
                         :: "r"(sb), "l"(Bsrc + (size_t)row * K + c16 * 8));
        }
        asm volatile("cp.async.commit_group;\n");
    };

    load_tile(0, 0);
    load_tile(1, 1);

    for (int kt = 0; kt < T; ++kt) {
        if (kt + 2 < T) {
            load_tile(kt + 2, (kt + 2) % 3);
            asm volatile("cp.async.wait_group 2;\n");
        } else if (kt + 1 < T) {
            asm volatile("cp.async.wait_group 1;\n");
        } else {
            asm volatile("cp.async.wait_group 0;\n");
        }
        __syncthreads();

        const __half* Asb = As + (kt % 3) * GF_STAGE_H;
        const __half* Bsb = Bs + (kt % 3) * GF_STAGE_H;

        #pragma unroll
        for (int ks = 0; ks < 4; ++ks) {
            const int k0 = ks * 16;
            unsigned int af[4][4], bf[2][4];
            #pragma unroll
            for (int i = 0; i < 4; ++i)
                ldsm4h(af[i], swp(Asb, wm * 64 + i * 16 + lr, k0 + lc));
            #pragma unroll
            for (int jp = 0; jp < 2; ++jp)
                ldsm4h(bf[jp], swp(Bsb, wn * 32 + 8 * (2 * jp + (sft >> 1)) + (lane & 7),
                                   k0 + ((sft & 1) << 3)));
            #pragma unroll
            for (int i = 0; i < 4; ++i)
                #pragma unroll
                for (int jp = 0; jp < 2; ++jp) {
                    mma_f16(acc[i][2 * jp],     af[i], bf[jp]);
                    mma_f16(acc[i][2 * jp + 1], af[i], bf[jp] + 2);
                }
        }
        __syncthreads();
    }

    #pragma unroll
    for (int i = 0; i < 4; ++i) {
        const int r0 = bm * 128 + wm * 64 + i * 16 + g;
        #pragma unroll
        for (int j = 0; j < 4; ++j) {
            const int c0 = bn * 128 + wn * 32 + j * 8 + 2 * t4;
            if (MODE == 1) {
                float* C = (float*)Cv;
                float2 rr0 = *(const float2*)(R + (size_t)r0 * N + c0);
                float2 rr1 = *(const float2*)(R + (size_t)(r0 + 8) * N + c0);
                *(float2*)(C + (size_t)r0 * N + c0) =
                    make_float2(acc[i][j][0] + rr0.x, acc[i][j][1] + rr0.y);
                *(float2*)(C + (size_t)(r0 + 8) * N + c0) =
                    make_float2(acc[i][j][2] + rr1.x, acc[i][j][3] + rr1.y);
            } else {
                __half* C = (__half*)Cv;
                *(__half2*)(C + (size_t)r0 * N + c0) =
                    __floats2half2_rn(acc[i][j][0], acc[i][j][1]);
                *(__half2*)(C + (size_t)(r0 + 8) * N + c0) =
                    __floats2half2_rn(acc[i][j][2], acc[i][j][3]);
            }
        }
    }
}

// ---------------------------------------------------------------------------
// Fused W1/W3/SwiGLU GEMM: out[M, DFF] = silu(A W1^T) * (A W3^T)
// CTA tile 128M x 64N; 8 warps as 4m x 2n, warp tile 32x32; two accumulator
// sets; 3-stage cp.async (A + B1 + B3 = 96KB). Grid: (DFF/64, NTOK/128).
// ---------------------------------------------------------------------------
#define GS_A_H (128 * 64)
#define GS_B_H (64 * 64)
#define GS_SMEM ((3 * GS_A_H + 6 * GS_B_H) * 2)   // 98304 bytes

__global__ __launch_bounds__(256) void gemm_swiglu(
    const __half* __restrict__ A,
    const __half* __restrict__ W1p, const __half* __restrict__ W3p,
    __half* __restrict__ Out, int K)
{
    extern __shared__ __half smh[];
    __half* As  = smh;                      // 3 x 8192 halfs
    __half* B1s = smh + 3 * GS_A_H;         // 3 x 4096
    __half* B3s = B1s + 3 * GS_B_H;         // 3 x 4096

    const int tid  = threadIdx.x;
    const int lane = tid & 31, warp = tid >> 5;
    const int g = lane >> 2, t4 = lane & 3;
    const int wm = warp >> 1, wn = warp & 1;
    const int bm = blockIdx.y, bn = blockIdx.x;

    const int lr = lane & 15;
    const int lc = (lane >> 4) << 3;
    const int sft = lane >> 3;

    const __half* Ab  = A   + (size_t)bm * 128 * K;
    const __half* B1b = W1p + (size_t)bn * 64 * K;
    const __half* B3b = W3p + (size_t)bn * 64 * K;

    float acc1[2][4][4], acc3[2][4][4];
    #pragma unroll
    for (int i = 0; i < 2; ++i)
        #pragma unroll
        for (int j = 0; j < 4; ++j)
            #pragma unroll
            for (int r = 0; r < 4; ++r) { acc1[i][j][r] = 0.0f; acc3[i][j][r] = 0.0f; }

    const int T = K >> 6;

    auto load_tile = [&](int kt, int st) {
        const __half* Asrc  = Ab  + kt * 64;
        const __half* B1src = B1b + kt * 64;
        const __half* B3src = B3b + kt * 64;
        __half* Adst  = As  + st * GS_A_H;
        __half* B1dst = B1s + st * GS_B_H;
        __half* B3dst = B3s + st * GS_B_H;
        #pragma unroll
        for (int e = 0; e < 4; ++e) {      // A: 1024 chunks
            int id  = e * 256 + tid;
            int row = id >> 3;
            int c16 = id & 7;
            unsigned int sw = (unsigned int)(row * 128) + (((unsigned int)c16 ^ ((unsigned int)row & 7u)) * 16u);
            unsigned int sa = (unsigned int)__cvta_generic_to_shared((const char*)Adst + sw);
            asm volatile("cp.async.cg.shared.global [%0], [%1], 16;\n"
                         :: "r"(sa), "l"(Asrc + (size_t)row * K + c16 * 8));
        }
        #pragma unroll
        for (int e = 0; e < 2; ++e) {      // B1, B3: 512 chunks each
            int id  = e * 256 + tid;
            int row = id >> 3;             // 0..63
            int c16 = id & 7;
            unsigned int sw = (unsigned int)(row * 128) + (((unsigned int)c16 ^ ((unsigned int)row & 7u)) * 16u);
            unsigned int s1 = (unsigned int)__cvta_generic_to_shared((const char*)B1dst + sw);
            asm volatile("cp.async.cg.shared.global [%0], [%1], 16;\n"
                         :: "r"(s1), "l"(B1src + (size_t)row * K + c16 * 8));
            unsigned int s3 = (unsigned int)__cvta_generic_to_shared((const char*)B3dst + sw);
            asm volatile("cp.async.cg.shared.global [%0], [%1], 16;\n"
                         :: "r"(s3), "l"(B3src + (size_t)row * K + c16 * 8));
        }
        asm volatile("cp.async.commit_group;\n");
    };

    load_tile(0, 0);
    load_tile(1, 1);

    for (int kt = 0; kt < T; ++kt) {
        if (kt + 2 < T) {
            load_tile(kt + 2, (kt + 2) % 3);
            asm volatile("cp.async.wait_group 2;\n");
        } else if (kt + 1 < T) {
            asm volatile("cp.async.wait_group 1;\n");
        } else {
            asm volatile("cp.async.wait_group 0;\n");
        }
        __syncthreads();

        const __half* Asb  = As  + (kt % 3) * GS_A_H;
        const __half* B1sb = B1s + (kt % 3) * GS_B_H;
        const __half* B3sb = B3s + (kt % 3) * GS_B_H;

        #pragma unroll
        for (int ks = 0; ks < 4; ++ks) {
            const int k0 = ks * 16;
            unsigned int af[2][4], b1f[2][4], b3f[2][4];
            #pragma unroll
            for (int i = 0; i < 2; ++i)
                ldsm4h(af[i], swp(Asb, wm * 32 + i * 16 + lr, k0 + lc));
            #pragma unroll
            for (int jp = 0; jp < 2; ++jp) {
                const int brow = wn * 32 + 8 * (2 * jp + (sft >> 1)) + (lane & 7);
                const int bcol = k0 + ((sft & 1) << 3);
                ldsm4h(b1f[jp], swp(B1sb, brow, bcol));
                ldsm4h(b3f[jp], swp(B3sb, brow, bcol));
            }
            #pragma unroll
            for (int i = 0; i < 2; ++i)
                #pragma unroll
                for (int jp = 0; jp < 2; ++jp) {
                    mma_f16(acc1[i][2 * jp],     af[i], b1f[jp]);
                    mma_f16(acc1[i][2 * jp + 1], af[i], b1f[jp] + 2);
                    mma_f16(acc3[i][2 * jp],     af[i], b3f[jp]);
                    mma_f16(acc3[i][2 * jp + 1], af[i], b3f[jp] + 2);
                }
        }
        __syncthreads();
    }

    // epilogue: out = silu(h1) * h3, fp32 math, fp16 store
    #pragma unroll
    for (int i = 0; i < 2; ++i) {
        const int r0 = bm * 128 + wm * 32 + i * 16 + g;
        #pragma unroll
        for (int j = 0; j < 4; ++j) {
            const int c0 = bn * 64 + wn * 32 + j * 8 + 2 * t4;
            float o0 = acc1[i][j][0] * (1.0f / (1.0f + __expf(-acc1[i][j][0]))) * acc3[i][j][0];
            float o1 = acc1[i][j][1] * (1.0f / (1.0f + __expf(-acc1[i][j][1]))) * acc3[i][j][1];
            float o2 = acc1[i][j][2] * (1.0f / (1.0f + __expf(-acc1[i][j][2]))) * acc3[i][j][2];
            float o3 = acc1[i][j][3] * (1.0f / (1.0f + __expf(-acc1[i][j][3]))) * acc3[i][j][3];
            *(__half2*)(Out + (size_t)r0 * DFF + c0)       = __floats2half2_rn(o0, o1);
            *(__half2*)(Out + (size_t)(r0 + 8) * DFF + c0) = __floats2half2_rn(o2, o3);
        }
    }
}

// ---------------------------------------------------------------------------
// Flash attention v2 (unchanged from R8). Grid: (S/128, B*H).
// ---------------------------------------------------------------------------
#define FA_Q_BYTES (128 * 128)
#define FA_KV_BYTES (64 * 128)
#define FA_SMEM_BYTES (FA_Q_BYTES + 4 * FA_KV_BYTES)

__global__ __launch_bounds__(256) void flash_attn_kernel(
    const __half* __restrict__ Q, const __half* __restrict__ K,
    const __half* __restrict__ V, __half* __restrict__ O)
{
    extern __shared__ char smraw[];
    __half* Qs = (__half*)smraw;

    const int tid  = threadIdx.x;
    const int lane = tid & 31, w = tid >> 5;
    const int g = lane >> 2, t4 = lane & 3;
    const int lr = lane & 15;
    const int lc = (lane >> 4) << 3;

    const int qb = (int)gridDim.x - 1 - (int)blockIdx.x;
    const int bh = blockIdx.y;
    const int b = bh >> 4, h = bh & 15;

    const size_t base = ((size_t)b * SEQ) * DMODEL + h * DHEAD;
    const __half* Qg = Q + base + (size_t)(qb * 128) * DMODEL;
    const __half* Kg = K + base;
    const __half* Vg = V + base;

    #pragma unroll
    for (int e = 0; e < 4; ++e) {
        int id  = e * 256 + tid;
        int row = id >> 3;
        int c16 = id & 7;
        unsigned int sw = (unsigned int)(row * 128) + (((unsigned int)c16 ^ ((unsigned int)row & 7u)) * 16u);
        unsigned int sa = (unsigned int)__cvta_generic_to_shared(smraw + sw);
        asm volatile("cp.async.cg.shared.global [%0], [%1], 16;\n"
                     :: "r"(sa), "l"(Qg + (size_t)row * DMODEL + c16 * 8));
    }
    asm volatile("cp.async.commit_group;\n");

    auto load_kv = [&](int t, int buf) {
        const __half* Ksrc = Kg + (size_t)(t * 64) * DMODEL;
        const __half* Vsrc = Vg + (size_t)(t * 64) * DMODEL;
        char* Kdst = smraw + FA_Q_BYTES + buf * FA_KV_BYTES;
        char* Vdst = smraw + FA_Q_BYTES + 2 * FA_KV_BYTES + buf * FA_KV_BYTES;
        #pragma unroll
        for (int e = 0; e < 2; ++e) {
            int id  = e * 256 + tid;
            int row = id >> 3;
            int c16 = id & 7;
            unsigned int sw = (unsigned int)(row * 128) + (((unsigned int)c16 ^ ((unsigned int)row & 7u)) * 16u);
            unsigned int sk = (unsigned int)__cvta_generic_to_shared(Kdst + sw);
            asm volatile("cp.async.cg.shared.global [%0], [%1], 16;\n"
                         :: "r"(sk), "l"(Ksrc + (size_t)row * DMODEL + c16 * 8));
            unsigned int sv = (unsigned int)__cvta_generic_to_shared(Vdst + sw);
            asm volatile("cp.async.cg.shared.global [%0], [%1], 16;\n"
                         :: "r"(sv), "l"(Vsrc + (size_t)row * DMODEL + c16 * 8));
        }
        asm volatile("cp.async.commit_group;\n");
    };

    load_kv(0, 0);

    asm volatile("cp.async.wait_group 1;\n");
    __syncthreads();

    unsigned int aq[4][4];
    #pragma unroll
    for (int dt = 0; dt < 4; ++dt)
        ldsm4h(aq[dt], swp(Qs, 16 * w + lr, dt * 16 + lc));

    float o_acc[8][4];
    #pragma unroll
    for (int j = 0; j < 8; ++j)
        #pragma unroll
        for (int r = 0; r < 4; ++r) o_acc[j][r] = 0.0f;

    float m0 = -INFINITY, m1 = -INFINITY, l0 = 0.0f, l1 = 0.0f;

    const int T = 2 * qb + 2;

    for (int t = 0; t < T; ++t) {
        if (t + 1 < T) {
            load_kv(t + 1, (t + 1) & 1);
            asm volatile("cp.async.wait_group 1;\n");
        } else {
            asm volatile("cp.async.wait_group 0;\n");
        }
        __syncthreads();

        const bool skip = (16 * w + 15) < (64 * t - 128 * qb);
        if (!skip) {
            const __half* Ksb = (const __half*)(smraw + FA_Q_BYTES + (t & 1) * FA_KV_BYTES);
            const __half* Vsb = (const __half*)(smraw + FA_Q_BYTES + 2 * FA_KV_BYTES + (t & 1) * FA_KV_BYTES);

            float s[8][4];
            #pragma unroll
            for (int j = 0; j < 8; ++j)
                #pragma unroll
                for (int r = 0; r < 4; ++r) s[j][r] = 0.0f;

            const int sft = lane >> 3;
            #pragma unroll
            for (int dt = 0; dt < 4; ++dt) {
                #pragma unroll
                for (int jp = 0; jp < 4; ++jp) {
                    unsigned int bk[4];
                    ldsm4h(bk, swp(Ksb, 8 * (2 * jp + (sft >> 1)) + (lane & 7),
                                   dt * 16 + ((sft & 1) << 3)));
                    mma_f16(s[2 * jp],     aq[dt], bk);
                    mma_f16(s[2 * jp + 1], aq[dt], bk + 2);
                }
            }

            #pragma unroll
            for (int j = 0; j < 8; ++j)
                #pragma unroll
                for (int r = 0; r < 4; ++r) s[j][r] *= 0.125f;

            if (t >= 2 * qb) {
                const int q0r = 128 * qb + 16 * w + g;
                #pragma unroll
                for (int j = 0; j < 8; ++j) {
                    const int kk = 64 * t + 8 * j + 2 * t4;
                    if (kk     > q0r)     s[j][0] = -INFINITY;
                    if (kk + 1 > q0r)     s[j][1] = -INFINITY;
                    if (kk     > q0r + 8) s[j][2] = -INFINITY;
                    if (kk + 1 > q0r + 8) s[j][3] = -INFINITY;
                }
            }

            float mt0 = -INFINITY, mt1 = -INFINITY;
            #pragma unroll
            for (int j = 0; j < 8; ++j) {
                mt0 = fmaxf(mt0, fmaxf(s[j][0], s[j][1]));
                mt1 = fmaxf(mt1, fmaxf(s[j][2], s[j][3]));
            }
            mt0 = fmaxf(mt0, __shfl_xor_sync(0xffffffffu, mt0, 1));
            mt0 = fmaxf(mt0, __shfl_xor_sync(0xffffffffu, mt0, 2));
            mt1 = fmaxf(mt1, __shfl_xor_sync(0xffffffffu, mt1, 1));
            mt1 = fmaxf(mt1, __shfl_xor_sync(0xffffffffu, mt1, 2));

            const float mn0 = fmaxf(m0, mt0);
            const float mn1 = fmaxf(m1, mt1);
            const float sc0 = __expf(m0 - mn0);
            const float sc1 = __expf(m1 - mn1);

            float sum0 = 0.0f, sum1 = 0.0f;
            unsigned int ap[4][4];
            #pragma unroll
            for (int j = 0; j < 8; ++j) {
                float p0 = __expf(s[j][0] - mn0);
                float p1 = __expf(s[j][1] - mn0);
                float p2 = __expf(s[j][2] - mn1);
                float p3 = __expf(s[j][3] - mn1);
                sum0 += p0 + p1;
                sum1 += p2 + p3;
                __half2 h01 = __floats2half2_rn(p0, p1);
                __half2 h23 = __floats2half2_rn(p2, p3);
                const int kt = j >> 1;
                if ((j & 1) == 0) {
                    ap[kt][0] = *(unsigned int*)&h01;
                    ap[kt][1] = *(unsigned int*)&h23;
                } else {
                    ap[kt][2] = *(unsigned int*)&h01;
                    ap[kt][3] = *(unsigned int*)&h23;
                }
            }
            sum0 += __shfl_xor_sync(0xffffffffu, sum0, 1);
            sum0 += __shfl_xor_sync(0xffffffffu, sum0, 2);
            sum1 += __shfl_xor_sync(0xffffffffu, sum1, 1);
            sum1 += __shfl_xor_sync(0xffffffffu, sum1, 2);

            l0 = l0 * sc0 + sum0;
            l1 = l1 * sc1 + sum1;
            m0 = mn0;
            m1 = mn1;

            #pragma unroll
            for (int j = 0; j < 8; ++j) {
                o_acc[j][0] *= sc0; o_acc[j][1] *= sc0;
                o_acc[j][2] *= sc1; o_acc[j][3] *= sc1;
            }

            #pragma unroll
            for (int kt = 0; kt < 4; ++kt) {
                #pragma unroll
                for (int jp = 0; jp < 4; ++jp) {
                    unsigned int bv[4];
                    ldsm4ht(bv, swp(Vsb, 16 * kt + ((sft & 1) << 3) + (lane & 7),
                                    16 * jp + ((sft >> 1) << 3)));
                    mma_f16(o_acc[2 * jp],     ap[kt], bv);
                    mma_f16(o_acc[2 * jp + 1], ap[kt], bv + 2);
                }
            }
        }
        __syncthreads();
    }

    const float inv0 = 1.0f / l0;
    const float inv1 = 1.0f / l1;
    __half* Og = O + base + (size_t)(qb * 128 + 16 * w) * DMODEL;
    #pragma unroll
    for (int j = 0; j < 8; ++j) {
        const int d = 8 * j + 2 * t4;
        *(__half2*)(Og + (size_t)g * DMODEL + d) =
            __floats2half2_rn(o_acc[j][0] * inv0, o_acc[j][1] * inv0);
        *(__half2*)(Og + (size_t)(g + 8) * DMODEL + d) =
            __floats2half2_rn(o_acc[j][2] * inv1, o_acc[j][3] * inv1);
    }
}

// ---------------------------------------------------------------------------
// Launch
// ---------------------------------------------------------------------------
extern "C" void kernel_launch(void* const* d_in, const int* in_sizes, int n_in,
                              void* d_out, int out_size)
{
    const float* x  = (const float*)d_in[0];
    const float* Wq = (const float*)d_in[1];
    const float* Wk = (const float*)d_in[2];
    const float* Wv = (const float*)d_in[3];
    const float* Wo = (const float*)d_in[4];
    const float* W1 = (const float*)d_in[5];
    const float* W2 = (const float*)d_in[6];
    const float* W3 = (const float*)d_in[7];
    const float* g1 = (const float*)d_in[8];
    const float* g2 = (const float*)d_in[9];
    float* out = (float*)d_out;

    __half *h1, *q, *k, *v, *o, *a;
    __half *wq, *wk, *wv, *wo, *w1, *w2, *w3;
    float *x2;
    cudaGetSymbolAddress((void**)&h1, g_h1);
    cudaGetSymbolAddress((void**)&q,  g_q);
    cudaGetSymbolAddress((void**)&k,  g_k);
    cudaGetSymbolAddress((void**)&v,  g_v);
    cudaGetSymbolAddress((void**)&o,  g_o);
    cudaGetSymbolAddress((void**)&x2, g_x2);
    cudaGetSymbolAddress((void**)&a,  g_a);
    cudaGetSymbolAddress((void**)&wq, g_wq);
    cudaGetSymbolAddress((void**)&wk, g_wk);
    cudaGetSymbolAddress((void**)&wv, g_wv);
    cudaGetSymbolAddress((void**)&wo, g_wo);
    cudaGetSymbolAddress((void**)&w1, g_w1);
    cudaGetSymbolAddress((void**)&w2, g_w2);
    cudaGetSymbolAddress((void**)&w3, g_w3);

    cudaFuncSetAttribute(flash_attn_kernel,
                         cudaFuncAttributeMaxDynamicSharedMemorySize, FA_SMEM_BYTES);
    cudaFuncSetAttribute(gemm_f16<0>,
                         cudaFuncAttributeMaxDynamicSharedMemorySize, GF_SMEM);
    cudaFuncSetAttribute(gemm_f16<1>,
                         cudaFuncAttributeMaxDynamicSharedMemorySize, GF_SMEM);
    cudaFuncSetAttribute(gemm_swiglu,
                         cudaFuncAttributeMaxDynamicSharedMemorySize, GS_SMEM);

    // 0) convert all weights to fp16 in one launch
    convert_all_kernel<<<NTOT8 / 256, 256>>>(Wq, Wk, Wv, Wo, W1, W2, W3,
                                             wq, wk, wv, wo, w1, w2, w3);

    const dim3 gemm_qkv(DMODEL / 128, NTOK / 128, 3);
    const dim3 gemm_d_d(DMODEL / 128, NTOK / 128, 1);
    const dim3 gemm_sw(DFF / 64, NTOK / 128);

    // 1) h1 = rmsnorm(x, g1) -> fp16
    rmsnorm_kernel<<<NTOK, 256>>>(x, g1, h1);

    // 2) q,k,v = h1 @ W{q,k,v}^T
    gemm_f16<0><<<gemm_qkv, 256, GF_SMEM>>>(h1, wq, wk, wv, nullptr,
                                            q, k, v, NTOK, DMODEL, DMODEL);

    // 3) o = causal_attention(q, k, v)
    dim3 fa_grid(SEQ / 128, BATCH * NHEADS);
    flash_attn_kernel<<<fa_grid, 256, FA_SMEM_BYTES>>>(q, k, v, o);

    // 4) x2 = x + o @ Wo^T (fp32 out)
    gemm_f16<1><<<gemm_d_d, 256, GF_SMEM>>>(o, wo, wo, wo, x,
                                            x2, x2, x2, NTOK, DMODEL, DMODEL);

    // 5) h2 = rmsnorm(x2, g2) -> fp16
    rmsnorm_kernel<<<NTOK, 256>>>(x2, g2, h1);

    // 6) a = silu(h2 @ W1^T) * (h2 @ W3^T)   (fused)
    gemm_swiglu<<<gemm_sw, 256, GS_SMEM>>>(h1, w1, w3, a, DMODEL);

    // 7) out = x2 + a @ W2^T (fp32 out)
    gemm_f16<1><<<gemm_d_d, 256, GF_SMEM>>>(a, w2, w2, w2, x2,
                                            out, out, out, NTOK, DMODEL, DFF);
}

// round 10
// speedup vs baseline: 7.8629x; 1.0076x over previous
#include <cuda_runtime.h>
#include <cuda_fp16.h>
#include <stdint.h>
#include <math.h>

// Problem constants
#define BATCH 2
#define SEQ 2048
#define DMODEL 1024
#define NHEADS 16
#define DHEAD 64
#define DFF 4096
#define NTOK (BATCH * SEQ)   // 4096

// ---------------------------------------------------------------------------
// Scratch (device globals; allocation is forbidden)
// ---------------------------------------------------------------------------
__device__ __half g_h1[NTOK * DMODEL];
__device__ __half g_q [NTOK * DMODEL];
__device__ __half g_k [NTOK * DMODEL];
__device__ __half g_v [NTOK * DMODEL];
__device__ __half g_o [NTOK * DMODEL];
__device__ float  g_x2[NTOK * DMODEL];
__device__ __half g_a [NTOK * DFF];
// fp16 weights
__device__ __half g_wq[DMODEL * DMODEL];
__device__ __half g_wk[DMODEL * DMODEL];
__device__ __half g_wv[DMODEL * DMODEL];
__device__ __half g_wo[DMODEL * DMODEL];
__device__ __half g_w1[DFF * DMODEL];
__device__ __half g_w2[DMODEL * DFF];
__device__ __half g_w3[DFF * DMODEL];

// ---------------------------------------------------------------------------
// mma.sync helpers
// ---------------------------------------------------------------------------
__device__ __forceinline__ void mma_f16(float* c, const unsigned int* a, const unsigned int* b) {
    asm volatile(
        "mma.sync.aligned.m16n8k16.row.col.f32.f16.f16.f32 "
        "{%0,%1,%2,%3}, {%4,%5,%6,%7}, {%8,%9}, {%0,%1,%2,%3};"
        : "+f"(c[0]), "+f"(c[1]), "+f"(c[2]), "+f"(c[3])
        : "r"(a[0]), "r"(a[1]), "r"(a[2]), "r"(a[3]), "r"(b[0]), "r"(b[1]));
}
__device__ __forceinline__ void ldsm4h(unsigned int* r, const __half* p) {
    unsigned int addr = (unsigned int)__cvta_generic_to_shared(p);
    asm volatile("ldmatrix.sync.aligned.m8n8.x4.shared.b16 {%0,%1,%2,%3}, [%4];"
                 : "=r"(r[0]), "=r"(r[1]), "=r"(r[2]), "=r"(r[3]) : "r"(addr));
}
__device__ __forceinline__ void ldsm4ht(unsigned int* r, const __half* p) {
    unsigned int addr = (unsigned int)__cvta_generic_to_shared(p);
    asm volatile("ldmatrix.sync.aligned.m8n8.x4.trans.shared.b16 {%0,%1,%2,%3}, [%4];"
                 : "=r"(r[0]), "=r"(r[1]), "=r"(r[2]), "=r"(r[3]) : "r"(addr));
}

// SW128 swizzled pointer within a [rows x 128 bytes] tile. halfcol multiple of 8.
__device__ __forceinline__ const __half* swp(const __half* base, int row, int halfcol) {
    unsigned int off = (unsigned int)(row * 128) +
        (((unsigned int)(halfcol * 2)) ^ (((unsigned int)row & 7u) * 16u));
    return (const __half*)((const char*)base + off);
}

// ---------------------------------------------------------------------------
// Fused weight convert: all 7 weight matrices fp32 -> fp16 in one launch.
// Unit = 16 floats per thread.
// ---------------------------------------------------------------------------
#define NDD16 (DMODEL * DMODEL / 16)   // 65536
#define NFF16 (DFF * DMODEL / 16)      // 262144
#define NTOT16 (4 * NDD16 + 3 * NFF16) // 1048576

__global__ __launch_bounds__(256) void convert_all_kernel(
    const float* __restrict__ s0, const float* __restrict__ s1,
    const float* __restrict__ s2, const float* __restrict__ s3,
    const float* __restrict__ s4, const float* __restrict__ s5,
    const float* __restrict__ s6,
    __half* __restrict__ d0, __half* __restrict__ d1,
    __half* __restrict__ d2, __half* __restrict__ d3,
    __half* __restrict__ d4, __half* __restrict__ d5,
    __half* __restrict__ d6)
{
    int idx = blockIdx.x * 256 + threadIdx.x;
    if (idx >= NTOT16) return;

    const float* src;
    __half* dst;
    int off;
    if (idx < 4 * NDD16) {
        int seg = idx / NDD16;
        off = idx - seg * NDD16;
        src = (seg == 0) ? s0 : (seg == 1) ? s1 : (seg == 2) ? s2 : s3;
        dst = (seg == 0) ? d0 : (seg == 1) ? d1 : (seg == 2) ? d2 : d3;
    } else {
        int r = idx - 4 * NDD16;
        int seg = r / NFF16;
        off = r - seg * NFF16;
        src = (seg == 0) ? s4 : (seg == 1) ? s5 : s6;
        dst = (seg == 0) ? d4 : (seg == 1) ? d5 : d6;
    }

    float4 v0 = *(const float4*)(src + (size_t)off * 16);
    float4 v1 = *(const float4*)(src + (size_t)off * 16 + 4);
    float4 v2 = *(const float4*)(src + (size_t)off * 16 + 8);
    float4 v3 = *(const float4*)(src + (size_t)off * 16 + 12);
    __half2 h[8];
    h[0] = __floats2half2_rn(v0.x, v0.y);
    h[1] = __floats2half2_rn(v0.z, v0.w);
    h[2] = __floats2half2_rn(v1.x, v1.y);
    h[3] = __floats2half2_rn(v1.z, v1.w);
    h[4] = __floats2half2_rn(v2.x, v2.y);
    h[5] = __floats2half2_rn(v2.z, v2.w);
    h[6] = __floats2half2_rn(v3.x, v3.y);
    h[7] = __floats2half2_rn(v3.z, v3.w);
    *(uint4*)(dst + (size_t)off * 16)     = ((uint4*)h)[0];
    *(uint4*)(dst + (size_t)off * 16 + 8) = ((uint4*)h)[1];
}

// ---------------------------------------------------------------------------
// RMSNorm: fp32 in -> fp16 out.
// ---------------------------------------------------------------------------
__global__ __launch_bounds__(256) void rmsnorm_kernel(
    const float* __restrict__ x, const float* __restrict__ g,
    __half* __restrict__ y)
{
    const int row = blockIdx.x;
    const int tid = threadIdx.x;
    const float* xr = x + (size_t)row * DMODEL;

    float4 v = *(const float4*)(xr + tid * 4);
    float ss = v.x * v.x + v.y * v.y + v.z * v.z + v.w * v.w;

    #pragma unroll
    for (int off = 16; off; off >>= 1)
        ss += __shfl_xor_sync(0xffffffffu, ss, off);

    __shared__ float red[8];
    const int lane = tid & 31, warp = tid >> 5;
    if (lane == 0) red[warp] = ss;
    __syncthreads();
    if (warp == 0) {
        float t = (lane < 8) ? red[lane] : 0.0f;
        #pragma unroll
        for (int off = 4; off; off >>= 1)
            t += __shfl_xor_sync(0xffffffffu, t, off);
        if (lane == 0) red[0] = t;
    }
    __syncthreads();

    const float inv = rsqrtf(red[0] * (1.0f / DMODEL) + 1e-5f);
    float4 gv = *(const float4*)(g + tid * 4);
    __half2 h0 = __floats2half2_rn(v.x * inv * gv.x, v.y * inv * gv.y);
    __half2 h1 = __floats2half2_rn(v.z * inv * gv.z, v.w * inv * gv.w);
    __half* yp = y + (size_t)row * DMODEL + tid * 4;
    *(__half2*)(yp)     = h0;
    *(__half2*)(yp + 2) = h1;
}

// ---------------------------------------------------------------------------
// FP16 tensor-core GEMM: C[M,N] = A[M,K] * B[N,K]^T (+ float R if MODE==1)
// BM=BN=128, BK=64 (128B rows, SW128), 8 warps 2x4, warp tile 64x32,
// 2-stage cp.async pipeline (64KB smem), 2 CTAs/SM.
// ---------------------------------------------------------------------------
#define GF_STAGE_H (128 * 64)
#define GF_SMEM (4 * GF_STAGE_H * 2)     // 65536 bytes

template <int MODE>
__global__ __launch_bounds__(256, 2) void gemm_f16(
    const __half* __restrict__ A,
    const __half* __restrict__ B0, const __half* __restrict__ B1, const __half* __restrict__ B2,
    const float* __restrict__ R,
    void* __restrict__ C0v, void* __restrict__ C1v, void* __restrict__ C2v,
    int M, int N, int K)
{
    extern __shared__ __half smh[];
    __half* As = smh;                       // 2 stages
    __half* Bs = smh + 2 * GF_STAGE_H;      // 2 stages

    const int z = blockIdx.z;
    const __half* B = (z == 0) ? B0 : (z == 1) ? B1 : B2;
    void*         Cv = (z == 0) ? C0v : (z == 1) ? C1v : C2v;

    const int tid  = threadIdx.x;
    const int lane = tid & 31, warp = tid >> 5;
    const int g = lane >> 2, t4 = lane & 3;
    const int wm = warp >> 2, wn = warp & 3;
    const int bm = blockIdx.y, bn = blockIdx.x;

    const int lr = lane & 15;
    const int lc = (lane >> 4) << 3;
    const int sft = lane >> 3;

    const __half* Ab = A + (size_t)bm * 128 * K;
    const __half* Bb = B + (size_t)bn * 128 * K;

    float acc[4][4][4];
    #pragma unroll
    for (int i = 0; i < 4; ++i)
        #pragma unroll
        for (int j = 0; j < 4; ++j)
            #pragma unroll
            for (int r = 0; r < 4; ++r) acc[i][j][r] = 0.0f;

    const int T = K >> 6;

    auto load_tile = [&](int kt, int st) {
        const __half* Asrc = Ab + kt * 64;
        const __half* Bsrc = Bb + kt * 64;
        __half* Adst = As + st * GF_STAGE_H;
        __half* Bdst = Bs + st * GF_STAGE_H;
        #pragma unroll
        for (int e = 0; e < 4; ++e) {
            int id  = e * 256 + tid;
            int row = id >> 3;
            int c16 = id & 7;
            unsigned int sw = (unsigned int)(row * 128) + (((unsigned int)c16 ^ ((unsigned int)row & 7u)) * 16u);
            unsigned int sa = (unsigned int)__cvta_generic_to_shared((const char*)Adst + sw);
            asm volatile("cp.async.cg.shared.global [%0], [%1], 16;\n"
                         :: "r"(sa), "l"(Asrc + (size_t)row * K + c16 * 8));
            unsigned int sb = (unsigned int)__cvta_generic_to_shared((const char*)Bdst + sw);
            asm volatile("cp.async.cg.shared.global [%0], [%1], 16;\n"
                         :: "r"(sb), "l"(Bsrc + (size_t)row * K + c16 * 8));
        }
        asm volatile("cp.async.commit_group;\n");
    };

    load_tile(0, 0);
    load_tile(1, 1);

    for (int kt = 0; kt < T; ++kt) {
        if (kt + 1 < T) asm volatile("cp.async.wait_group 1;\n");
        else            asm volatile("cp.async.wait_group 0;\n");
        __syncthreads();

        const __half* Asb = As + (kt & 1) * GF_STAGE_H;
        const __half* Bsb = Bs + (kt & 1) * GF_STAGE_H;

        #pragma unroll
        for (int ks = 0; ks < 4; ++ks) {
            const int k0 = ks * 16;
            unsigned int af[4][4], bf[2][4];
            #pragma unroll
            for (int i = 0; i < 4; ++i)
                ldsm4h(af[i], swp(Asb, wm * 64 + i * 16 + lr, k0 + lc));
            #pragma unroll
            for (int jp = 0; jp < 2; ++jp)
                ldsm4h(bf[jp], swp(Bsb, wn * 32 + 8 * (2 * jp + (sft >> 1)) + (lane & 7),
                                   k0 + ((sft & 1) << 3)));
            #pragma unroll
            for (int i = 0; i < 4; ++i)
                #pragma unroll
                for (int jp = 0; jp < 2; ++jp) {
                    mma_f16(acc[i][2 * jp],     af[i], bf[jp]);
                    mma_f16(acc[i][2 * jp + 1], af[i], bf[jp] + 2);
                }
        }
        __syncthreads();

        if (kt + 2 < T) load_tile(kt + 2, kt & 1);
    }

    #pragma unroll
    for (int i = 0; i < 4; ++i) {
        const int r0 = bm * 128 + wm * 64 + i * 16 + g;
        #pragma unroll
        for (int j = 0; j < 4; ++j) {
            const int c0 = bn * 128 + wn * 32 + j * 8 + 2 * t4;
            if (MODE == 1) {
                float* C = (float*)Cv;
                float2 rr0 = *(const float2*)(R + (size_t)r0 * N + c0);
                float2 rr1 = *(const float2*)(R + (size_t)(r0 + 8) * N + c0);
                *(float2*)(C + (size_t)r0 * N + c0) =
                    make_float2(acc[i][j][0] + rr0.x, acc[i][j][1] + rr0.y);
                *(float2*)(C + (size_t)(r0 + 8) * N + c0) =
                    make_float2(acc[i][j][2] + rr1.x, acc[i][j][3] + rr1.y);
            } else {
                __half* C = (__half*)Cv;
                *(__half2*)(C + (size_t)r0 * N + c0) =
                    __floats2half2_rn(acc[i][j][0], acc[i][j][1]);
                *(__half2*)(C + (size_t)(r0 + 8) * N + c0) =
                    __floats2half2_rn(acc[i][j][2], acc[i][j][3]);
            }
        }
    }
}

// ---------------------------------------------------------------------------
// Fused W1/W3/SwiGLU GEMM: out[M, DFF] = silu(A W1^T) * (A W3^T)
// CTA tile 128M x 64N; 8 warps 4m x 2n; 2-stage cp.async (64KB), 2 CTAs/SM.
// ---------------------------------------------------------------------------
#define GS_A_H (128 * 64)
#define GS_B_H (64 * 64)
#define GS_SMEM ((2 * GS_A_H + 4 * GS_B_H) * 2)   // 65536 bytes

__global__ __launch_bounds__(256, 2) void gemm_swiglu(
    const __half* __restrict__ A,
    const __half* __restrict__ W1p, const __half* __restrict__ W3p,
    __half* __restrict__ Out, int K)
{
    extern __shared__ __half smh[];
    __half* As  = smh;                      // 2 x 8192 halfs
    __half* B1s = smh + 2 * GS_A_H;         // 2 x 4096
    __half* B3s = B1s + 2 * GS_B_H;         // 2 x 4096

    const int tid  = threadIdx.x;
    const int lane = tid & 31, warp = tid >> 5;
    const int g = lane >> 2, t4 = lane & 3;
    const int wm = warp >> 1, wn = warp & 1;
    const int bm = blockIdx.y, bn = blockIdx.x;

    const int lr = lane & 15;
    const int lc = (lane >> 4) << 3;
    const int sft = lane >> 3;

    const __half* Ab  = A   + (size_t)bm * 128 * K;
    const __half* B1b = W1p + (size_t)bn * 64 * K;
    const __half* B3b = W3p + (size_t)bn * 64 * K;

    float acc1[2][4][4], acc3[2][4][4];
    #pragma unroll
    for (int i = 0; i < 2; ++i)
        #pragma unroll
        for (int j = 0; j < 4; ++j)
            #pragma unroll
            for (int r = 0; r < 4; ++r) { acc1[i][j][r] = 0.0f; acc3[i][j][r] = 0.0f; }

    const int T = K >> 6;

    auto load_tile = [&](int kt, int st) {
        const __half* Asrc  = Ab  + kt * 64;
        const __half* B1src = B1b + kt * 64;
        const __half* B3src = B3b + kt * 64;
        __half* Adst  = As  + st * GS_A_H;
        __half* B1dst = B1s + st * GS_B_H;
        __half* B3dst = B3s + st * GS_B_H;
        #pragma unroll
        for (int e = 0; e < 4; ++e) {
            int id  = e * 256 + tid;
            int row = id >> 3;
            int c16 = id & 7;
            unsigned int sw = (unsigned int)(row * 128) + (((unsigned int)c16 ^ ((unsigned int)row & 7u)) * 16u);
            unsigned int sa = (unsigned int)__cvta_generic_to_shared((const char*)Adst + sw);
            asm volatile("cp.async.cg.shared.global [%0], [%1], 16;\n"
                         :: "r"(sa), "l"(Asrc + (size_t)row * K + c16 * 8));
        }
        #pragma unroll
        for (int e = 0; e < 2; ++e) {
            int id  = e * 256 + tid;
            int row = id >> 3;
            int c16 = id & 7;
            unsigned int sw = (unsigned int)(row * 128) + (((unsigned int)c16 ^ ((unsigned int)row & 7u)) * 16u);
            unsigned int s1 = (unsigned int)__cvta_generic_to_shared((const char*)B1dst + sw);
            asm volatile("cp.async.cg.shared.global [%0], [%1], 16;\n"
                         :: "r"(s1), "l"(B1src + (size_t)row * K + c16 * 8));
            unsigned int s3 = (unsigned int)__cvta_generic_to_shared((const char*)B3dst + sw);
            asm volatile("cp.async.cg.shared.global [%0], [%1], 16;\n"
                         :: "r"(s3), "l"(B3src + (size_t)row * K + c16 * 8));
        }
        asm volatile("cp.async.commit_group;\n");
    };

    load_tile(0, 0);
    load_tile(1, 1);

    for (int kt = 0; kt < T; ++kt) {
        if (kt + 1 < T) asm volatile("cp.async.wait_group 1;\n");
        else            asm volatile("cp.async.wait_group 0;\n");
        __syncthreads();

        const __half* Asb  = As  + (kt & 1) * GS_A_H;
        const __half* B1sb = B1s + (kt & 1) * GS_B_H;
        const __half* B3sb = B3s + (kt & 1) * GS_B_H;

        #pragma unroll
        for (int ks = 0; ks < 4; ++ks) {
            const int k0 = ks * 16;
            unsigned int af[2][4], b1f[2][4], b3f[2][4];
            #pragma unroll
            for (int i = 0; i < 2; ++i)
                ldsm4h(af[i], swp(Asb, wm * 32 + i * 16 + lr, k0 + lc));
            #pragma unroll
            for (int jp = 0; jp < 2; ++jp) {
                const int brow = wn * 32 + 8 * (2 * jp + (sft >> 1)) + (lane & 7);
                const int bcol = k0 + ((sft & 1) << 3);
                ldsm4h(b1f[jp], swp(B1sb, brow, bcol));
                ldsm4h(b3f[jp], swp(B3sb, brow, bcol));
            }
            #pragma unroll
            for (int i = 0; i < 2; ++i)
                #pragma unroll
                for (int jp = 0; jp < 2; ++jp) {
                    mma_f16(acc1[i][2 * jp],     af[i], b1f[jp]);
                    mma_f16(acc1[i][2 * jp + 1], af[i], b1f[jp] + 2);
                    mma_f16(acc3[i][2 * jp],     af[i], b3f[jp]);
                    mma_f16(acc3[i][2 * jp + 1], af[i], b3f[jp] + 2);
                }
        }
        __syncthreads();

        if (kt + 2 < T) load_tile(kt + 2, kt & 1);
    }

    #pragma unroll
    for (int i = 0; i < 2; ++i) {
        const int r0 = bm * 128 + wm * 32 + i * 16 + g;
        #pragma unroll
        for (int j = 0; j < 4; ++j) {
            const int c0 = bn * 64 + wn * 32 + j * 8 + 2 * t4;
            float o0 = acc1[i][j][0] * (1.0f / (1.0f + __expf(-acc1[i][j][0]))) * acc3[i][j][0];
            float o1 = acc1[i][j][1] * (1.0f / (1.0f + __expf(-acc1[i][j][1]))) * acc3[i][j][1];
            float o2 = acc1[i][j][2] * (1.0f / (1.0f + __expf(-acc1[i][j][2]))) * acc3[i][j][2];
            float o3 = acc1[i][j][3] * (1.0f / (1.0f + __expf(-acc1[i][j][3]))) * acc3[i][j][3];
            *(__half2*)(Out + (size_t)r0 * DFF + c0)       = __floats2half2_rn(o0, o1);
            *(__half2*)(Out + (size_t)(r0 + 8) * DFF + c0) = __floats2half2_rn(o2, o3);
        }
    }
}

// ---------------------------------------------------------------------------
// Flash attention v2 (unchanged from R9). Grid: (S/128, B*H).
// ---------------------------------------------------------------------------
#define FA_Q_BYTES (128 * 128)
#define FA_KV_BYTES (64 * 128)
#define FA_SMEM_BYTES (FA_Q_BYTES + 4 * FA_KV_BYTES)

__global__ __launch_bounds__(256) void flash_attn_kernel(
    const __half* __restrict__ Q, const __half* __restrict__ K,
    const __half* __restrict__ V, __half* __restrict__ O)
{
    extern __shared__ char smraw[];
    __half* Qs = (__half*)smraw;

    const int tid  = threadIdx.x;
    const int lane = tid & 31, w = tid >> 5;
    const int g = lane >> 2, t4 = lane & 3;
    const int lr = lane & 15;
    const int lc = (lane >> 4) << 3;

    const int qb = (int)gridDim.x - 1 - (int)blockIdx.x;
    const int bh = blockIdx.y;
    const int b = bh >> 4, h = bh & 15;

    const size_t base = ((size_t)b * SEQ) * DMODEL + h * DHEAD;
    const __half* Qg = Q + base + (size_t)(qb * 128) * DMODEL;
    const __half* Kg = K + base;
    const __half* Vg = V + base;

    #pragma unroll
    for (int e = 0; e < 4; ++e) {
        int id  = e * 256 + tid;
        int row = id >> 3;
        int c16 = id & 7;
        unsigned int sw = (unsigned int)(row * 128) + (((unsigned int)c16 ^ ((unsigned int)row & 7u)) * 16u);
        unsigned int sa = (unsigned int)__cvta_generic_to_shared(smraw + sw);
        asm volatile("cp.async.cg.shared.global [%0], [%1], 16;\n"
                     :: "r"(sa), "l"(Qg + (size_t)row * DMODEL + c16 * 8));
    }
    asm volatile("cp.async.commit_group;\n");

    auto load_kv = [&](int t, int buf) {
        const __half* Ksrc = Kg + (size_t)(t * 64) * DMODEL;
        const __half* Vsrc = Vg + (size_t)(t * 64) * DMODEL;
        char* Kdst = smraw + FA_Q_BYTES + buf * FA_KV_BYTES;
        char* Vdst = smraw + FA_Q_BYTES + 2 * FA_KV_BYTES + buf * FA_KV_BYTES;
        #pragma unroll
        for (int e = 0; e < 2; ++e) {
            int id  = e * 256 + tid;
            int row = id >> 3;
            int c16 = id & 7;
            unsigned int sw = (unsigned int)(row * 128) + (((unsigned int)c16 ^ ((unsigned int)row & 7u)) * 16u);
            unsigned int sk = (unsigned int)__cvta_generic_to_shared(Kdst + sw);
            asm volatile("cp.async.cg.shared.global [%0], [%1], 16;\n"
                         :: "r"(sk), "l"(Ksrc + (size_t)row * DMODEL + c16 * 8));
            unsigned int sv = (unsigned int)__cvta_generic_to_shared(Vdst + sw);
            asm volatile("cp.async.cg.shared.global [%0], [%1], 16;\n"
                         :: "r"(sv), "l"(Vsrc + (size_t)row * DMODEL + c16 * 8));
        }
        asm volatile("cp.async.commit_group;\n");
    };

    load_kv(0, 0);

    asm volatile("cp.async.wait_group 1;\n");
    __syncthreads();

    unsigned int aq[4][4];
    #pragma unroll
    for (int dt = 0; dt < 4; ++dt)
        ldsm4h(aq[dt], swp(Qs, 16 * w + lr, dt * 16 + lc));

    float o_acc[8][4];
    #pragma unroll
    for (int j = 0; j < 8; ++j)
        #pragma unroll
        for (int r = 0; r < 4; ++r) o_acc[j][r] = 0.0f;

    float m0 = -INFINITY, m1 = -INFINITY, l0 = 0.0f, l1 = 0.0f;

    const int T = 2 * qb + 2;

    for (int t = 0; t < T; ++t) {
        if (t + 1 < T) {
            load_kv(t + 1, (t + 1) & 1);
            asm volatile("cp.async.wait_group 1;\n");
        } else {
            asm volatile("cp.async.wait_group 0;\n");
        }
        __syncthreads();

        const bool skip = (16 * w + 15) < (64 * t - 128 * qb);
        if (!skip) {
            const __half* Ksb = (const __half*)(smraw + FA_Q_BYTES + (t & 1) * FA_KV_BYTES);
            const __half* Vsb = (const __half*)(smraw + FA_Q_BYTES + 2 * FA_KV_BYTES + (t & 1) * FA_KV_BYTES);

            float s[8][4];
            #pragma unroll
            for (int j = 0; j < 8; ++j)
                #pragma unroll
                for (int r = 0; r < 4; ++r) s[j][r] = 0.0f;

            const int sft = lane >> 3;
            #pragma unroll
            for (int dt = 0; dt < 4; ++dt) {
                #pragma unroll
                for (int jp = 0; jp < 4; ++jp) {
                    unsigned int bk[4];
                    ldsm4h(bk, swp(Ksb, 8 * (2 * jp + (sft >> 1)) + (lane & 7),
                                   dt * 16 + ((sft & 1) << 3)));
                    mma_f16(s[2 * jp],     aq[dt], bk);
                    mma_f16(s[2 * jp + 1], aq[dt], bk + 2);
                }
            }

            #pragma unroll
            for (int j = 0; j < 8; ++j)
                #pragma unroll
                for (int r = 0; r < 4; ++r) s[j][r] *= 0.125f;

            if (t >= 2 * qb) {
                const int q0r = 128 * qb + 16 * w + g;
                #pragma unroll
                for (int j = 0; j < 8; ++j) {
                    const int kk = 64 * t + 8 * j + 2 * t4;
                    if (kk     > q0r)     s[j][0] = -INFINITY;
                    if (kk + 1 > q0r)     s[j][1] = -INFINITY;
                    if (kk     > q0r + 8) s[j][2] = -INFINITY;
                    if (kk + 1 > q0r + 8) s[j][3] = -INFINITY;
                }
            }

            float mt0 = -INFINITY, mt1 = -INFINITY;
            #pragma unroll
            for (int j = 0; j < 8; ++j) {
                mt0 = fmaxf(mt0, fmaxf(s[j][0], s[j][1]));
                mt1 = fmaxf(mt1, fmaxf(s[j][2], s[j][3]));
            }
            mt0 = fmaxf(mt0, __shfl_xor_sync(0xffffffffu, mt0, 1));
            mt0 = fmaxf(mt0, __shfl_xor_sync(0xffffffffu, mt0, 2));
            mt1 = fmaxf(mt1, __shfl_xor_sync(0xffffffffu, mt1, 1));
            mt1 = fmaxf(mt1, __shfl_xor_sync(0xffffffffu, mt1, 2));

            const float mn0 = fmaxf(m0, mt0);
            const float mn1 = fmaxf(m1, mt1);
            const float sc0 = __expf(m0 - mn0);
            const float sc1 = __expf(m1 - mn1);

            float sum0 = 0.0f, sum1 = 0.0f;
            unsigned int ap[4][4];
            #pragma unroll
            for (int j = 0; j < 8; ++j) {
                float p0 = __expf(s[j][0] - mn0);
                float p1 = __expf(s[j][1] - mn0);
                float p2 = __expf(s[j][2] - mn1);
                float p3 = __expf(s[j][3] - mn1);
                sum0 += p0 + p1;
                sum1 += p2 + p3;
                __half2 h01 = __floats2half2_rn(p0, p1);
                __half2 h23 = __floats2half2_rn(p2, p3);
                const int kt = j >> 1;
                if ((j & 1) == 0) {
                    ap[kt][0] = *(unsigned int*)&h01;
                    ap[kt][1] = *(unsigned int*)&h23;
                } else {
                    ap[kt][2] = *(unsigned int*)&h01;
                    ap[kt][3] = *(unsigned int*)&h23;
                }
            }
            sum0 += __shfl_xor_sync(0xffffffffu, sum0, 1);
            sum0 += __shfl_xor_sync(0xffffffffu, sum0, 2);
            sum1 += __shfl_xor_sync(0xffffffffu, sum1, 1);
            sum1 += __shfl_xor_sync(0xffffffffu, sum1, 2);

            l0 = l0 * sc0 + sum0;
            l1 = l1 * sc1 + sum1;
            m0 = mn0;
            m1 = mn1;

            #pragma unroll
            for (int j = 0; j < 8; ++j) {
                o_acc[j][0] *= sc0; o_acc[j][1] *= sc0;
                o_acc[j][2] *= sc1; o_acc[j][3] *= sc1;
            }

            #pragma unroll
            for (int kt = 0; kt < 4; ++kt) {
                #pragma unroll
                for (int jp = 0; jp < 4; ++jp) {
                    unsigned int bv[4];
                    ldsm4ht(bv, swp(Vsb, 16 * kt + ((sft & 1) << 3) + (lane & 7),
                                    16 * jp + ((sft >> 1) << 3)));
                    mma_f16(o_acc[2 * jp],     ap[kt], bv);
                    mma_f16(o_acc[2 * jp + 1], ap[kt], bv + 2);
                }
            }
        }
        __syncthreads();
    }

    const float inv0 = 1.0f / l0;
    const float inv1 = 1.0f / l1;
    __half* Og = O + base + (size_t)(qb * 128 + 16 * w) * DMODEL;
    #pragma unroll
    for (int j = 0; j < 8; ++j) {
        const int d = 8 * j + 2 * t4;
        *(__half2*)(Og + (size_t)g * DMODEL + d) =
            __floats2half2_rn(o_acc[j][0] * inv0, o_acc[j][1] * inv0);
        *(__half2*)(Og + (size_t)(g + 8) * DMODEL + d) =
            __floats2half2_rn(o_acc[j][2] * inv1, o_acc[j][3] * inv1);
    }
}

// ---------------------------------------------------------------------------
// Launch
// ---------------------------------------------------------------------------
extern "C" void kernel_launch(void* const* d_in, const int* in_sizes, int n_in,
                              void* d_out, int out_size)
{
    const float* x  = (const float*)d_in[0];
    const float* Wq = (const float*)d_in[1];
    const float* Wk = (const float*)d_in[2];
    const float* Wv = (const float*)d_in[3];
    const float* Wo = (const float*)d_in[4];
    const float* W1 = (const float*)d_in[5];
    const float* W2 = (const float*)d_in[6];
    const float* W3 = (const float*)d_in[7];
    const float* g1 = (const float*)d_in[8];
    const float* g2 = (const float*)d_in[9];
    float* out = (float*)d_out;

    __half *h1, *q, *k, *v, *o, *a;
    __half *wq, *wk, *wv, *wo, *w1, *w2, *w3;
    float *x2;
    cudaGetSymbolAddress((void**)&h1, g_h1);
    cudaGetSymbolAddress((void**)&q,  g_q);
    cudaGetSymbolAddress((void**)&k,  g_k);
    cudaGetSymbolAddress((void**)&v,  g_v);
    cudaGetSymbolAddress((void**)&o,  g_o);
    cudaGetSymbolAddress((void**)&x2, g_x2);
    cudaGetSymbolAddress((void**)&a,  g_a);
    cudaGetSymbolAddress((void**)&wq, g_wq);
    cudaGetSymbolAddress((void**)&wk, g_wk);
    cudaGetSymbolAddress((void**)&wv, g_wv);
    cudaGetSymbolAddress((void**)&wo, g_wo);
    cudaGetSymbolAddress((void**)&w1, g_w1);
    cudaGetSymbolAddress((void**)&w2, g_w2);
    cudaGetSymbolAddress((void**)&w3, g_w3);

    cudaFuncSetAttribute(flash_attn_kernel,
                         cudaFuncAttributeMaxDynamicSharedMemorySize, FA_SMEM_BYTES);
    cudaFuncSetAttribute(gemm_f16<0>,
                         cudaFuncAttributeMaxDynamicSharedMemorySize, GF_SMEM);
    cudaFuncSetAttribute(gemm_f16<1>,
                         cudaFuncAttributeMaxDynamicSharedMemorySize, GF_SMEM);
    cudaFuncSetAttribute(gemm_swiglu,
                         cudaFuncAttributeMaxDynamicSharedMemorySize, GS_SMEM);

    // 0) convert all weights to fp16 in one launch
    convert_all_kernel<<<NTOT16 / 256, 256>>>(Wq, Wk, Wv, Wo, W1, W2, W3,
                                              wq, wk, wv, wo, w1, w2, w3);

    const dim3 gemm_qkv(DMODEL / 128, NTOK / 128, 3);
    const dim3 gemm_d_d(DMODEL / 128, NTOK / 128, 1);
    const dim3 gemm_sw(DFF / 64, NTOK / 128);

    // 1) h1 = rmsnorm(x, g1) -> fp16
    rmsnorm_kernel<<<NTOK, 256>>>(x, g1, h1);

    // 2) q,k,v = h1 @ W{q,k,v}^T
    gemm_f16<0><<<gemm_qkv, 256, GF_SMEM>>>(h1, wq, wk, wv, nullptr,
                                            q, k, v, NTOK, DMODEL, DMODEL);

    // 3) o = causal_attention(q, k, v)
    dim3 fa_grid(SEQ / 128, BATCH * NHEADS);
    flash_attn_kernel<<<fa_grid, 256, FA_SMEM_BYTES>>>(q, k, v, o);

    // 4) x2 = x + o @ Wo^T (fp32 out)
    gemm_f16<1><<<gemm_d_d, 256, GF_SMEM>>>(o, wo, wo, wo, x,
                                            x2, x2, x2, NTOK, DMODEL, DMODEL);

    // 5) h2 = rmsnorm(x2, g2) -> fp16
    rmsnorm_kernel<<<NTOK, 256>>>(x2, g2, h1);

    // 6) a = silu(h2 @ W1^T) * (h2 @ W3^T)   (fused)
    gemm_swiglu<<<gemm_sw, 256, GS_SMEM>>>(h1, w1, w3, a, DMODEL);

    // 7) out = x2 + a @ W2^T (fp32 out)
    gemm_f16<1><<<gemm_d_d, 256, GF_SMEM>>>(a, w2, w2, w2, x2,
                                            out, out, out, NTOK, DMODEL, DFF);
}

// round 11
// speedup vs baseline: 8.1398x; 1.0352x over previous
#include <cuda_runtime.h>
#include <cuda_fp16.h>
#include <stdint.h>
#include <math.h>

// Problem constants
#define BATCH 2
#define SEQ 2048
#define DMODEL 1024
#define NHEADS 16
#define DHEAD 64
#define DFF 4096
#define NTOK (BATCH * SEQ)   // 4096

// ---------------------------------------------------------------------------
// Scratch (device globals; allocation is forbidden)
// ---------------------------------------------------------------------------
__device__ __half g_h1[NTOK * DMODEL];
__device__ __half g_q [NTOK * DMODEL];
__device__ __half g_k [NTOK * DMODEL];
__device__ __half g_v [NTOK * DMODEL];
__device__ __half g_o [NTOK * DMODEL];
__device__ float  g_x2[NTOK * DMODEL];
__device__ __half g_a [NTOK * DFF];
// fp16 weights
__device__ __half g_wq[DMODEL * DMODEL];
__device__ __half g_wk[DMODEL * DMODEL];
__device__ __half g_wv[DMODEL * DMODEL];
__device__ __half g_wo[DMODEL * DMODEL];
__device__ __half g_w1[DFF * DMODEL];
__device__ __half g_w2[DMODEL * DFF];
__device__ __half g_w3[DFF * DMODEL];

// ---------------------------------------------------------------------------
// mma.sync helpers
// ---------------------------------------------------------------------------
__device__ __forceinline__ void mma_f16(float* c, const unsigned int* a, const unsigned int* b) {
    asm volatile(
        "mma.sync.aligned.m16n8k16.row.col.f32.f16.f16.f32 "
        "{%0,%1,%2,%3}, {%4,%5,%6,%7}, {%8,%9}, {%0,%1,%2,%3};"
        : "+f"(c[0]), "+f"(c[1]), "+f"(c[2]), "+f"(c[3])
        : "r"(a[0]), "r"(a[1]), "r"(a[2]), "r"(a[3]), "r"(b[0]), "r"(b[1]));
}
__device__ __forceinline__ void ldsm4h(unsigned int* r, const __half* p) {
    unsigned int addr = (unsigned int)__cvta_generic_to_shared(p);
    asm volatile("ldmatrix.sync.aligned.m8n8.x4.shared.b16 {%0,%1,%2,%3}, [%4];"
                 : "=r"(r[0]), "=r"(r[1]), "=r"(r[2]), "=r"(r[3]) : "r"(addr));
}
__device__ __forceinline__ void ldsm4ht(unsigned int* r, const __half* p) {
    unsigned int addr = (unsigned int)__cvta_generic_to_shared(p);
    asm volatile("ldmatrix.sync.aligned.m8n8.x4.trans.shared.b16 {%0,%1,%2,%3}, [%4];"
                 : "=r"(r[0]), "=r"(r[1]), "=r"(r[2]), "=r"(r[3]) : "r"(addr));
}
__device__ __forceinline__ float ex2f(float x) {
    float y;
    asm("ex2.approx.ftz.f32 %0, %1;" : "=f"(y) : "f"(x));
    return y;
}

// SW128 swizzled pointer within a [rows x 128 bytes] tile. halfcol multiple of 8.
__device__ __forceinline__ const __half* swp(const __half* base, int row, int halfcol) {
    unsigned int off = (unsigned int)(row * 128) +
        (((unsigned int)(halfcol * 2)) ^ (((unsigned int)row & 7u) * 16u));
    return (const __half*)((const char*)base + off);
}

// ---------------------------------------------------------------------------
// Fused weight convert: all 7 weight matrices fp32 -> fp16 in one launch.
// ---------------------------------------------------------------------------
#define NDD16 (DMODEL * DMODEL / 16)
#define NFF16 (DFF * DMODEL / 16)
#define NTOT16 (4 * NDD16 + 3 * NFF16)

__global__ __launch_bounds__(256) void convert_all_kernel(
    const float* __restrict__ s0, const float* __restrict__ s1,
    const float* __restrict__ s2, const float* __restrict__ s3,
    const float* __restrict__ s4, const float* __restrict__ s5,
    const float* __restrict__ s6,
    __half* __restrict__ d0, __half* __restrict__ d1,
    __half* __restrict__ d2, __half* __restrict__ d3,
    __half* __restrict__ d4, __half* __restrict__ d5,
    __half* __restrict__ d6)
{
    int idx = blockIdx.x * 256 + threadIdx.x;
    if (idx >= NTOT16) return;

    const float* src;
    __half* dst;
    int off;
    if (idx < 4 * NDD16) {
        int seg = idx / NDD16;
        off = idx - seg * NDD16;
        src = (seg == 0) ? s0 : (seg == 1) ? s1 : (seg == 2) ? s2 : s3;
        dst = (seg == 0) ? d0 : (seg == 1) ? d1 : (seg == 2) ? d2 : d3;
    } else {
        int r = idx - 4 * NDD16;
        int seg = r / NFF16;
        off = r - seg * NFF16;
        src = (seg == 0) ? s4 : (seg == 1) ? s5 : s6;
        dst = (seg == 0) ? d4 : (seg == 1) ? d5 : d6;
    }

    float4 v0 = *(const float4*)(src + (size_t)off * 16);
    float4 v1 = *(const float4*)(src + (size_t)off * 16 + 4);
    float4 v2 = *(const float4*)(src + (size_t)off * 16 + 8);
    float4 v3 = *(const float4*)(src + (size_t)off * 16 + 12);
    __half2 h[8];
    h[0] = __floats2half2_rn(v0.x, v0.y);
    h[1] = __floats2half2_rn(v0.z, v0.w);
    h[2] = __floats2half2_rn(v1.x, v1.y);
    h[3] = __floats2half2_rn(v1.z, v1.w);
    h[4] = __floats2half2_rn(v2.x, v2.y);
    h[5] = __floats2half2_rn(v2.z, v2.w);
    h[6] = __floats2half2_rn(v3.x, v3.y);
    h[7] = __floats2half2_rn(v3.z, v3.w);
    *(uint4*)(dst + (size_t)off * 16)     = ((uint4*)h)[0];
    *(uint4*)(dst + (size_t)off * 16 + 8) = ((uint4*)h)[1];
}

// ---------------------------------------------------------------------------
// RMSNorm: fp32 in -> fp16 out.
// ---------------------------------------------------------------------------
__global__ __launch_bounds__(256) void rmsnorm_kernel(
    const float* __restrict__ x, const float* __restrict__ g,
    __half* __restrict__ y)
{
    const int row = blockIdx.x;
    const int tid = threadIdx.x;
    const float* xr = x + (size_t)row * DMODEL;

    float4 v = *(const float4*)(xr + tid * 4);
    float ss = v.x * v.x + v.y * v.y + v.z * v.z + v.w * v.w;

    #pragma unroll
    for (int off = 16; off; off >>= 1)
        ss += __shfl_xor_sync(0xffffffffu, ss, off);

    __shared__ float red[8];
    const int lane = tid & 31, warp = tid >> 5;
    if (lane == 0) red[warp] = ss;
    __syncthreads();
    if (warp == 0) {
        float t = (lane < 8) ? red[lane] : 0.0f;
        #pragma unroll
        for (int off = 4; off; off >>= 1)
            t += __shfl_xor_sync(0xffffffffu, t, off);
        if (lane == 0) red[0] = t;
    }
    __syncthreads();

    const float inv = rsqrtf(red[0] * (1.0f / DMODEL) + 1e-5f);
    float4 gv = *(const float4*)(g + tid * 4);
    __half2 h0 = __floats2half2_rn(v.x * inv * gv.x, v.y * inv * gv.y);
    __half2 h1 = __floats2half2_rn(v.z * inv * gv.z, v.w * inv * gv.w);
    __half* yp = y + (size_t)row * DMODEL + tid * 4;
    *(__half2*)(yp)     = h0;
    *(__half2*)(yp + 2) = h1;
}

// ---------------------------------------------------------------------------
// FP16 tensor-core GEMM: C[M,N] = A[M,K] * B[N,K]^T (+ float R if MODE==1)
// BM=BN=128, BK=64 (128B rows, SW128), 8 warps 2x4, warp tile 64x32,
// 3-stage cp.async pipeline with ONE sync per k-tile, 2 CTAs/SM.
// ---------------------------------------------------------------------------
#define GF_STAGE_H (128 * 64)
#define GF_SMEM (6 * GF_STAGE_H * 2)     // 98304 bytes

template <int MODE>
__global__ __launch_bounds__(256, 2) void gemm_f16(
    const __half* __restrict__ A,
    const __half* __restrict__ B0, const __half* __restrict__ B1, const __half* __restrict__ B2,
    const float* __restrict__ R,
    void* __restrict__ C0v, void* __restrict__ C1v, void* __restrict__ C2v,
    int M, int N, int K)
{
    extern __shared__ __half smh[];
    __half* As = smh;                       // 3 stages
    __half* Bs = smh + 3 * GF_STAGE_H;      // 3 stages

    const int z = blockIdx.z;
    const __half* B = (z == 0) ? B0 : (z == 1) ? B1 : B2;
    void*         Cv = (z == 0) ? C0v : (z == 1) ? C1v : C2v;

    const int tid  = threadIdx.x;
    const int lane = tid & 31, warp = tid >> 5;
    const int g = lane >> 2, t4 = lane & 3;
    const int wm = warp >> 2, wn = warp & 3;
    const int bm = blockIdx.y, bn = blockIdx.x;

    const int lr = lane & 15;
    const int lc = (lane >> 4) << 3;
    const int sft = lane >> 3;

    const __half* Ab = A + (size_t)bm * 128 * K;
    const __half* Bb = B + (size_t)bn * 128 * K;

    float acc[4][4][4];
    #pragma unroll
    for (int i = 0; i < 4; ++i)
        #pragma unroll
        for (int j = 0; j < 4; ++j)
            #pragma unroll
            for (int r = 0; r < 4; ++r) acc[i][j][r] = 0.0f;

    const int T = K >> 6;

    auto load_tile = [&](int kt, int st) {
        const __half* Asrc = Ab + kt * 64;
        const __half* Bsrc = Bb + kt * 64;
        __half* Adst = As + st * GF_STAGE_H;
        __half* Bdst = Bs + st * GF_STAGE_H;
        #pragma unroll
        for (int e = 0; e < 4; ++e) {
            int id  = e * 256 + tid;
            int row = id >> 3;
            int c16 = id & 7;
            unsigned int sw = (unsigned int)(row * 128) + (((unsigned int)c16 ^ ((unsigned int)row & 7u)) * 16u);
            unsigned int sa = (unsigned int)__cvta_generic_to_shared((const char*)Adst + sw);
            asm volatile("cp.async.cg.shared.global [%0], [%1], 16;\n"
                         :: "r"(sa), "l"(Asrc + (size_t)row * K + c16 * 8));
            unsigned int sb = (unsigned int)__cvta_generic_to_shared((const char*)Bdst + sw);
            asm volatile("cp.async.cg.shared.global [%0], [%1], 16;\n"
                         :: "r"(sb), "l"(Bsrc + (size_t)row * K + c16 * 8));
        }
        asm volatile("cp.async.commit_group;\n");
    };

    load_tile(0, 0);
    load_tile(1, 1);

    for (int kt = 0; kt < T; ++kt) {
        if (kt + 1 < T) asm volatile("cp.async.wait_group 1;\n");
        else            asm volatile("cp.async.wait_group 0;\n");
        __syncthreads();

        // safe: stage (kt+2)%3 == (kt-1)%3, all warps finished it (top sync)
        if (kt + 2 < T) load_tile(kt + 2, (kt + 2) % 3);

        const __half* Asb = As + (kt % 3) * GF_STAGE_H;
        const __half* Bsb = Bs + (kt % 3) * GF_STAGE_H;

        #pragma unroll
        for (int ks = 0; ks < 4; ++ks) {
            const int k0 = ks * 16;
            unsigned int af[4][4], bf[2][4];
            #pragma unroll
            for (int i = 0; i < 4; ++i)
                ldsm4h(af[i], swp(Asb, wm * 64 + i * 16 + lr, k0 + lc));
            #pragma unroll
            for (int jp = 0; jp < 2; ++jp)
                ldsm4h(bf[jp], swp(Bsb, wn * 32 + 8 * (2 * jp + (sft >> 1)) + (lane & 7),
                                   k0 + ((sft & 1) << 3)));
            #pragma unroll
            for (int i = 0; i < 4; ++i)
                #pragma unroll
                for (int jp = 0; jp < 2; ++jp) {
                    mma_f16(acc[i][2 * jp],     af[i], bf[jp]);
                    mma_f16(acc[i][2 * jp + 1], af[i], bf[jp] + 2);
                }
        }
    }

    #pragma unroll
    for (int i = 0; i < 4; ++i) {
        const int r0 = bm * 128 + wm * 64 + i * 16 + g;
        #pragma unroll
        for (int j = 0; j < 4; ++j) {
            const int c0 = bn * 128 + wn * 32 + j * 8 + 2 * t4;
            if (MODE == 1) {
                float* C = (float*)Cv;
                float2 rr0 = *(const float2*)(R + (size_t)r0 * N + c0);
                float2 rr1 = *(const float2*)(R + (size_t)(r0 + 8) * N + c0);
                *(float2*)(C + (size_t)r0 * N + c0) =
                    make_float2(acc[i][j][0] + rr0.x, acc[i][j][1] + rr0.y);
                *(float2*)(C + (size_t)(r0 + 8) * N + c0) =
                    make_float2(acc[i][j][2] + rr1.x, acc[i][j][3] + rr1.y);
            } else {
                __half* C = (__half*)Cv;
                *(__half2*)(C + (size_t)r0 * N + c0) =
                    __floats2half2_rn(acc[i][j][0], acc[i][j][1]);
                *(__half2*)(C + (size_t)(r0 + 8) * N + c0) =
                    __floats2half2_rn(acc[i][j][2], acc[i][j][3]);
            }
        }
    }
}

// ---------------------------------------------------------------------------
// Fused W1/W3/SwiGLU GEMM: out[M, DFF] = silu(A W1^T) * (A W3^T)
// CTA tile 128M x 64N; 8 warps 4m x 2n; 3-stage, one sync per k-tile.
// ---------------------------------------------------------------------------
#define GS_A_H (128 * 64)
#define GS_B_H (64 * 64)
#define GS_SMEM ((3 * GS_A_H + 6 * GS_B_H) * 2)   // 98304 bytes

__global__ __launch_bounds__(256, 2) void gemm_swiglu(
    const __half* __restrict__ A,
    const __half* __restrict__ W1p, const __half* __restrict__ W3p,
    __half* __restrict__ Out, int K)
{
    extern __shared__ __half smh[];
    __half* As  = smh;                      // 3 x 8192 halfs
    __half* B1s = smh + 3 * GS_A_H;         // 3 x 4096
    __half* B3s = B1s + 3 * GS_B_H;         // 3 x 4096

    const int tid  = threadIdx.x;
    const int lane = tid & 31, warp = tid >> 5;
    const int g = lane >> 2, t4 = lane & 3;
    const int wm = warp >> 1, wn = warp & 1;
    const int bm = blockIdx.y, bn = blockIdx.x;

    const int lr = lane & 15;
    const int lc = (lane >> 4) << 3;
    const int sft = lane >> 3;

    const __half* Ab  = A   + (size_t)bm * 128 * K;
    const __half* B1b = W1p + (size_t)bn * 64 * K;
    const __half* B3b = W3p + (size_t)bn * 64 * K;

    float acc1[2][4][4], acc3[2][4][4];
    #pragma unroll
    for (int i = 0; i < 2; ++i)
        #pragma unroll
        for (int j = 0; j < 4; ++j)
            #pragma unroll
            for (int r = 0; r < 4; ++r) { acc1[i][j][r] = 0.0f; acc3[i][j][r] = 0.0f; }

    const int T = K >> 6;

    auto load_tile = [&](int kt, int st) {
        const __half* Asrc  = Ab  + kt * 64;
        const __half* B1src = B1b + kt * 64;
        const __half* B3src = B3b + kt * 64;
        __half* Adst  = As  + st * GS_A_H;
        __half* B1dst = B1s + st * GS_B_H;
        __half* B3dst = B3s + st * GS_B_H;
        #pragma unroll
        for (int e = 0; e < 4; ++e) {
            int id  = e * 256 + tid;
            int row = id >> 3;
            int c16 = id & 7;
            unsigned int sw = (unsigned int)(row * 128) + (((unsigned int)c16 ^ ((unsigned int)row & 7u)) * 16u);
            unsigned int sa = (unsigned int)__cvta_generic_to_shared((const char*)Adst + sw);
            asm volatile("cp.async.cg.shared.global [%0], [%1], 16;\n"
                         :: "r"(sa), "l"(Asrc + (size_t)row * K + c16 * 8));
        }
        #pragma unroll
        for (int e = 0; e < 2; ++e) {
            int id  = e * 256 + tid;
            int row = id >> 3;
            int c16 = id & 7;
            unsigned int sw = (unsigned int)(row * 128) + (((unsigned int)c16 ^ ((unsigned int)row & 7u)) * 16u);
            unsigned int s1 = (unsigned int)__cvta_generic_to_shared((const char*)B1dst + sw);
            asm volatile("cp.async.cg.shared.global [%0], [%1], 16;\n"
                         :: "r"(s1), "l"(B1src + (size_t)row * K + c16 * 8));
            unsigned int s3 = (unsigned int)__cvta_generic_to_shared((const char*)B3dst + sw);
            asm volatile("cp.async.cg.shared.global [%0], [%1], 16;\n"
                         :: "r"(s3), "l"(B3src + (size_t)row * K + c16 * 8));
        }
        asm volatile("cp.async.commit_group;\n");
    };

    load_tile(0, 0);
    load_tile(1, 1);

    for (int kt = 0; kt < T; ++kt) {
        if (kt + 1 < T) asm volatile("cp.async.wait_group 1;\n");
        else            asm volatile("cp.async.wait_group 0;\n");
        __syncthreads();

        if (kt + 2 < T) load_tile(kt + 2, (kt + 2) % 3);

        const __half* Asb  = As  + (kt % 3) * GS_A_H;
        const __half* B1sb = B1s + (kt % 3) * GS_B_H;
        const __half* B3sb = B3s + (kt % 3) * GS_B_H;

        #pragma unroll
        for (int ks = 0; ks < 4; ++ks) {
            const int k0 = ks * 16;
            unsigned int af[2][4], b1f[2][4], b3f[2][4];
            #pragma unroll
            for (int i = 0; i < 2; ++i)
                ldsm4h(af[i], swp(Asb, wm * 32 + i * 16 + lr, k0 + lc));
            #pragma unroll
            for (int jp = 0; jp < 2; ++jp) {
                const int brow = wn * 32 + 8 * (2 * jp + (sft >> 1)) + (lane & 7);
                const int bcol = k0 + ((sft & 1) << 3);
                ldsm4h(b1f[jp], swp(B1sb, brow, bcol));
                ldsm4h(b3f[jp], swp(B3sb, brow, bcol));
            }
            #pragma unroll
            for (int i = 0; i < 2; ++i)
                #pragma unroll
                for (int jp = 0; jp < 2; ++jp) {
                    mma_f16(acc1[i][2 * jp],     af[i], b1f[jp]);
                    mma_f16(acc1[i][2 * jp + 1], af[i], b1f[jp] + 2);
                    mma_f16(acc3[i][2 * jp],     af[i], b3f[jp]);
                    mma_f16(acc3[i][2 * jp + 1], af[i], b3f[jp] + 2);
                }
        }
    }

    #pragma unroll
    for (int i = 0; i < 2; ++i) {
        const int r0 = bm * 128 + wm * 32 + i * 16 + g;
        #pragma unroll
        for (int j = 0; j < 4; ++j) {
            const int c0 = bn * 64 + wn * 32 + j * 8 + 2 * t4;
            float o0 = acc1[i][j][0] * (1.0f / (1.0f + __expf(-acc1[i][j][0]))) * acc3[i][j][0];
            float o1 = acc1[i][j][1] * (1.0f / (1.0f + __expf(-acc1[i][j][1]))) * acc3[i][j][1];
            float o2 = acc1[i][j][2] * (1.0f / (1.0f + __expf(-acc1[i][j][2]))) * acc3[i][j][2];
            float o3 = acc1[i][j][3] * (1.0f / (1.0f + __expf(-acc1[i][j][3]))) * acc3[i][j][3];
            *(__half2*)(Out + (size_t)r0 * DFF + c0)       = __floats2half2_rn(o0, o1);
            *(__half2*)(Out + (size_t)(r0 + 8) * DFF + c0) = __floats2half2_rn(o2, o3);
        }
    }
}

// ---------------------------------------------------------------------------
// Flash attention v3: exp2-folded softmax, ones-MMA row sums, 3-buffer KV
// with one sync per tile. Grid: (S/128, B*H), 8 warps, warp tile 16q x 64k.
// ---------------------------------------------------------------------------
#define FA_Q_BYTES (128 * 128)
#define FA_KV_BYTES (64 * 128)
#define FA_SMEM_BYTES (FA_Q_BYTES + 6 * FA_KV_BYTES)   // 65536

__global__ __launch_bounds__(256) void flash_attn_kernel(
    const __half* __restrict__ Q, const __half* __restrict__ K,
    const __half* __restrict__ V, __half* __restrict__ O)
{
    extern __shared__ char smraw[];
    __half* Qs = (__half*)smraw;
    // K buffers: +16384 + buf*8192 (buf 0..2); V buffers: +40960 + buf*8192

    const int tid  = threadIdx.x;
    const int lane = tid & 31, w = tid >> 5;
    const int g = lane >> 2, t4 = lane & 3;
    const int lr = lane & 15;
    const int lc = (lane >> 4) << 3;

    const int qb = (int)gridDim.x - 1 - (int)blockIdx.x;
    const int bh = blockIdx.y;
    const int b = bh >> 4, h = bh & 15;

    const size_t base = ((size_t)b * SEQ) * DMODEL + h * DHEAD;
    const __half* Qg = Q + base + (size_t)(qb * 128) * DMODEL;
    const __half* Kg = K + base;
    const __half* Vg = V + base;

    #pragma unroll
    for (int e = 0; e < 4; ++e) {
        int id  = e * 256 + tid;
        int row = id >> 3;
        int c16 = id & 7;
        unsigned int sw = (unsigned int)(row * 128) + (((unsigned int)c16 ^ ((unsigned int)row & 7u)) * 16u);
        unsigned int sa = (unsigned int)__cvta_generic_to_shared(smraw + sw);
        asm volatile("cp.async.cg.shared.global [%0], [%1], 16;\n"
                     :: "r"(sa), "l"(Qg + (size_t)row * DMODEL + c16 * 8));
    }
    asm volatile("cp.async.commit_group;\n");

    auto load_kv = [&](int t, int buf) {
        const __half* Ksrc = Kg + (size_t)(t * 64) * DMODEL;
        const __half* Vsrc = Vg + (size_t)(t * 64) * DMODEL;
        char* Kdst = smraw + FA_Q_BYTES + buf * FA_KV_BYTES;
        char* Vdst = smraw + FA_Q_BYTES + 3 * FA_KV_BYTES + buf * FA_KV_BYTES;
        #pragma unroll
        for (int e = 0; e < 2; ++e) {
            int id  = e * 256 + tid;
            int row = id >> 3;
            int c16 = id & 7;
            unsigned int sw = (unsigned int)(row * 128) + (((unsigned int)c16 ^ ((unsigned int)row & 7u)) * 16u);
            unsigned int sk = (unsigned int)__cvta_generic_to_shared(Kdst + sw);
            asm volatile("cp.async.cg.shared.global [%0], [%1], 16;\n"
                         :: "r"(sk), "l"(Ksrc + (size_t)row * DMODEL + c16 * 8));
            unsigned int sv = (unsigned int)__cvta_generic_to_shared(Vdst + sw);
            asm volatile("cp.async.cg.shared.global [%0], [%1], 16;\n"
                         :: "r"(sv), "l"(Vsrc + (size_t)row * DMODEL + c16 * 8));
        }
        asm volatile("cp.async.commit_group;\n");
    };

    load_kv(0, 0);
    load_kv(1, 1);

    // Q group done (2 newest = kv0, kv1 may be pending)
    asm volatile("cp.async.wait_group 2;\n");
    __syncthreads();

    unsigned int aq[4][4];
    #pragma unroll
    for (int dt = 0; dt < 4; ++dt)
        ldsm4h(aq[dt], swp(Qs, 16 * w + lr, dt * 16 + lc));

    float o_acc[8][4];
    #pragma unroll
    for (int j = 0; j < 8; ++j)
        #pragma unroll
        for (int r = 0; r < 4; ++r) o_acc[j][r] = 0.0f;

    float m0 = -INFINITY, m1 = -INFINITY, l0 = 0.0f, l1 = 0.0f;

    const float CE = 0.125f * 1.44269504f;   // softmax scale folded into exp2
    const unsigned int bones[2] = {0x3C003C00u, 0x3C003C00u};

    const int T = 2 * qb + 2;

    for (int t = 0; t < T; ++t) {
        if (t + 1 < T) asm volatile("cp.async.wait_group 1;\n");
        else           asm volatile("cp.async.wait_group 0;\n");
        __syncthreads();

        // safe: buffer (t+2)%3 == (t-1)%3, all warps done with it (top sync)
        if (t + 2 < T) load_kv(t + 2, (t + 2) % 3);

        const bool skip = (16 * w + 15) < (64 * t - 128 * qb);
        if (!skip) {
            const __half* Ksb = (const __half*)(smraw + FA_Q_BYTES + (t % 3) * FA_KV_BYTES);
            const __half* Vsb = (const __half*)(smraw + FA_Q_BYTES + 3 * FA_KV_BYTES + (t % 3) * FA_KV_BYTES);

            // ---- S = Q K^T (raw, unscaled) ----
            float s[8][4];
            #pragma unroll
            for (int j = 0; j < 8; ++j)
                #pragma unroll
                for (int r = 0; r < 4; ++r) s[j][r] = 0.0f;

            const int sft = lane >> 3;
            #pragma unroll
            for (int dt = 0; dt < 4; ++dt) {
                #pragma unroll
                for (int jp = 0; jp < 4; ++jp) {
                    unsigned int bk[4];
                    ldsm4h(bk, swp(Ksb, 8 * (2 * jp + (sft >> 1)) + (lane & 7),
                                   dt * 16 + ((sft & 1) << 3)));
                    mma_f16(s[2 * jp],     aq[dt], bk);
                    mma_f16(s[2 * jp + 1], aq[dt], bk + 2);
                }
            }

            // causal mask on raw s (only last two tiles touch the diagonal)
            if (t >= 2 * qb) {
                const int q0r = 128 * qb + 16 * w + g;
                #pragma unroll
                for (int j = 0; j < 8; ++j) {
                    const int kk = 64 * t + 8 * j + 2 * t4;
                    if (kk     > q0r)     s[j][0] = -INFINITY;
                    if (kk + 1 > q0r)     s[j][1] = -INFINITY;
                    if (kk     > q0r + 8) s[j][2] = -INFINITY;
                    if (kk + 1 > q0r + 8) s[j][3] = -INFINITY;
                }
            }

            // ---- online softmax: max in fp32, p = exp2((s - m)*CE) ----
            float mt0 = -INFINITY, mt1 = -INFINITY;
            #pragma unroll
            for (int j = 0; j < 8; ++j) {
                mt0 = fmaxf(mt0, fmaxf(s[j][0], s[j][1]));
                mt1 = fmaxf(mt1, fmaxf(s[j][2], s[j][3]));
            }
            mt0 = fmaxf(mt0, __shfl_xor_sync(0xffffffffu, mt0, 1));
            mt0 = fmaxf(mt0, __shfl_xor_sync(0xffffffffu, mt0, 2));
            mt1 = fmaxf(mt1, __shfl_xor_sync(0xffffffffu, mt1, 1));
            mt1 = fmaxf(mt1, __shfl_xor_sync(0xffffffffu, mt1, 2));

            const float mn0 = fmaxf(m0, mt0);
            const float mn1 = fmaxf(m1, mt1);
            const float sc0 = ex2f((m0 - mn0) * CE);
            const float sc1 = ex2f((m1 - mn1) * CE);
            const float bexp0 = mn0 * CE;
            const float bexp1 = mn1 * CE;

            unsigned int ap[4][4];
            #pragma unroll
            for (int j = 0; j < 8; ++j) {
                float p0 = ex2f(fmaf(s[j][0], CE, -bexp0));
                float p1 = ex2f(fmaf(s[j][1], CE, -bexp0));
                float p2 = ex2f(fmaf(s[j][2], CE, -bexp1));
                float p3 = ex2f(fmaf(s[j][3], CE, -bexp1));
                __half2 h01 = __floats2half2_rn(p0, p1);
                __half2 h23 = __floats2half2_rn(p2, p3);
                const int kt = j >> 1;
                if ((j & 1) == 0) {
                    ap[kt][0] = *(unsigned int*)&h01;
                    ap[kt][1] = *(unsigned int*)&h23;
                } else {
                    ap[kt][2] = *(unsigned int*)&h01;
                    ap[kt][3] = *(unsigned int*)&h23;
                }
            }

            // ---- row sums via ones-MMA (exact fp32 sum of the fp16 P) ----
            float sm[4] = {0.0f, 0.0f, 0.0f, 0.0f};
            #pragma unroll
            for (int kt = 0; kt < 4; ++kt)
                mma_f16(sm, ap[kt], bones);

            l0 = l0 * sc0 + sm[0];
            l1 = l1 * sc1 + sm[2];
            m0 = mn0;
            m1 = mn1;

            #pragma unroll
            for (int j = 0; j < 8; ++j) {
                o_acc[j][0] *= sc0; o_acc[j][1] *= sc0;
                o_acc[j][2] *= sc1; o_acc[j][3] *= sc1;
            }

            // ---- O += P V ----
            #pragma unroll
            for (int kt = 0; kt < 4; ++kt) {
                #pragma unroll
                for (int jp = 0; jp < 4; ++jp) {
                    unsigned int bv[4];
                    ldsm4ht(bv, swp(Vsb, 16 * kt + ((sft & 1) << 3) + (lane & 7),
                                    16 * jp + ((sft >> 1) << 3)));
                    mma_f16(o_acc[2 * jp],     ap[kt], bv);
                    mma_f16(o_acc[2 * jp + 1], ap[kt], bv + 2);
                }
            }
        }
    }

    const float inv0 = 1.0f / l0;
    const float inv1 = 1.0f / l1;
    __half* Og = O + base + (size_t)(qb * 128 + 16 * w) * DMODEL;
    #pragma unroll
    for (int j = 0; j < 8; ++j) {
        const int d = 8 * j + 2 * t4;
        *(__half2*)(Og + (size_t)g * DMODEL + d) =
            __floats2half2_rn(o_acc[j][0] * inv0, o_acc[j][1] * inv0);
        *(__half2*)(Og + (size_t)(g + 8) * DMODEL + d) =
            __floats2half2_rn(o_acc[j][2] * inv1, o_acc[j][3] * inv1);
    }
}

// ---------------------------------------------------------------------------
// Launch
// ---------------------------------------------------------------------------
extern "C" void kernel_launch(void* const* d_in, const int* in_sizes, int n_in,
                              void* d_out, int out_size)
{
    const float* x  = (const float*)d_in[0];
    const float* Wq = (const float*)d_in[1];
    const float* Wk = (const float*)d_in[2];
    const float* Wv = (const float*)d_in[3];
    const float* Wo = (const float*)d_in[4];
    const float* W1 = (const float*)d_in[5];
    const float* W2 = (const float*)d_in[6];
    const float* W3 = (const float*)d_in[7];
    const float* g1 = (const float*)d_in[8];
    const float* g2 = (const float*)d_in[9];
    float* out = (float*)d_out;

    __half *h1, *q, *k, *v, *o, *a;
    __half *wq, *wk, *wv, *wo, *w1, *w2, *w3;
    float *x2;
    cudaGetSymbolAddress((void**)&h1, g_h1);
    cudaGetSymbolAddress((void**)&q,  g_q);
    cudaGetSymbolAddress((void**)&k,  g_k);
    cudaGetSymbolAddress((void**)&v,  g_v);
    cudaGetSymbolAddress((void**)&o,  g_o);
    cudaGetSymbolAddress((void**)&x2, g_x2);
    cudaGetSymbolAddress((void**)&a,  g_a);
    cudaGetSymbolAddress((void**)&wq, g_wq);
    cudaGetSymbolAddress((void**)&wk, g_wk);
    cudaGetSymbolAddress((void**)&wv, g_wv);
    cudaGetSymbolAddress((void**)&wo, g_wo);
    cudaGetSymbolAddress((void**)&w1, g_w1);
    cudaGetSymbolAddress((void**)&w2, g_w2);
    cudaGetSymbolAddress((void**)&w3, g_w3);

    cudaFuncSetAttribute(flash_attn_kernel,
                         cudaFuncAttributeMaxDynamicSharedMemorySize, FA_SMEM_BYTES);
    cudaFuncSetAttribute(gemm_f16<0>,
                         cudaFuncAttributeMaxDynamicSharedMemorySize, GF_SMEM);
    cudaFuncSetAttribute(gemm_f16<1>,
                         cudaFuncAttributeMaxDynamicSharedMemorySize, GF_SMEM);
    cudaFuncSetAttribute(gemm_swiglu,
                         cudaFuncAttributeMaxDynamicSharedMemorySize, GS_SMEM);

    // 0) convert all weights to fp16 in one launch
    convert_all_kernel<<<NTOT16 / 256, 256>>>(Wq, Wk, Wv, Wo, W1, W2, W3,
                                              wq, wk, wv, wo, w1, w2, w3);

    const dim3 gemm_qkv(DMODEL / 128, NTOK / 128, 3);
    const dim3 gemm_d_d(DMODEL / 128, NTOK / 128, 1);
    const dim3 gemm_sw(DFF / 64, NTOK / 128);

    // 1) h1 = rmsnorm(x, g1) -> fp16
    rmsnorm_kernel<<<NTOK, 256>>>(x, g1, h1);

    // 2) q,k,v = h1 @ W{q,k,v}^T
    gemm_f16<0><<<gemm_qkv, 256, GF_SMEM>>>(h1, wq, wk, wv, nullptr,
                                            q, k, v, NTOK, DMODEL, DMODEL);

    // 3) o = causal_attention(q, k, v)
    dim3 fa_grid(SEQ / 128, BATCH * NHEADS);
    flash_attn_kernel<<<fa_grid, 256, FA_SMEM_BYTES>>>(q, k, v, o);

    // 4) x2 = x + o @ Wo^T (fp32 out)
    gemm_f16<1><<<gemm_d_d, 256, GF_SMEM>>>(o, wo, wo, wo, x,
                                            x2, x2, x2, NTOK, DMODEL, DMODEL);

    // 5) h2 = rmsnorm(x2, g2) -> fp16
    rmsnorm_kernel<<<NTOK, 256>>>(x2, g2, h1);

    // 6) a = silu(h2 @ W1^T) * (h2 @ W3^T)   (fused)
    gemm_swiglu<<<gemm_sw, 256, GS_SMEM>>>(h1, w1, w3, a, DMODEL);

    // 7) out = x2 + a @ W2^T (fp32 out)
    gemm_f16<1><<<gemm_d_d, 256, GF_SMEM>>>(a, w2, w2, w2, x2,
                                            out, out, out, NTOK, DMODEL, DFF);
}